// round 1
// baseline (speedup 1.0000x reference)
#include <cuda_runtime.h>
#include <math.h>

#define BATCH 4
#define SEQ   2048
#define DIN   1024
#define NH    16
#define DKH   64
#define DM    1024
#define LOG2E 1.4426950408889634f

// Scratch (static device globals — allocation-free per harness rules)
__device__ float g_Q[(size_t)BATCH*NH*SEQ*DKH];
__device__ float g_K[(size_t)BATCH*NH*SEQ*DKH];
__device__ float g_V[(size_t)BATCH*NH*SEQ*DKH];
__device__ float g_A[(size_t)BATCH*SEQ*NH*DKH];  // [B, S, H*DKH] (heads concatenated)

// ---------------------------------------------------------------------------
// Kernel 1: QKV projections. grid = (S/128, B*(H/2), 3)
// Block computes a 128(s) x 128(2 heads x 64) tile for one of Wq/Wk/Wv.
// ---------------------------------------------------------------------------
__global__ __launch_bounds__(256, 2) void qkv_kernel(
    const float* __restrict__ x,
    const float* __restrict__ Wq,
    const float* __restrict__ Wk,
    const float* __restrict__ Wv)
{
    __shared__ float As[128][17];   // odd pad: conflict-free scalar broadcast
    __shared__ float Bs[16][132];   // pad 132: 16B-aligned rows for LDS.128

    const int which = blockIdx.z;
    const float* W = (which == 0) ? Wq : (which == 1) ? Wk : Wv;
    float* outp    = (which == 0) ? g_Q : (which == 1) ? g_K : g_V;

    const int b  = blockIdx.y >> 3;
    const int h0 = (blockIdx.y & 7) * 2;
    const int s0 = blockIdx.x * 128;
    const int tid = threadIdx.x;
    const int tx = tid & 15;   // n: cols tx*8..tx*8+7
    const int ty = tid >> 4;   // m: rows ty*8..ty*8+7

    const float* xb = x + ((size_t)b * SEQ + s0) * DIN;

    float acc[8][8];
#pragma unroll
    for (int i = 0; i < 8; i++)
#pragma unroll
        for (int j = 0; j < 8; j++) acc[i][j] = 0.f;

    for (int k0 = 0; k0 < DIN; k0 += 16) {
#pragma unroll
        for (int i = tid; i < 128 * 16; i += 256) {
            int r = i >> 4, c = i & 15;
            As[r][c] = xb[(size_t)r * DIN + k0 + c];
        }
#pragma unroll
        for (int i = tid; i < 16 * 128; i += 256) {
            int r = i >> 7, c = i & 127;
            int h = h0 + (c >> 6);
            Bs[r][c] = W[((size_t)h * DIN + (k0 + r)) * DKH + (c & 63)];
        }
        __syncthreads();
#pragma unroll
        for (int kk = 0; kk < 16; kk++) {
            float a[8];
#pragma unroll
            for (int i = 0; i < 8; i++) a[i] = As[ty * 8 + i][kk];
            float4 b0 = *(const float4*)&Bs[kk][tx * 8];
            float4 b1 = *(const float4*)&Bs[kk][tx * 8 + 4];
            float bv[8] = {b0.x, b0.y, b0.z, b0.w, b1.x, b1.y, b1.z, b1.w};
#pragma unroll
            for (int i = 0; i < 8; i++)
#pragma unroll
                for (int j = 0; j < 8; j++) acc[i][j] += a[i] * bv[j];
        }
        __syncthreads();
    }

#pragma unroll
    for (int i = 0; i < 8; i++) {
        int s = s0 + ty * 8 + i;
#pragma unroll
        for (int half = 0; half < 2; half++) {
            int c = tx * 8 + half * 4;
            int h = h0 + (c >> 6);
            float4 v = make_float4(acc[i][half * 4 + 0], acc[i][half * 4 + 1],
                                   acc[i][half * 4 + 2], acc[i][half * 4 + 3]);
            *(float4*)&outp[(((size_t)(b * NH + h)) * SEQ + s) * DKH + (c & 63)] = v;
        }
    }
}

// ---------------------------------------------------------------------------
// Kernel 2: causal flash attention. grid = (S/128, B*H), 256 threads.
// BM=128 q rows, BN=64 kv rows, d=64. 8x4 micro-tiles, vectorized operands.
// ---------------------------------------------------------------------------
#define ATTN_SMEM_FLOATS (64 * 132 + 64 * 68 + 64 * 68 + 64 * 132)
#define ATTN_SMEM_BYTES  (ATTN_SMEM_FLOATS * 4)

__global__ __launch_bounds__(256, 2) void attn_kernel()
{
    extern __shared__ float smf[];
    float* QsT = smf;                         // [k=64][m=128] pad 132 (Q * scale)
    float* KsT = QsT + 64 * 132;              // [k=64][n=64]  pad 68
    float* Vsm = KsT + 64 * 68;               // [n=64][d=64]  pad 68
    float* PsT = Vsm + 64 * 68;               // [n=64][m=128] pad 132

    const int qi = (int)gridDim.x - 1 - (int)blockIdx.x;  // heavy tiles first
    const int q0 = qi * 128;
    const int bh = blockIdx.y;
    const int b = bh / NH, h = bh % NH;
    const int tid = threadIdx.x;
    const int tx = tid & 15;   // n/d cols tx*4..+3
    const int ty = tid >> 4;   // m rows ty*8..+7

    const float* Qb = g_Q + ((size_t)bh * SEQ + q0) * DKH;
    const float* Kb = g_K + (size_t)bh * SEQ * DKH;
    const float* Vb = g_V + (size_t)bh * SEQ * DKH;

    for (int i = tid; i < 128 * 64; i += 256) {
        int m = i >> 6, k = i & 63;
        QsT[k * 132 + m] = Qb[i] * 0.125f;   // fold 1/sqrt(dk)
    }

    float O[8][4], mrow[8], lrow[8];
#pragma unroll
    for (int i = 0; i < 8; i++) {
        mrow[i] = -1e30f; lrow[i] = 0.f;
#pragma unroll
        for (int j = 0; j < 4; j++) O[i][j] = 0.f;
    }

    const int njt = 2 * qi + 2;
    for (int j = 0; j < njt; j++) {
        __syncthreads();   // prior PV done; also covers initial QsT fill
        const float* Kt = Kb + (size_t)j * 64 * DKH;
        const float* Vt = Vb + (size_t)j * 64 * DKH;
        for (int i = tid; i < 64 * 64; i += 256) {
            int n = i >> 6, k = i & 63;
            KsT[k * 68 + n] = Kt[i];
            Vsm[n * 68 + k] = Vt[i];
        }
        __syncthreads();

        // scores S = (Q*scale) @ K^T  (128 x 64 tile)
        float s[8][4];
#pragma unroll
        for (int i = 0; i < 8; i++)
#pragma unroll
            for (int jj = 0; jj < 4; jj++) s[i][jj] = 0.f;

#pragma unroll 4
        for (int k = 0; k < 64; k++) {
            float4 a0 = *(const float4*)&QsT[k * 132 + ty * 8];
            float4 a1 = *(const float4*)&QsT[k * 132 + ty * 8 + 4];
            float4 bb = *(const float4*)&KsT[k * 68 + tx * 4];
            float a[8] = {a0.x, a0.y, a0.z, a0.w, a1.x, a1.y, a1.z, a1.w};
            float bv[4] = {bb.x, bb.y, bb.z, bb.w};
#pragma unroll
            for (int i = 0; i < 8; i++)
#pragma unroll
                for (int jj = 0; jj < 4; jj++) s[i][jj] += a[i] * bv[jj];
        }

        // causal mask — only diagonal-region tiles need it
        if (j >= 2 * qi) {
#pragma unroll
            for (int i = 0; i < 8; i++) {
                int m = q0 + ty * 8 + i;
#pragma unroll
                for (int jj = 0; jj < 4; jj++) {
                    int n = j * 64 + tx * 4 + jj;
                    if (n > m) s[i][jj] = -1e30f;
                }
            }
        }

        // online softmax (row stats reduced over the 16 tx lanes, in-warp)
#pragma unroll
        for (int i = 0; i < 8; i++) {
            float t = fmaxf(fmaxf(s[i][0], s[i][1]), fmaxf(s[i][2], s[i][3]));
            t = fmaxf(t, __shfl_xor_sync(0xffffffffu, t, 1));
            t = fmaxf(t, __shfl_xor_sync(0xffffffffu, t, 2));
            t = fmaxf(t, __shfl_xor_sync(0xffffffffu, t, 4));
            t = fmaxf(t, __shfl_xor_sync(0xffffffffu, t, 8));
            float mnew  = fmaxf(mrow[i], t);
            float alpha = exp2f((mrow[i] - mnew) * LOG2E);
            float rs = 0.f;
#pragma unroll
            for (int jj = 0; jj < 4; jj++) {
                float p = exp2f((s[i][jj] - mnew) * LOG2E);
                s[i][jj] = p;
                rs += p;
            }
            rs += __shfl_xor_sync(0xffffffffu, rs, 1);
            rs += __shfl_xor_sync(0xffffffffu, rs, 2);
            rs += __shfl_xor_sync(0xffffffffu, rs, 4);
            rs += __shfl_xor_sync(0xffffffffu, rs, 8);
            lrow[i] = lrow[i] * alpha + rs;
            mrow[i] = mnew;
#pragma unroll
            for (int jj = 0; jj < 4; jj++) O[i][jj] *= alpha;
        }

        // P -> shared (transposed for vectorized PV reads)
#pragma unroll
        for (int jj = 0; jj < 4; jj++) {
            int n = tx * 4 + jj;
            float4 v0 = make_float4(s[0][jj], s[1][jj], s[2][jj], s[3][jj]);
            float4 v1 = make_float4(s[4][jj], s[5][jj], s[6][jj], s[7][jj]);
            *(float4*)&PsT[n * 132 + ty * 8]     = v0;
            *(float4*)&PsT[n * 132 + ty * 8 + 4] = v1;
        }
        __syncthreads();

        // O += P @ V
#pragma unroll 4
        for (int n = 0; n < 64; n++) {
            float4 a0 = *(const float4*)&PsT[n * 132 + ty * 8];
            float4 a1 = *(const float4*)&PsT[n * 132 + ty * 8 + 4];
            float4 bb = *(const float4*)&Vsm[n * 68 + tx * 4];
            float a[8] = {a0.x, a0.y, a0.z, a0.w, a1.x, a1.y, a1.z, a1.w};
            float bv[4] = {bb.x, bb.y, bb.z, bb.w};
#pragma unroll
            for (int i = 0; i < 8; i++)
#pragma unroll
                for (int jj = 0; jj < 4; jj++) O[i][jj] += a[i] * bv[jj];
        }
    }

    // epilogue: normalize and write concatenated-head layout [B, S, H*64]
#pragma unroll
    for (int i = 0; i < 8; i++) {
        float inv = 1.0f / lrow[i];
        int srow = q0 + ty * 8 + i;
        float4 v = make_float4(O[i][0] * inv, O[i][1] * inv,
                               O[i][2] * inv, O[i][3] * inv);
        *(float4*)&g_A[((size_t)b * SEQ + srow) * DM + h * DKH + tx * 4] = v;
    }
}

// ---------------------------------------------------------------------------
// Kernel 3: output projection. grid = (DM/128, B*S/128)
// ---------------------------------------------------------------------------
__global__ __launch_bounds__(256, 2) void proj_kernel(
    const float* __restrict__ Wo, float* __restrict__ out)
{
    __shared__ float As[128][17];
    __shared__ float Bs[16][132];

    const int n0 = blockIdx.x * 128;
    const int m0 = blockIdx.y * 128;
    const int tid = threadIdx.x;
    const int tx = tid & 15;
    const int ty = tid >> 4;

    const float* ab = g_A + (size_t)m0 * DM;

    float acc[8][8];
#pragma unroll
    for (int i = 0; i < 8; i++)
#pragma unroll
        for (int j = 0; j < 8; j++) acc[i][j] = 0.f;

    for (int k0 = 0; k0 < DM; k0 += 16) {
#pragma unroll
        for (int i = tid; i < 128 * 16; i += 256) {
            int r = i >> 4, c = i & 15;
            As[r][c] = ab[(size_t)r * DM + k0 + c];
        }
#pragma unroll
        for (int i = tid; i < 16 * 128; i += 256) {
            int r = i >> 7, c = i & 127;
            Bs[r][c] = Wo[(size_t)(k0 + r) * DM + n0 + c];
        }
        __syncthreads();
#pragma unroll
        for (int kk = 0; kk < 16; kk++) {
            float a[8];
#pragma unroll
            for (int i = 0; i < 8; i++) a[i] = As[ty * 8 + i][kk];
            float4 b0 = *(const float4*)&Bs[kk][tx * 8];
            float4 b1 = *(const float4*)&Bs[kk][tx * 8 + 4];
            float bv[8] = {b0.x, b0.y, b0.z, b0.w, b1.x, b1.y, b1.z, b1.w};
#pragma unroll
            for (int i = 0; i < 8; i++)
#pragma unroll
                for (int j = 0; j < 8; j++) acc[i][j] += a[i] * bv[j];
        }
        __syncthreads();
    }

#pragma unroll
    for (int i = 0; i < 8; i++) {
        size_t row = (size_t)(m0 + ty * 8 + i) * DM + n0;
#pragma unroll
        for (int half = 0; half < 2; half++) {
            float4 v = make_float4(acc[i][half * 4 + 0], acc[i][half * 4 + 1],
                                   acc[i][half * 4 + 2], acc[i][half * 4 + 3]);
            *(float4*)&out[row + tx * 8 + half * 4] = v;
        }
    }
}

// ---------------------------------------------------------------------------
extern "C" void kernel_launch(void* const* d_in, const int* in_sizes, int n_in,
                              void* d_out, int out_size)
{
    const float* x  = (const float*)d_in[0];
    const float* Wq = (const float*)d_in[1];
    const float* Wk = (const float*)d_in[2];
    const float* Wv = (const float*)d_in[3];
    const float* Wo = (const float*)d_in[4];
    float* out = (float*)d_out;

    cudaFuncSetAttribute(attn_kernel,
                         cudaFuncAttributeMaxDynamicSharedMemorySize,
                         ATTN_SMEM_BYTES);

    qkv_kernel<<<dim3(SEQ / 128, BATCH * (NH / 2), 3), 256>>>(x, Wq, Wk, Wv);
    attn_kernel<<<dim3(SEQ / 128, BATCH * NH), 256, ATTN_SMEM_BYTES>>>();
    proj_kernel<<<dim3(DM / 128, (BATCH * SEQ) / 128), 256>>>(Wo, out);
}

// round 2
// speedup vs baseline: 1.0023x; 1.0023x over previous
#include <cuda_runtime.h>
#include <math.h>

#define BATCH 4
#define SEQ   2048
#define DIN   1024
#define NH    16
#define DKH   64
#define DM    1024
#define LOG2E 1.4426950408889634f

// Scratch (static device globals — allocation-free per harness rules)
__device__ float g_Q[(size_t)BATCH*NH*SEQ*DKH];
__device__ float g_K[(size_t)BATCH*NH*SEQ*DKH];
__device__ float g_V[(size_t)BATCH*NH*SEQ*DKH];
__device__ float g_A[(size_t)BATCH*SEQ*NH*DKH];  // [B, S, H*DKH] (heads concatenated)

// ---------------------------------------------------------------------------
// Kernel 1: QKV projections. grid = (S/128, B*(H/2), 3)
// Block computes a 128(s) x 128(2 heads x 64) tile for one of Wq/Wk/Wv.
// ---------------------------------------------------------------------------
__global__ __launch_bounds__(256, 2) void qkv_kernel(
    const float* __restrict__ x,
    const float* __restrict__ Wq,
    const float* __restrict__ Wk,
    const float* __restrict__ Wv)
{
    __shared__ float As[128][17];   // odd pad: conflict-free scalar broadcast
    __shared__ float Bs[16][132];   // pad 132: 16B-aligned rows for LDS.128

    const int which = blockIdx.z;
    const float* W = (which == 0) ? Wq : (which == 1) ? Wk : Wv;
    float* outp    = (which == 0) ? g_Q : (which == 1) ? g_K : g_V;

    const int b  = blockIdx.y >> 3;
    const int h0 = (blockIdx.y & 7) * 2;
    const int s0 = blockIdx.x * 128;
    const int tid = threadIdx.x;
    const int tx = tid & 15;   // n: cols tx*8..tx*8+7
    const int ty = tid >> 4;   // m: rows ty*8..ty*8+7

    const float* xb = x + ((size_t)b * SEQ + s0) * DIN;

    float acc[8][8];
#pragma unroll
    for (int i = 0; i < 8; i++)
#pragma unroll
        for (int j = 0; j < 8; j++) acc[i][j] = 0.f;

    for (int k0 = 0; k0 < DIN; k0 += 16) {
#pragma unroll
        for (int i = tid; i < 128 * 16; i += 256) {
            int r = i >> 4, c = i & 15;
            As[r][c] = xb[(size_t)r * DIN + k0 + c];
        }
#pragma unroll
        for (int i = tid; i < 16 * 128; i += 256) {
            int r = i >> 7, c = i & 127;
            int h = h0 + (c >> 6);
            Bs[r][c] = W[((size_t)h * DIN + (k0 + r)) * DKH + (c & 63)];
        }
        __syncthreads();
#pragma unroll
        for (int kk = 0; kk < 16; kk++) {
            float a[8];
#pragma unroll
            for (int i = 0; i < 8; i++) a[i] = As[ty * 8 + i][kk];
            float4 b0 = *(const float4*)&Bs[kk][tx * 8];
            float4 b1 = *(const float4*)&Bs[kk][tx * 8 + 4];
            float bv[8] = {b0.x, b0.y, b0.z, b0.w, b1.x, b1.y, b1.z, b1.w};
#pragma unroll
            for (int i = 0; i < 8; i++)
#pragma unroll
                for (int j = 0; j < 8; j++) acc[i][j] += a[i] * bv[j];
        }
        __syncthreads();
    }

#pragma unroll
    for (int i = 0; i < 8; i++) {
        int s = s0 + ty * 8 + i;
#pragma unroll
        for (int half = 0; half < 2; half++) {
            int c = tx * 8 + half * 4;
            int h = h0 + (c >> 6);
            float4 v = make_float4(acc[i][half * 4 + 0], acc[i][half * 4 + 1],
                                   acc[i][half * 4 + 2], acc[i][half * 4 + 3]);
            *(float4*)&outp[(((size_t)(b * NH + h)) * SEQ + s) * DKH + (c & 63)] = v;
        }
    }
}

// ---------------------------------------------------------------------------
// Kernel 2: causal flash attention. grid = (S/128, B*H), 256 threads.
// BM=128 q rows, BN=64 kv rows, d=64. 8x4 micro-tiles, vectorized operands.
// ---------------------------------------------------------------------------
#define ATTN_SMEM_FLOATS (64 * 132 + 64 * 68 + 64 * 68 + 64 * 132)
#define ATTN_SMEM_BYTES  (ATTN_SMEM_FLOATS * 4)

__global__ __launch_bounds__(256, 2) void attn_kernel()
{
    extern __shared__ float smf[];
    float* QsT = smf;                         // [k=64][m=128] pad 132 (Q * scale)
    float* KsT = QsT + 64 * 132;              // [k=64][n=64]  pad 68
    float* Vsm = KsT + 64 * 68;               // [n=64][d=64]  pad 68
    float* PsT = Vsm + 64 * 68;               // [n=64][m=128] pad 132

    const int qi = (int)gridDim.x - 1 - (int)blockIdx.x;  // heavy tiles first
    const int q0 = qi * 128;
    const int bh = blockIdx.y;
    const int b = bh / NH, h = bh % NH;
    const int tid = threadIdx.x;
    const int tx = tid & 15;   // n/d cols tx*4..+3
    const int ty = tid >> 4;   // m rows ty*8..+7

    const float* Qb = g_Q + ((size_t)bh * SEQ + q0) * DKH;
    const float* Kb = g_K + (size_t)bh * SEQ * DKH;
    const float* Vb = g_V + (size_t)bh * SEQ * DKH;

    for (int i = tid; i < 128 * 64; i += 256) {
        int m = i >> 6, k = i & 63;
        QsT[k * 132 + m] = Qb[i] * 0.125f;   // fold 1/sqrt(dk)
    }

    float O[8][4], mrow[8], lrow[8];
#pragma unroll
    for (int i = 0; i < 8; i++) {
        mrow[i] = -1e30f; lrow[i] = 0.f;
#pragma unroll
        for (int j = 0; j < 4; j++) O[i][j] = 0.f;
    }

    const int njt = 2 * qi + 2;
    for (int j = 0; j < njt; j++) {
        __syncthreads();   // prior PV done; also covers initial QsT fill
        const float* Kt = Kb + (size_t)j * 64 * DKH;
        const float* Vt = Vb + (size_t)j * 64 * DKH;
        for (int i = tid; i < 64 * 64; i += 256) {
            int n = i >> 6, k = i & 63;
            KsT[k * 68 + n] = Kt[i];
            Vsm[n * 68 + k] = Vt[i];
        }
        __syncthreads();

        // scores S = (Q*scale) @ K^T  (128 x 64 tile)
        float s[8][4];
#pragma unroll
        for (int i = 0; i < 8; i++)
#pragma unroll
            for (int jj = 0; jj < 4; jj++) s[i][jj] = 0.f;

#pragma unroll 4
        for (int k = 0; k < 64; k++) {
            float4 a0 = *(const float4*)&QsT[k * 132 + ty * 8];
            float4 a1 = *(const float4*)&QsT[k * 132 + ty * 8 + 4];
            float4 bb = *(const float4*)&KsT[k * 68 + tx * 4];
            float a[8] = {a0.x, a0.y, a0.z, a0.w, a1.x, a1.y, a1.z, a1.w};
            float bv[4] = {bb.x, bb.y, bb.z, bb.w};
#pragma unroll
            for (int i = 0; i < 8; i++)
#pragma unroll
                for (int jj = 0; jj < 4; jj++) s[i][jj] += a[i] * bv[jj];
        }

        // causal mask — only diagonal-region tiles need it
        if (j >= 2 * qi) {
#pragma unroll
            for (int i = 0; i < 8; i++) {
                int m = q0 + ty * 8 + i;
#pragma unroll
                for (int jj = 0; jj < 4; jj++) {
                    int n = j * 64 + tx * 4 + jj;
                    if (n > m) s[i][jj] = -1e30f;
                }
            }
        }

        // online softmax (row stats reduced over the 16 tx lanes, in-warp)
#pragma unroll
        for (int i = 0; i < 8; i++) {
            float t = fmaxf(fmaxf(s[i][0], s[i][1]), fmaxf(s[i][2], s[i][3]));
            t = fmaxf(t, __shfl_xor_sync(0xffffffffu, t, 1));
            t = fmaxf(t, __shfl_xor_sync(0xffffffffu, t, 2));
            t = fmaxf(t, __shfl_xor_sync(0xffffffffu, t, 4));
            t = fmaxf(t, __shfl_xor_sync(0xffffffffu, t, 8));
            float mnew  = fmaxf(mrow[i], t);
            float alpha = exp2f((mrow[i] - mnew) * LOG2E);
            float rs = 0.f;
#pragma unroll
            for (int jj = 0; jj < 4; jj++) {
                float p = exp2f((s[i][jj] - mnew) * LOG2E);
                s[i][jj] = p;
                rs += p;
            }
            rs += __shfl_xor_sync(0xffffffffu, rs, 1);
            rs += __shfl_xor_sync(0xffffffffu, rs, 2);
            rs += __shfl_xor_sync(0xffffffffu, rs, 4);
            rs += __shfl_xor_sync(0xffffffffu, rs, 8);
            lrow[i] = lrow[i] * alpha + rs;
            mrow[i] = mnew;
#pragma unroll
            for (int jj = 0; jj < 4; jj++) O[i][jj] *= alpha;
        }

        // P -> shared (transposed for vectorized PV reads)
#pragma unroll
        for (int jj = 0; jj < 4; jj++) {
            int n = tx * 4 + jj;
            float4 v0 = make_float4(s[0][jj], s[1][jj], s[2][jj], s[3][jj]);
            float4 v1 = make_float4(s[4][jj], s[5][jj], s[6][jj], s[7][jj]);
            *(float4*)&PsT[n * 132 + ty * 8]     = v0;
            *(float4*)&PsT[n * 132 + ty * 8 + 4] = v1;
        }
        __syncthreads();

        // O += P @ V
#pragma unroll 4
        for (int n = 0; n < 64; n++) {
            float4 a0 = *(const float4*)&PsT[n * 132 + ty * 8];
            float4 a1 = *(const float4*)&PsT[n * 132 + ty * 8 + 4];
            float4 bb = *(const float4*)&Vsm[n * 68 + tx * 4];
            float a[8] = {a0.x, a0.y, a0.z, a0.w, a1.x, a1.y, a1.z, a1.w};
            float bv[4] = {bb.x, bb.y, bb.z, bb.w};
#pragma unroll
            for (int i = 0; i < 8; i++)
#pragma unroll
                for (int jj = 0; jj < 4; jj++) O[i][jj] += a[i] * bv[jj];
        }
    }

    // epilogue: normalize and write concatenated-head layout [B, S, H*64]
#pragma unroll
    for (int i = 0; i < 8; i++) {
        float inv = 1.0f / lrow[i];
        int srow = q0 + ty * 8 + i;
        float4 v = make_float4(O[i][0] * inv, O[i][1] * inv,
                               O[i][2] * inv, O[i][3] * inv);
        *(float4*)&g_A[((size_t)b * SEQ + srow) * DM + h * DKH + tx * 4] = v;
    }
}

// ---------------------------------------------------------------------------
// Kernel 3: output projection. grid = (DM/128, B*S/128)
// ---------------------------------------------------------------------------
__global__ __launch_bounds__(256, 2) void proj_kernel(
    const float* __restrict__ Wo, float* __restrict__ out)
{
    __shared__ float As[128][17];
    __shared__ float Bs[16][132];

    const int n0 = blockIdx.x * 128;
    const int m0 = blockIdx.y * 128;
    const int tid = threadIdx.x;
    const int tx = tid & 15;
    const int ty = tid >> 4;

    const float* ab = g_A + (size_t)m0 * DM;

    float acc[8][8];
#pragma unroll
    for (int i = 0; i < 8; i++)
#pragma unroll
        for (int j = 0; j < 8; j++) acc[i][j] = 0.f;

    for (int k0 = 0; k0 < DM; k0 += 16) {
#pragma unroll
        for (int i = tid; i < 128 * 16; i += 256) {
            int r = i >> 4, c = i & 15;
            As[r][c] = ab[(size_t)r * DM + k0 + c];
        }
#pragma unroll
        for (int i = tid; i < 16 * 128; i += 256) {
            int r = i >> 7, c = i & 127;
            Bs[r][c] = Wo[(size_t)(k0 + r) * DM + n0 + c];
        }
        __syncthreads();
#pragma unroll
        for (int kk = 0; kk < 16; kk++) {
            float a[8];
#pragma unroll
            for (int i = 0; i < 8; i++) a[i] = As[ty * 8 + i][kk];
            float4 b0 = *(const float4*)&Bs[kk][tx * 8];
            float4 b1 = *(const float4*)&Bs[kk][tx * 8 + 4];
            float bv[8] = {b0.x, b0.y, b0.z, b0.w, b1.x, b1.y, b1.z, b1.w};
#pragma unroll
            for (int i = 0; i < 8; i++)
#pragma unroll
                for (int j = 0; j < 8; j++) acc[i][j] += a[i] * bv[j];
        }
        __syncthreads();
    }

#pragma unroll
    for (int i = 0; i < 8; i++) {
        size_t row = (size_t)(m0 + ty * 8 + i) * DM + n0;
#pragma unroll
        for (int half = 0; half < 2; half++) {
            float4 v = make_float4(acc[i][half * 4 + 0], acc[i][half * 4 + 1],
                                   acc[i][half * 4 + 2], acc[i][half * 4 + 3]);
            *(float4*)&out[row + tx * 8 + half * 4] = v;
        }
    }
}

// ---------------------------------------------------------------------------
extern "C" void kernel_launch(void* const* d_in, const int* in_sizes, int n_in,
                              void* d_out, int out_size)
{
    const float* x  = (const float*)d_in[0];
    const float* Wq = (const float*)d_in[1];
    const float* Wk = (const float*)d_in[2];
    const float* Wv = (const float*)d_in[3];
    const float* Wo = (const float*)d_in[4];
    float* out = (float*)d_out;

    cudaFuncSetAttribute(attn_kernel,
                         cudaFuncAttributeMaxDynamicSharedMemorySize,
                         ATTN_SMEM_BYTES);

    qkv_kernel<<<dim3(SEQ / 128, BATCH * (NH / 2), 3), 256>>>(x, Wq, Wk, Wv);
    attn_kernel<<<dim3(SEQ / 128, BATCH * NH), 256, ATTN_SMEM_BYTES>>>();
    proj_kernel<<<dim3(DM / 128, (BATCH * SEQ) / 128), 256>>>(Wo, out);
}

// round 5
// speedup vs baseline: 1.5990x; 1.5953x over previous
#include <cuda_runtime.h>
#include <cuda_bf16.h>
#include <math.h>
#include <stdint.h>

#define BATCH 4
#define SEQ   2048
#define DIN   1024
#define NH    16
#define DKH   64
#define DM    1024
#define LOG2E 1.4426950408889634f

// ---------------- scratch globals (no allocation allowed) -------------------
__device__ float g_Q[(size_t)BATCH*NH*SEQ*DKH];
__device__ float g_K[(size_t)BATCH*NH*SEQ*DKH];
__device__ float g_V[(size_t)BATCH*NH*SEQ*DKH];
__device__ __align__(128) __nv_bfloat16 g_xhi[(size_t)BATCH*SEQ*DIN];
__device__ __align__(128) __nv_bfloat16 g_xlo[(size_t)BATCH*SEQ*DIN];
__device__ __align__(128) __nv_bfloat16 g_wt_h[(size_t)4<<20];  // Wq,Wk,Wv,Wo transposed [n][k]
__device__ __align__(128) __nv_bfloat16 g_wt_l[(size_t)4<<20];
__device__ __align__(128) __nv_bfloat16 g_Ahi[(size_t)BATCH*SEQ*DM];
__device__ __align__(128) __nv_bfloat16 g_Alo[(size_t)BATCH*SEQ*DM];

// ---------------- PTX helpers (sm_100 baseline: ldmatrix / mma.sync) --------
__device__ __forceinline__ uint32_t smem_u32(const void* p) {
    uint32_t a;
    asm("{ .reg .u64 t; cvta.to.shared.u64 t, %1; cvt.u32.u64 %0, t; }" : "=r"(a) : "l"(p));
    return a;
}
__device__ __forceinline__ void ldsm4(uint32_t* f, uint32_t addr) {
    asm volatile("ldmatrix.sync.aligned.m8n8.x4.shared.b16 {%0,%1,%2,%3}, [%4];"
                 : "=r"(f[0]), "=r"(f[1]), "=r"(f[2]), "=r"(f[3]) : "r"(addr));
}
__device__ __forceinline__ void mma16816(float* c, const uint32_t* a, const uint32_t* b) {
    asm volatile(
        "mma.sync.aligned.m16n8k16.row.col.f32.bf16.bf16.f32 "
        "{%0,%1,%2,%3}, {%4,%5,%6,%7}, {%8,%9}, {%0,%1,%2,%3};"
        : "+f"(c[0]), "+f"(c[1]), "+f"(c[2]), "+f"(c[3])
        : "r"(a[0]), "r"(a[1]), "r"(a[2]), "r"(a[3]), "r"(b[0]), "r"(b[1]));
}

// ---------------- prep: fp32 -> bf16 hi/lo splits ---------------------------
__global__ void split_x_kernel(const float* __restrict__ x) {
    size_t i0 = ((size_t)blockIdx.x * 256 + threadIdx.x) * 4;
    float4 v = *(const float4*)(x + i0);
    float vv[4] = {v.x, v.y, v.z, v.w};
    __nv_bfloat16 h[4], l[4];
#pragma unroll
    for (int j = 0; j < 4; j++) {
        h[j] = __float2bfloat16(vv[j]);
        l[j] = __float2bfloat16(vv[j] - __bfloat162float(h[j]));
    }
    *(uint2*)(g_xhi + i0) = *(uint2*)h;
    *(uint2*)(g_xlo + i0) = *(uint2*)l;
}

// transpose matrix z ([R][C] -> [C][R]) with hi/lo split into g_wt_{h,l}[which]
__global__ void tsplit_kernel(const float* __restrict__ in, int which, int R, int C) {
    __shared__ float t[32][33];
    const int z = blockIdx.z;
    const int c0 = blockIdx.x * 32, r0 = blockIdx.y * 32;
    const int tx = threadIdx.x, ty = threadIdx.y;
    const float* inp = in + (size_t)z * R * C;
#pragma unroll
    for (int k = 0; k < 4; k++)
        t[ty + 8 * k][tx] = inp[(size_t)(r0 + ty + 8 * k) * C + c0 + tx];
    __syncthreads();
    __nv_bfloat16* oh = g_wt_h + ((size_t)which << 20) + (size_t)z * R * C;
    __nv_bfloat16* ol = g_wt_l + ((size_t)which << 20) + (size_t)z * R * C;
#pragma unroll
    for (int k = 0; k < 4; k++) {
        float v = t[tx][ty + 8 * k];
        __nv_bfloat16 hb = __float2bfloat16(v);
        size_t o = (size_t)(c0 + ty + 8 * k) * R + r0 + tx;
        oh[o] = hb;
        ol[o] = __float2bfloat16(v - __bfloat162float(hb));
    }
}

// ---------------- HMMA GEMM: C = A @ B^T, bf16x3, fp32 accum ----------------
// Block 128x128, 8 warps (2 M x 4 N), warp tile 64x32, k-chunk 32, 2 stages.
// smem tile row stride 80 B (32 bf16 data + 16 B pad) -> ldmatrix conflict-free.
// MODE 0: A = x split, B = Wq/Wk/Wv^T (z), out per-head fp32 g_Q/g_K/g_V.
// MODE 1: A = attn out split, B = Wo^T, out row-major fp32 (d_out).
#define KC 32
#define TILE_B   10240          // 128 rows * 80 B
#define STG_BYTES (4 * TILE_B)  // Ah | Al | Bh | Bl
#define GEMM_SMEM (2 * STG_BYTES)

__device__ __forceinline__ void copy_chunk(int tid, uint32_t stg, int kc, int m0, int n0,
    const __nv_bfloat16* Ah, const __nv_bfloat16* Al,
    const __nv_bfloat16* Bh, const __nv_bfloat16* Bl)
{
    const int ko = kc * 32;
#pragma unroll
    for (int i = 0; i < 8; i++) {
        int idx = tid + i * 256;
        int tile = idx >> 9, r = (idx >> 2) & 127, c = idx & 3;
        const __nv_bfloat16* base = (tile == 0) ? Ah : (tile == 1) ? Al
                                  : (tile == 2) ? Bh : Bl;
        int rowg = ((tile < 2) ? m0 : n0) + r;
        const __nv_bfloat16* src = base + (size_t)rowg * 1024 + ko + c * 8;
        uint32_t dst = stg + tile * TILE_B + r * 80 + c * 16;
        asm volatile("cp.async.cg.shared.global [%0], [%1], 16;" :: "r"(dst), "l"(src));
    }
    asm volatile("cp.async.commit_group;" ::: "memory");
}

template<int MODE>
__global__ __launch_bounds__(256, 1) void gemm_mma(float* __restrict__ outp_)
{
    extern __shared__ __align__(128) char dsm[];
    const uint32_t sb = smem_u32(dsm);
    const int tid = threadIdx.x, wid = tid >> 5, lane = tid & 31;
    const int warp_m = wid >> 2, warp_n = wid & 3;
    const int m0 = blockIdx.x * 128, n0 = blockIdx.y * 128, z = blockIdx.z;

    const __nv_bfloat16* Bh = g_wt_h + ((size_t)(MODE ? 3 : z) << 20);
    const __nv_bfloat16* Bl = g_wt_l + ((size_t)(MODE ? 3 : z) << 20);
    const __nv_bfloat16* Ah = (MODE == 0) ? g_xhi : g_Ahi;
    const __nv_bfloat16* Al = (MODE == 0) ? g_xlo : g_Alo;
    float* outp = (MODE == 1) ? outp_ : (z == 0 ? g_Q : z == 1 ? g_K : g_V);

    // per-lane ldmatrix base offsets (bytes) within a tile
    const uint32_t a_off = (uint32_t)(warp_m * 64 + (lane & 15)) * 80 + (lane >> 4) * 16;
    const uint32_t b_off = (uint32_t)(warp_n * 32 + (lane >> 4) * 8 + (lane & 7)) * 80
                         + ((lane >> 3) & 1) * 16;

    float acc[4][4][4];
#pragma unroll
    for (int i = 0; i < 4; i++)
#pragma unroll
        for (int j = 0; j < 4; j++)
#pragma unroll
            for (int k = 0; k < 4; k++) acc[i][j][k] = 0.f;

    copy_chunk(tid, sb, 0, m0, n0, Ah, Al, Bh, Bl);

    for (int kc = 0; kc < KC; kc++) {
        const uint32_t cur = kc & 1;
        if (kc + 1 < KC) {
            copy_chunk(tid, sb + (cur ^ 1) * STG_BYTES, kc + 1, m0, n0, Ah, Al, Bh, Bl);
            asm volatile("cp.async.wait_group 1;" ::: "memory");
        } else {
            asm volatile("cp.async.wait_group 0;" ::: "memory");
        }
        __syncthreads();

        const uint32_t stg = sb + cur * STG_BYTES;
#pragma unroll
        for (int ks = 0; ks < 2; ks++) {
            uint32_t ah[4][4], al[4][4], bh[2][4], bl[2][4];
#pragma unroll
            for (int mt = 0; mt < 4; mt++) {
                ldsm4(ah[mt], stg + 0 * TILE_B + a_off + mt * (16 * 80) + ks * 32);
                ldsm4(al[mt], stg + 1 * TILE_B + a_off + mt * (16 * 80) + ks * 32);
            }
#pragma unroll
            for (int pr = 0; pr < 2; pr++) {
                ldsm4(bh[pr], stg + 2 * TILE_B + b_off + pr * (16 * 80) + ks * 32);
                ldsm4(bl[pr], stg + 3 * TILE_B + b_off + pr * (16 * 80) + ks * 32);
            }
#pragma unroll
            for (int mt = 0; mt < 4; mt++)
#pragma unroll
                for (int nt = 0; nt < 4; nt++) {
                    float* c = acc[mt][nt];
                    const uint32_t* ph = &bh[nt >> 1][(nt & 1) * 2];
                    const uint32_t* pl = &bl[nt >> 1][(nt & 1) * 2];
                    mma16816(c, ah[mt], ph);   // hi * hi
                    mma16816(c, ah[mt], pl);   // hi * lo
                    mma16816(c, al[mt], ph);   // lo * hi
                }
        }
        __syncthreads();
    }

    // epilogue: c frag thread map: rows t/4, t/4+8; cols 2*(t%4), +1
    const int tg = lane >> 2, tq = lane & 3;
#pragma unroll
    for (int mt = 0; mt < 4; mt++) {
#pragma unroll
        for (int nt = 0; nt < 4; nt++) {
            int row = m0 + warp_m * 64 + mt * 16 + tg;
            int col = n0 + warp_n * 32 + nt * 8 + tq * 2;
            float* dst0;
            float* dst1;
            if (MODE == 0) {
                int h = col >> 6, dk = col & 63;
                int b = row >> 11, s = row & 2047;
                size_t base = ((size_t)(b * NH + h) * SEQ + s) * DKH + dk;
                dst0 = outp + base;
                dst1 = outp + base + 8 * DKH;   // row+8, same b (rows within 16-blk)
            } else {
                dst0 = outp + (size_t)row * DM + col;
                dst1 = outp + (size_t)(row + 8) * DM + col;
            }
            *(float2*)dst0 = make_float2(acc[mt][nt][0], acc[mt][nt][1]);
            *(float2*)dst1 = make_float2(acc[mt][nt][2], acc[mt][nt][3]);
        }
    }
}

// ---------------- causal flash attention (fp32 SIMT, proven) ----------------
#define ATTN_SMEM_FLOATS (64 * 132 + 64 * 68 + 64 * 68 + 64 * 132)
#define ATTN_SMEM_BYTES  (ATTN_SMEM_FLOATS * 4)

__global__ __launch_bounds__(256, 2) void attn_kernel()
{
    extern __shared__ float smf[];
    float* QsT = smf;
    float* KsT = QsT + 64 * 132;
    float* Vsm = KsT + 64 * 68;
    float* PsT = Vsm + 64 * 68;

    const int qi = (int)gridDim.x - 1 - (int)blockIdx.x;
    const int q0 = qi * 128;
    const int bh = blockIdx.y;
    const int b = bh / NH, h = bh % NH;
    const int tid = threadIdx.x;
    const int tx = tid & 15;
    const int ty = tid >> 4;

    const float* Qb = g_Q + ((size_t)bh * SEQ + q0) * DKH;
    const float* Kb = g_K + (size_t)bh * SEQ * DKH;
    const float* Vb = g_V + (size_t)bh * SEQ * DKH;

    for (int i = tid; i < 128 * 64; i += 256) {
        int m = i >> 6, k = i & 63;
        QsT[k * 132 + m] = Qb[i] * 0.125f;
    }

    float O[8][4], mrow[8], lrow[8];
#pragma unroll
    for (int i = 0; i < 8; i++) {
        mrow[i] = -1e30f; lrow[i] = 0.f;
#pragma unroll
        for (int j = 0; j < 4; j++) O[i][j] = 0.f;
    }

    const int njt = 2 * qi + 2;
    for (int j = 0; j < njt; j++) {
        __syncthreads();
        const float* Kt = Kb + (size_t)j * 64 * DKH;
        const float* Vt = Vb + (size_t)j * 64 * DKH;
        for (int i = tid; i < 64 * 64; i += 256) {
            int n = i >> 6, k = i & 63;
            KsT[k * 68 + n] = Kt[i];
            Vsm[n * 68 + k] = Vt[i];
        }
        __syncthreads();

        float s[8][4];
#pragma unroll
        for (int i = 0; i < 8; i++)
#pragma unroll
            for (int jj = 0; jj < 4; jj++) s[i][jj] = 0.f;

#pragma unroll 4
        for (int k = 0; k < 64; k++) {
            float4 a0 = *(const float4*)&QsT[k * 132 + ty * 8];
            float4 a1 = *(const float4*)&QsT[k * 132 + ty * 8 + 4];
            float4 bb = *(const float4*)&KsT[k * 68 + tx * 4];
            float a[8] = {a0.x, a0.y, a0.z, a0.w, a1.x, a1.y, a1.z, a1.w};
            float bv[4] = {bb.x, bb.y, bb.z, bb.w};
#pragma unroll
            for (int i = 0; i < 8; i++)
#pragma unroll
                for (int jj = 0; jj < 4; jj++) s[i][jj] += a[i] * bv[jj];
        }

        if (j >= 2 * qi) {
#pragma unroll
            for (int i = 0; i < 8; i++) {
                int m = q0 + ty * 8 + i;
#pragma unroll
                for (int jj = 0; jj < 4; jj++) {
                    int n = j * 64 + tx * 4 + jj;
                    if (n > m) s[i][jj] = -1e30f;
                }
            }
        }

#pragma unroll
        for (int i = 0; i < 8; i++) {
            float t = fmaxf(fmaxf(s[i][0], s[i][1]), fmaxf(s[i][2], s[i][3]));
            t = fmaxf(t, __shfl_xor_sync(0xffffffffu, t, 1));
            t = fmaxf(t, __shfl_xor_sync(0xffffffffu, t, 2));
            t = fmaxf(t, __shfl_xor_sync(0xffffffffu, t, 4));
            t = fmaxf(t, __shfl_xor_sync(0xffffffffu, t, 8));
            float mnew  = fmaxf(mrow[i], t);
            float alpha = exp2f((mrow[i] - mnew) * LOG2E);
            float rs = 0.f;
#pragma unroll
            for (int jj = 0; jj < 4; jj++) {
                float p = exp2f((s[i][jj] - mnew) * LOG2E);
                s[i][jj] = p;
                rs += p;
            }
            rs += __shfl_xor_sync(0xffffffffu, rs, 1);
            rs += __shfl_xor_sync(0xffffffffu, rs, 2);
            rs += __shfl_xor_sync(0xffffffffu, rs, 4);
            rs += __shfl_xor_sync(0xffffffffu, rs, 8);
            lrow[i] = lrow[i] * alpha + rs;
            mrow[i] = mnew;
#pragma unroll
            for (int jj = 0; jj < 4; jj++) O[i][jj] *= alpha;
        }

#pragma unroll
        for (int jj = 0; jj < 4; jj++) {
            int n = tx * 4 + jj;
            float4 v0 = make_float4(s[0][jj], s[1][jj], s[2][jj], s[3][jj]);
            float4 v1 = make_float4(s[4][jj], s[5][jj], s[6][jj], s[7][jj]);
            *(float4*)&PsT[n * 132 + ty * 8]     = v0;
            *(float4*)&PsT[n * 132 + ty * 8 + 4] = v1;
        }
        __syncthreads();

#pragma unroll 4
        for (int n = 0; n < 64; n++) {
            float4 a0 = *(const float4*)&PsT[n * 132 + ty * 8];
            float4 a1 = *(const float4*)&PsT[n * 132 + ty * 8 + 4];
            float4 bb = *(const float4*)&Vsm[n * 68 + tx * 4];
            float a[8] = {a0.x, a0.y, a0.z, a0.w, a1.x, a1.y, a1.z, a1.w};
            float bv[4] = {bb.x, bb.y, bb.z, bb.w};
#pragma unroll
            for (int i = 0; i < 8; i++)
#pragma unroll
                for (int jj = 0; jj < 4; jj++) O[i][jj] += a[i] * bv[jj];
        }
    }

    // epilogue: normalize + bf16 hi/lo split for the tensor-core projection
#pragma unroll
    for (int i = 0; i < 8; i++) {
        float inv = 1.0f / lrow[i];
        int srow = q0 + ty * 8 + i;
        size_t base = ((size_t)b * SEQ + srow) * DM + h * DKH + tx * 4;
        __nv_bfloat16 hh[4], ll[4];
#pragma unroll
        for (int jj = 0; jj < 4; jj++) {
            float v = O[i][jj] * inv;
            hh[jj] = __float2bfloat16(v);
            ll[jj] = __float2bfloat16(v - __bfloat162float(hh[jj]));
        }
        *(uint2*)&g_Ahi[base] = *(uint2*)hh;
        *(uint2*)&g_Alo[base] = *(uint2*)ll;
    }
}

// ---------------------------------------------------------------------------
extern "C" void kernel_launch(void* const* d_in, const int* in_sizes, int n_in,
                              void* d_out, int out_size)
{
    const float* x  = (const float*)d_in[0];
    const float* Wq = (const float*)d_in[1];
    const float* Wk = (const float*)d_in[2];
    const float* Wv = (const float*)d_in[3];
    const float* Wo = (const float*)d_in[4];
    float* out = (float*)d_out;

    cudaFuncSetAttribute(attn_kernel, cudaFuncAttributeMaxDynamicSharedMemorySize,
                         ATTN_SMEM_BYTES);
    cudaFuncSetAttribute(gemm_mma<0>, cudaFuncAttributeMaxDynamicSharedMemorySize,
                         GEMM_SMEM);
    cudaFuncSetAttribute(gemm_mma<1>, cudaFuncAttributeMaxDynamicSharedMemorySize,
                         GEMM_SMEM);

    split_x_kernel<<<8192, 256>>>(x);
    tsplit_kernel<<<dim3(2, 32, 16), dim3(32, 8)>>>(Wq, 0, 1024, 64);
    tsplit_kernel<<<dim3(2, 32, 16), dim3(32, 8)>>>(Wk, 1, 1024, 64);
    tsplit_kernel<<<dim3(2, 32, 16), dim3(32, 8)>>>(Wv, 2, 1024, 64);
    tsplit_kernel<<<dim3(32, 32, 1), dim3(32, 8)>>>(Wo, 3, 1024, 1024);

    gemm_mma<0><<<dim3(64, 8, 3), 256, GEMM_SMEM>>>(nullptr);
    attn_kernel<<<dim3(SEQ / 128, BATCH * NH), 256, ATTN_SMEM_BYTES>>>();
    gemm_mma<1><<<dim3(64, 8, 1), 256, GEMM_SMEM>>>(out);
}

// round 7
// speedup vs baseline: 2.6709x; 1.6703x over previous
#include <cuda_runtime.h>
#include <cuda_bf16.h>
#include <math.h>
#include <stdint.h>
#include <string.h>

#define BATCH 4
#define SEQ   2048
#define DIN   1024
#define NH    16
#define DKH   64
#define DM    1024
#define QKV_ELE ((size_t)BATCH*NH*SEQ*DKH)   // 8388608
#define QSCALE 0.18033688011112042f          // 0.125 * log2(e): softmax in base 2

// ---------------- scratch globals (no allocation allowed) -------------------
__device__ __align__(128) __nv_bfloat16 g_xhi[(size_t)BATCH*SEQ*DIN];
__device__ __align__(128) __nv_bfloat16 g_xlo[(size_t)BATCH*SEQ*DIN];
__device__ __align__(128) __nv_bfloat16 g_wt_h[(size_t)4<<20];  // Wq,Wk,Wv,Wo transposed [n][k]
__device__ __align__(128) __nv_bfloat16 g_wt_l[(size_t)4<<20];
__device__ __align__(128) __nv_bfloat16 g_qkvh[3*QKV_ELE];      // Q,K,V per-head bf16 hi
__device__ __align__(128) __nv_bfloat16 g_qkvl[3*QKV_ELE];      // lo
__device__ __align__(128) __nv_bfloat16 g_Ahi[(size_t)BATCH*SEQ*DM];
__device__ __align__(128) __nv_bfloat16 g_Alo[(size_t)BATCH*SEQ*DM];

// ---------------- PTX helpers (sm_100 baseline: ldmatrix / mma.sync) --------
__device__ __forceinline__ uint32_t smem_u32(const void* p) {
    uint32_t a;
    asm("{ .reg .u64 t; cvta.to.shared.u64 t, %1; cvt.u32.u64 %0, t; }" : "=r"(a) : "l"(p));
    return a;
}
__device__ __forceinline__ void ldsm4(uint32_t* f, uint32_t addr) {
    asm volatile("ldmatrix.sync.aligned.m8n8.x4.shared.b16 {%0,%1,%2,%3}, [%4];"
                 : "=r"(f[0]), "=r"(f[1]), "=r"(f[2]), "=r"(f[3]) : "r"(addr));
}
__device__ __forceinline__ void ldsm4t(uint32_t* f, uint32_t addr) {
    asm volatile("ldmatrix.sync.aligned.m8n8.x4.trans.shared.b16 {%0,%1,%2,%3}, [%4];"
                 : "=r"(f[0]), "=r"(f[1]), "=r"(f[2]), "=r"(f[3]) : "r"(addr));
}
__device__ __forceinline__ void mma16816(float* c, const uint32_t* a, const uint32_t* b) {
    asm volatile(
        "mma.sync.aligned.m16n8k16.row.col.f32.bf16.bf16.f32 "
        "{%0,%1,%2,%3}, {%4,%5,%6,%7}, {%8,%9}, {%0,%1,%2,%3};"
        : "+f"(c[0]), "+f"(c[1]), "+f"(c[2]), "+f"(c[3])
        : "r"(a[0]), "r"(a[1]), "r"(a[2]), "r"(a[3]), "r"(b[0]), "r"(b[1]));
}
__device__ __forceinline__ void cp16(uint32_t dst, const void* src) {
    asm volatile("cp.async.cg.shared.global [%0], [%1], 16;" :: "r"(dst), "l"(src));
}
__device__ __forceinline__ float ex2(float x) {
    float y; asm("ex2.approx.ftz.f32 %0, %1;" : "=f"(y) : "f"(x)); return y;
}
__device__ __forceinline__ uint32_t b2u(__nv_bfloat162 v) {
    uint32_t u; memcpy(&u, &v, 4); return u;
}

// ---------------- prep: fp32 -> bf16 hi/lo splits ---------------------------
__global__ void split_x_kernel(const float* __restrict__ x) {
    size_t i0 = ((size_t)blockIdx.x * 256 + threadIdx.x) * 4;
    float4 v = *(const float4*)(x + i0);
    float vv[4] = {v.x, v.y, v.z, v.w};
    __nv_bfloat16 h[4], l[4];
#pragma unroll
    for (int j = 0; j < 4; j++) {
        h[j] = __float2bfloat16(vv[j]);
        l[j] = __float2bfloat16(vv[j] - __bfloat162float(h[j]));
    }
    *(uint2*)(g_xhi + i0) = *(uint2*)h;
    *(uint2*)(g_xlo + i0) = *(uint2*)l;
}

__global__ void tsplit_kernel(const float* __restrict__ in, int which, int R, int C) {
    __shared__ float t[32][33];
    const int z = blockIdx.z;
    const int c0 = blockIdx.x * 32, r0 = blockIdx.y * 32;
    const int tx = threadIdx.x, ty = threadIdx.y;
    const float* inp = in + (size_t)z * R * C;
#pragma unroll
    for (int k = 0; k < 4; k++)
        t[ty + 8 * k][tx] = inp[(size_t)(r0 + ty + 8 * k) * C + c0 + tx];
    __syncthreads();
    __nv_bfloat16* oh = g_wt_h + ((size_t)which << 20) + (size_t)z * R * C;
    __nv_bfloat16* ol = g_wt_l + ((size_t)which << 20) + (size_t)z * R * C;
#pragma unroll
    for (int k = 0; k < 4; k++) {
        float v = t[tx][ty + 8 * k];
        __nv_bfloat16 hb = __float2bfloat16(v);
        size_t o = (size_t)(c0 + ty + 8 * k) * R + r0 + tx;
        oh[o] = hb;
        ol[o] = __float2bfloat16(v - __bfloat162float(hb));
    }
}

// ---------------- HMMA GEMM: C = A @ B^T, bf16x3, fp32 accum ----------------
// MODE 0: A = x split, B = Wq/Wk/Wv^T (z), out bf16 hi/lo per-head (Q pre-scaled).
// MODE 1: A = attn out split, B = Wo^T, out row-major fp32 (d_out).
#define KC 32
#define TILE_B   10240
#define STG_BYTES (4 * TILE_B)
#define GEMM_SMEM (2 * STG_BYTES)

__device__ __forceinline__ void copy_chunk(int tid, uint32_t stg, int kc, int m0, int n0,
    const __nv_bfloat16* Ah, const __nv_bfloat16* Al,
    const __nv_bfloat16* Bh, const __nv_bfloat16* Bl)
{
    const int ko = kc * 32;
#pragma unroll
    for (int i = 0; i < 8; i++) {
        int idx = tid + i * 256;
        int tile = idx >> 9, r = (idx >> 2) & 127, c = idx & 3;
        const __nv_bfloat16* base = (tile == 0) ? Ah : (tile == 1) ? Al
                                  : (tile == 2) ? Bh : Bl;
        int rowg = ((tile < 2) ? m0 : n0) + r;
        const __nv_bfloat16* src = base + (size_t)rowg * 1024 + ko + c * 8;
        uint32_t dst = stg + tile * TILE_B + r * 80 + c * 16;
        cp16(dst, src);
    }
    asm volatile("cp.async.commit_group;" ::: "memory");
}

template<int MODE>
__global__ __launch_bounds__(256, 1) void gemm_mma(float* __restrict__ outp_)
{
    extern __shared__ __align__(128) char dsm[];
    const uint32_t sb = smem_u32(dsm);
    const int tid = threadIdx.x, wid = tid >> 5, lane = tid & 31;
    const int warp_m = wid >> 2, warp_n = wid & 3;
    const int m0 = blockIdx.x * 128, n0 = blockIdx.y * 128, z = blockIdx.z;

    const __nv_bfloat16* Bh = g_wt_h + ((size_t)(MODE ? 3 : z) << 20);
    const __nv_bfloat16* Bl = g_wt_l + ((size_t)(MODE ? 3 : z) << 20);
    const __nv_bfloat16* Ah = (MODE == 0) ? g_xhi : g_Ahi;
    const __nv_bfloat16* Al = (MODE == 0) ? g_xlo : g_Alo;

    const uint32_t a_off = (uint32_t)(warp_m * 64 + (lane & 15)) * 80 + (lane >> 4) * 16;
    const uint32_t b_off = (uint32_t)(warp_n * 32 + (lane >> 4) * 8 + (lane & 7)) * 80
                         + ((lane >> 3) & 1) * 16;

    float acc[4][4][4];
#pragma unroll
    for (int i = 0; i < 4; i++)
#pragma unroll
        for (int j = 0; j < 4; j++)
#pragma unroll
            for (int k = 0; k < 4; k++) acc[i][j][k] = 0.f;

    copy_chunk(tid, sb, 0, m0, n0, Ah, Al, Bh, Bl);

    for (int kc = 0; kc < KC; kc++) {
        const uint32_t cur = kc & 1;
        if (kc + 1 < KC) {
            copy_chunk(tid, sb + (cur ^ 1) * STG_BYTES, kc + 1, m0, n0, Ah, Al, Bh, Bl);
            asm volatile("cp.async.wait_group 1;" ::: "memory");
        } else {
            asm volatile("cp.async.wait_group 0;" ::: "memory");
        }
        __syncthreads();

        const uint32_t stg = sb + cur * STG_BYTES;
#pragma unroll
        for (int ks = 0; ks < 2; ks++) {
            uint32_t ah[4][4], al[4][4], bh[2][4], bl[2][4];
#pragma unroll
            for (int mt = 0; mt < 4; mt++) {
                ldsm4(ah[mt], stg + 0 * TILE_B + a_off + mt * (16 * 80) + ks * 32);
                ldsm4(al[mt], stg + 1 * TILE_B + a_off + mt * (16 * 80) + ks * 32);
            }
#pragma unroll
            for (int pr = 0; pr < 2; pr++) {
                ldsm4(bh[pr], stg + 2 * TILE_B + b_off + pr * (16 * 80) + ks * 32);
                ldsm4(bl[pr], stg + 3 * TILE_B + b_off + pr * (16 * 80) + ks * 32);
            }
#pragma unroll
            for (int mt = 0; mt < 4; mt++)
#pragma unroll
                for (int nt = 0; nt < 4; nt++) {
                    float* c = acc[mt][nt];
                    const uint32_t* ph = &bh[nt >> 1][(nt & 1) * 2];
                    const uint32_t* pl = &bl[nt >> 1][(nt & 1) * 2];
                    mma16816(c, ah[mt], ph);
                    mma16816(c, ah[mt], pl);
                    mma16816(c, al[mt], ph);
                }
        }
        __syncthreads();
    }

    const int tg = lane >> 2, tq = lane & 3;
#pragma unroll
    for (int mt = 0; mt < 4; mt++) {
#pragma unroll
        for (int nt = 0; nt < 4; nt++) {
            int row = m0 + warp_m * 64 + mt * 16 + tg;
            int col = n0 + warp_n * 32 + nt * 8 + tq * 2;
            if (MODE == 0) {
                const float scale = (z == 0) ? QSCALE : 1.0f;
                int bb = row >> 11, ss = row & 2047, hh = col >> 6, dk = col & 63;
                size_t base = (size_t)z * QKV_ELE
                            + (((size_t)(bb * NH + hh)) * SEQ + ss) * DKH + dk;
                float v0 = acc[mt][nt][0] * scale, v1 = acc[mt][nt][1] * scale;
                float v2 = acc[mt][nt][2] * scale, v3 = acc[mt][nt][3] * scale;
                __nv_bfloat162 h0 = __floats2bfloat162_rn(v0, v1);
                __nv_bfloat162 h1 = __floats2bfloat162_rn(v2, v3);
                __nv_bfloat162 l0 = __floats2bfloat162_rn(v0 - __low2float(h0),
                                                          v1 - __high2float(h0));
                __nv_bfloat162 l1 = __floats2bfloat162_rn(v2 - __low2float(h1),
                                                          v3 - __high2float(h1));
                *(__nv_bfloat162*)&g_qkvh[base]           = h0;
                *(__nv_bfloat162*)&g_qkvh[base + 8 * DKH] = h1;
                *(__nv_bfloat162*)&g_qkvl[base]           = l0;
                *(__nv_bfloat162*)&g_qkvl[base + 8 * DKH] = l1;
            } else {
                float* dst0 = outp_ + (size_t)row * DM + col;
                float* dst1 = outp_ + (size_t)(row + 8) * DM + col;
                *(float2*)dst0 = make_float2(acc[mt][nt][0], acc[mt][nt][1]);
                *(float2*)dst1 = make_float2(acc[mt][nt][2], acc[mt][nt][3]);
            }
        }
    }
}

// ---------------- causal flash attention on HMMA ----------------------------
// BM=128 (8 warps x 16 rows), BN=64, d=64. bf16x3 for QK^T and PV.
#define AT_STRIDE 144
#define Q_TILE_B   (128 * AT_STRIDE)        // 18432
#define KV_ARR_B   (64 * AT_STRIDE)         // 9216
#define KV_STAGE_B (4 * KV_ARR_B)           // 36864
#define ATT_SMEM   (2 * Q_TILE_B + 2 * KV_STAGE_B)   // 110592

__device__ __forceinline__ void load_kv(int tid, uint32_t stg, int j,
    const __nv_bfloat16* Khg, const __nv_bfloat16* Klg,
    const __nv_bfloat16* Vhg, const __nv_bfloat16* Vlg)
{
#pragma unroll
    for (int it = 0; it < 8; it++) {
        int i = tid + it * 256;
        int arr = i >> 9, r = (i >> 3) & 63, c = i & 7;
        const __nv_bfloat16* src = (arr == 0 ? Khg : arr == 1 ? Klg
                                  : arr == 2 ? Vhg : Vlg) + ((size_t)(j * 64 + r)) * DKH + c * 8;
        cp16(stg + arr * KV_ARR_B + r * AT_STRIDE + c * 16, src);
    }
    asm volatile("cp.async.commit_group;" ::: "memory");
}

__global__ __launch_bounds__(256, 1) void attn_mma()
{
    extern __shared__ __align__(128) char dsm[];
    const uint32_t sb = smem_u32(dsm);
    const uint32_t sQh = sb, sQl = sb + Q_TILE_B;
    const uint32_t sKV = sb + 2 * Q_TILE_B;

    const int qi = (int)gridDim.x - 1 - (int)blockIdx.x;   // heavy tiles first
    const int q0 = qi * 128;
    const int bh = blockIdx.y;
    const int b = bh >> 4, h = bh & 15;
    const int tid = threadIdx.x, w = tid >> 5, lane = tid & 31;

    const __nv_bfloat16* Qhg = g_qkvh + ((size_t)bh * SEQ + q0) * DKH;
    const __nv_bfloat16* Qlg = g_qkvl + ((size_t)bh * SEQ + q0) * DKH;
    const __nv_bfloat16* Khg = g_qkvh + QKV_ELE     + (size_t)bh * SEQ * DKH;
    const __nv_bfloat16* Klg = g_qkvl + QKV_ELE     + (size_t)bh * SEQ * DKH;
    const __nv_bfloat16* Vhg = g_qkvh + 2 * QKV_ELE + (size_t)bh * SEQ * DKH;
    const __nv_bfloat16* Vlg = g_qkvl + 2 * QKV_ELE + (size_t)bh * SEQ * DKH;

    // Q (hi+lo) -> smem, group 0
#pragma unroll
    for (int it = 0; it < 8; it++) {
        int i = tid + it * 256;
        int half = i >> 10, r = (i >> 3) & 127, c = i & 7;
        const __nv_bfloat16* src = (half ? Qlg : Qhg) + (size_t)r * DKH + c * 8;
        cp16((half ? sQl : sQh) + r * AT_STRIDE + c * 16, src);
    }
    asm volatile("cp.async.commit_group;" ::: "memory");

    load_kv(tid, sKV, 0, Khg, Klg, Vhg, Vlg);

    float O[8][4];
#pragma unroll
    for (int i = 0; i < 8; i++)
#pragma unroll
        for (int j = 0; j < 4; j++) O[i][j] = 0.f;
    float m0 = -1e30f, m1 = -1e30f, l0 = 0.f, l1 = 0.f;

    const uint32_t qa_base = (uint32_t)(w * 16 + (lane & 15)) * AT_STRIDE + (lane >> 4) * 16;
    const uint32_t kb_base = (uint32_t)((lane & 7) + ((lane >> 4) & 1) * 8) * AT_STRIDE
                           + ((lane >> 3) & 1) * 16;
    const uint32_t vb_base = (uint32_t)(lane & 15) * AT_STRIDE + (lane >> 4) * 16;

    const int njt = 2 * qi + 2;
    for (int j = 0; j < njt; j++) {
        const uint32_t st = sKV + (uint32_t)(j & 1) * KV_STAGE_B;
        if (j + 1 < njt) {
            load_kv(tid, sKV + (uint32_t)((j + 1) & 1) * KV_STAGE_B, j + 1,
                    Khg, Klg, Vhg, Vlg);
            asm volatile("cp.async.wait_group 1;" ::: "memory");
        } else {
            asm volatile("cp.async.wait_group 0;" ::: "memory");
        }
        __syncthreads();

        // ---- S = Qs @ K^T (fp32 via bf16x3) ----
        float s[8][4];
#pragma unroll
        for (int i = 0; i < 8; i++)
#pragma unroll
            for (int jj = 0; jj < 4; jj++) s[i][jj] = 0.f;

#pragma unroll
        for (int ks = 0; ks < 4; ks++) {
            uint32_t qh[4], ql[4];
            ldsm4(qh, sQh + qa_base + ks * 32);
            ldsm4(ql, sQl + qa_base + ks * 32);
#pragma unroll
            for (int ng = 0; ng < 4; ng++) {
                uint32_t kh[4], kl[4];
                uint32_t ko = kb_base + ng * (16 * AT_STRIDE) + ks * 32;
                ldsm4(kh, st + 0 * KV_ARR_B + ko);
                ldsm4(kl, st + 1 * KV_ARR_B + ko);
                mma16816(s[2 * ng],     qh, &kh[0]);
                mma16816(s[2 * ng],     qh, &kl[0]);
                mma16816(s[2 * ng],     ql, &kh[0]);
                mma16816(s[2 * ng + 1], qh, &kh[2]);
                mma16816(s[2 * ng + 1], qh, &kl[2]);
                mma16816(s[2 * ng + 1], ql, &kh[2]);
            }
        }

        // ---- causal mask (diagonal-region tiles only) ----
        if (j >= 2 * qi) {
            int r0 = q0 + w * 16 + (lane >> 2);
            int cb = j * 64 + (lane & 3) * 2;
#pragma unroll
            for (int nt = 0; nt < 8; nt++)
#pragma unroll
                for (int cc = 0; cc < 2; cc++) {
                    int col = cb + nt * 8 + cc;
                    if (col > r0)     s[nt][cc]     = -1e30f;
                    if (col > r0 + 8) s[nt][2 + cc] = -1e30f;
                }
        }

        // ---- online softmax (base-2; scale folded into Q) ----
        float mx0 = -1e30f, mx1 = -1e30f;
#pragma unroll
        for (int nt = 0; nt < 8; nt++) {
            mx0 = fmaxf(mx0, fmaxf(s[nt][0], s[nt][1]));
            mx1 = fmaxf(mx1, fmaxf(s[nt][2], s[nt][3]));
        }
        mx0 = fmaxf(mx0, __shfl_xor_sync(0xffffffffu, mx0, 1));
        mx0 = fmaxf(mx0, __shfl_xor_sync(0xffffffffu, mx0, 2));
        mx1 = fmaxf(mx1, __shfl_xor_sync(0xffffffffu, mx1, 1));
        mx1 = fmaxf(mx1, __shfl_xor_sync(0xffffffffu, mx1, 2));
        float mn0 = fmaxf(m0, mx0), mn1 = fmaxf(m1, mx1);
        float a0 = ex2(m0 - mn0), a1 = ex2(m1 - mn1);
        float sm0 = 0.f, sm1 = 0.f;
#pragma unroll
        for (int nt = 0; nt < 8; nt++) {
            s[nt][0] = ex2(s[nt][0] - mn0); sm0 += s[nt][0];
            s[nt][1] = ex2(s[nt][1] - mn0); sm0 += s[nt][1];
            s[nt][2] = ex2(s[nt][2] - mn1); sm1 += s[nt][2];
            s[nt][3] = ex2(s[nt][3] - mn1); sm1 += s[nt][3];
        }
        sm0 += __shfl_xor_sync(0xffffffffu, sm0, 1);
        sm0 += __shfl_xor_sync(0xffffffffu, sm0, 2);
        sm1 += __shfl_xor_sync(0xffffffffu, sm1, 1);
        sm1 += __shfl_xor_sync(0xffffffffu, sm1, 2);
        l0 = l0 * a0 + sm0; l1 = l1 * a1 + sm1;
        m0 = mn0; m1 = mn1;
#pragma unroll
        for (int nt = 0; nt < 8; nt++) {
            O[nt][0] *= a0; O[nt][1] *= a0;
            O[nt][2] *= a1; O[nt][3] *= a1;
        }

        // ---- O += P @ V (P split hi/lo in registers, V split in smem) ----
#pragma unroll
        for (int ks = 0; ks < 4; ks++) {
            uint32_t ph[4], pl[4];
            {
                __nv_bfloat162 t;
                t = __floats2bfloat162_rn(s[2 * ks][0], s[2 * ks][1]);
                ph[0] = b2u(t);
                pl[0] = b2u(__floats2bfloat162_rn(s[2 * ks][0] - __low2float(t),
                                                  s[2 * ks][1] - __high2float(t)));
                t = __floats2bfloat162_rn(s[2 * ks][2], s[2 * ks][3]);
                ph[1] = b2u(t);
                pl[1] = b2u(__floats2bfloat162_rn(s[2 * ks][2] - __low2float(t),
                                                  s[2 * ks][3] - __high2float(t)));
                t = __floats2bfloat162_rn(s[2 * ks + 1][0], s[2 * ks + 1][1]);
                ph[2] = b2u(t);
                pl[2] = b2u(__floats2bfloat162_rn(s[2 * ks + 1][0] - __low2float(t),
                                                  s[2 * ks + 1][1] - __high2float(t)));
                t = __floats2bfloat162_rn(s[2 * ks + 1][2], s[2 * ks + 1][3]);
                ph[3] = b2u(t);
                pl[3] = b2u(__floats2bfloat162_rn(s[2 * ks + 1][2] - __low2float(t),
                                                  s[2 * ks + 1][3] - __high2float(t)));
            }
#pragma unroll
            for (int ng = 0; ng < 4; ng++) {
                uint32_t vh[4], vl[4];
                uint32_t vo = vb_base + ks * (16 * AT_STRIDE) + ng * 32;
                ldsm4t(vh, st + 2 * KV_ARR_B + vo);
                ldsm4t(vl, st + 3 * KV_ARR_B + vo);
                mma16816(O[2 * ng],     ph, &vh[0]);
                mma16816(O[2 * ng],     ph, &vl[0]);
                mma16816(O[2 * ng],     pl, &vh[0]);
                mma16816(O[2 * ng + 1], ph, &vh[2]);
                mma16816(O[2 * ng + 1], ph, &vl[2]);
                mma16816(O[2 * ng + 1], pl, &vh[2]);
            }
        }
        __syncthreads();
    }

    // ---- epilogue: normalize + bf16 hi/lo for the output projection ----
    float inv0 = 1.0f / l0, inv1 = 1.0f / l1;
    int r0 = q0 + w * 16 + (lane >> 2);
    size_t rb0 = ((size_t)b * SEQ + r0) * DM + h * 64;
    size_t rb1 = rb0 + (size_t)8 * DM;
#pragma unroll
    for (int nt = 0; nt < 8; nt++) {
        int c0 = nt * 8 + (lane & 3) * 2;
        float v0 = O[nt][0] * inv0, v1 = O[nt][1] * inv0;
        float v2 = O[nt][2] * inv1, v3 = O[nt][3] * inv1;
        __nv_bfloat162 h0 = __floats2bfloat162_rn(v0, v1);
        __nv_bfloat162 h1 = __floats2bfloat162_rn(v2, v3);
        *(__nv_bfloat162*)&g_Ahi[rb0 + c0] = h0;
        *(__nv_bfloat162*)&g_Ahi[rb1 + c0] = h1;
        *(__nv_bfloat162*)&g_Alo[rb0 + c0] =
            __floats2bfloat162_rn(v0 - __low2float(h0), v1 - __high2float(h0));
        *(__nv_bfloat162*)&g_Alo[rb1 + c0] =
            __floats2bfloat162_rn(v2 - __low2float(h1), v3 - __high2float(h1));
    }
}

// ---------------------------------------------------------------------------
extern "C" void kernel_launch(void* const* d_in, const int* in_sizes, int n_in,
                              void* d_out, int out_size)
{
    const float* x  = (const float*)d_in[0];
    const float* Wq = (const float*)d_in[1];
    const float* Wk = (const float*)d_in[2];
    const float* Wv = (const float*)d_in[3];
    const float* Wo = (const float*)d_in[4];
    float* out = (float*)d_out;

    cudaFuncSetAttribute(gemm_mma<0>, cudaFuncAttributeMaxDynamicSharedMemorySize, GEMM_SMEM);
    cudaFuncSetAttribute(gemm_mma<1>, cudaFuncAttributeMaxDynamicSharedMemorySize, GEMM_SMEM);
    cudaFuncSetAttribute(attn_mma,    cudaFuncAttributeMaxDynamicSharedMemorySize, ATT_SMEM);

    split_x_kernel<<<8192, 256>>>(x);
    tsplit_kernel<<<dim3(2, 32, 16), dim3(32, 8)>>>(Wq, 0, 1024, 64);
    tsplit_kernel<<<dim3(2, 32, 16), dim3(32, 8)>>>(Wk, 1, 1024, 64);
    tsplit_kernel<<<dim3(2, 32, 16), dim3(32, 8)>>>(Wv, 2, 1024, 64);
    tsplit_kernel<<<dim3(32, 32, 1), dim3(32, 8)>>>(Wo, 3, 1024, 1024);

    gemm_mma<0><<<dim3(64, 8, 3), 256, GEMM_SMEM>>>(nullptr);
    attn_mma<<<dim3(SEQ / 128, BATCH * NH), 256, ATT_SMEM>>>();
    gemm_mma<1><<<dim3(64, 8, 1), 256, GEMM_SMEM>>>(out);
}

// round 8
// speedup vs baseline: 2.7350x; 1.0240x over previous
#include <cuda_runtime.h>
#include <cuda_bf16.h>
#include <math.h>
#include <stdint.h>
#include <string.h>

#define BATCH 4
#define SEQ   2048
#define DIN   1024
#define NH    16
#define DKH   64
#define DM    1024
#define QKV_ELE ((size_t)BATCH*NH*SEQ*DKH)   // 8388608
#define QSCALE 0.18033688011112042f          // 0.125 * log2(e): softmax in base 2

// ---------------- scratch globals (no allocation allowed) -------------------
__device__ __align__(128) __nv_bfloat16 g_xhi[(size_t)BATCH*SEQ*DIN];
__device__ __align__(128) __nv_bfloat16 g_xlo[(size_t)BATCH*SEQ*DIN];
__device__ __align__(128) __nv_bfloat16 g_wt_h[(size_t)4<<20];  // Wq,Wk,Wv,Wo transposed [n][k]
__device__ __align__(128) __nv_bfloat16 g_wt_l[(size_t)4<<20];
__device__ __align__(128) __nv_bfloat16 g_qkvh[3*QKV_ELE];      // Q,K,V per-head bf16 hi
__device__ __align__(128) __nv_bfloat16 g_qkvl[3*QKV_ELE];      // lo
__device__ __align__(128) __nv_bfloat16 g_Ahi[(size_t)BATCH*SEQ*DM];
__device__ __align__(128) __nv_bfloat16 g_Alo[(size_t)BATCH*SEQ*DM];

// ---------------- PTX helpers (sm_100 baseline: ldmatrix / mma.sync) --------
__device__ __forceinline__ uint32_t smem_u32(const void* p) {
    uint32_t a;
    asm("{ .reg .u64 t; cvta.to.shared.u64 t, %1; cvt.u32.u64 %0, t; }" : "=r"(a) : "l"(p));
    return a;
}
__device__ __forceinline__ void ldsm4(uint32_t* f, uint32_t addr) {
    asm volatile("ldmatrix.sync.aligned.m8n8.x4.shared.b16 {%0,%1,%2,%3}, [%4];"
                 : "=r"(f[0]), "=r"(f[1]), "=r"(f[2]), "=r"(f[3]) : "r"(addr));
}
__device__ __forceinline__ void ldsm4t(uint32_t* f, uint32_t addr) {
    asm volatile("ldmatrix.sync.aligned.m8n8.x4.trans.shared.b16 {%0,%1,%2,%3}, [%4];"
                 : "=r"(f[0]), "=r"(f[1]), "=r"(f[2]), "=r"(f[3]) : "r"(addr));
}
__device__ __forceinline__ void mma16816(float* c, const uint32_t* a, const uint32_t* b) {
    asm volatile(
        "mma.sync.aligned.m16n8k16.row.col.f32.bf16.bf16.f32 "
        "{%0,%1,%2,%3}, {%4,%5,%6,%7}, {%8,%9}, {%0,%1,%2,%3};"
        : "+f"(c[0]), "+f"(c[1]), "+f"(c[2]), "+f"(c[3])
        : "r"(a[0]), "r"(a[1]), "r"(a[2]), "r"(a[3]), "r"(b[0]), "r"(b[1]));
}
__device__ __forceinline__ void cp16(uint32_t dst, const void* src) {
    asm volatile("cp.async.cg.shared.global [%0], [%1], 16;" :: "r"(dst), "l"(src));
}
__device__ __forceinline__ float ex2(float x) {
    float y; asm("ex2.approx.ftz.f32 %0, %1;" : "=f"(y) : "f"(x)); return y;
}
__device__ __forceinline__ uint32_t b2u(__nv_bfloat162 v) {
    uint32_t u; memcpy(&u, &v, 4); return u;
}

// ---------------- prep: fp32 -> bf16 hi/lo splits ---------------------------
__global__ void split_x_kernel(const float* __restrict__ x) {
    size_t i0 = ((size_t)blockIdx.x * 256 + threadIdx.x) * 4;
    float4 v = *(const float4*)(x + i0);
    float vv[4] = {v.x, v.y, v.z, v.w};
    __nv_bfloat16 h[4], l[4];
#pragma unroll
    for (int j = 0; j < 4; j++) {
        h[j] = __float2bfloat16(vv[j]);
        l[j] = __float2bfloat16(vv[j] - __bfloat162float(h[j]));
    }
    *(uint2*)(g_xhi + i0) = *(uint2*)h;
    *(uint2*)(g_xlo + i0) = *(uint2*)l;
}

__global__ void tsplit_kernel(const float* __restrict__ in, int which, int R, int C) {
    __shared__ float t[32][33];
    const int z = blockIdx.z;
    const int c0 = blockIdx.x * 32, r0 = blockIdx.y * 32;
    const int tx = threadIdx.x, ty = threadIdx.y;
    const float* inp = in + (size_t)z * R * C;
#pragma unroll
    for (int k = 0; k < 4; k++)
        t[ty + 8 * k][tx] = inp[(size_t)(r0 + ty + 8 * k) * C + c0 + tx];
    __syncthreads();
    __nv_bfloat16* oh = g_wt_h + ((size_t)which << 20) + (size_t)z * R * C;
    __nv_bfloat16* ol = g_wt_l + ((size_t)which << 20) + (size_t)z * R * C;
#pragma unroll
    for (int k = 0; k < 4; k++) {
        float v = t[tx][ty + 8 * k];
        __nv_bfloat16 hb = __float2bfloat16(v);
        size_t o = (size_t)(c0 + ty + 8 * k) * R + r0 + tx;
        oh[o] = hb;
        ol[o] = __float2bfloat16(v - __bfloat162float(hb));
    }
}

// ---------------- HMMA GEMM: C = A @ B^T, bf16x3, fp32 accum ----------------
// Block 128(M) x 256(N), 8 warps (2M x 4N), warp tile 64x64, k-chunk 32,
// 3-stage cp.async ring. Row stride 80 B (validated conflict-free).
// MODE 0: A = x split, B = Wq/Wk/Wv^T (z), out bf16 hi/lo per-head (Q pre-scaled).
// MODE 1: A = attn out split, B = Wo^T, out row-major fp32 (d_out).
#define KC 32
#define A_TILE_B 10240               // 128 rows * 80 B
#define B_TILE_B 20480               // 256 rows * 80 B
#define STG_BYTES (2 * A_TILE_B + 2 * B_TILE_B)   // 61440
#define GEMM_SMEM (3 * STG_BYTES)                 // 184320

__device__ __forceinline__ void copy_chunk(int tid, uint32_t stg, int kc, int m0, int n0,
    const __nv_bfloat16* Ah, const __nv_bfloat16* Al,
    const __nv_bfloat16* Bh, const __nv_bfloat16* Bl)
{
    const int ko = kc * 32;
#pragma unroll
    for (int i = 0; i < 12; i++) {
        int t = tid + i * 256;
        const __nv_bfloat16* src; uint32_t dst;
        if (t < 1024) {        // A: 2 halves x (128 rows x 4 x 16B)
            int half = t >> 9, idx = t & 511, r = idx >> 2, c = idx & 3;
            src = (half ? Al : Ah) + (size_t)(m0 + r) * 1024 + ko + c * 8;
            dst = stg + half * A_TILE_B + r * 80 + c * 16;
        } else {               // B: 2 halves x (256 rows x 4 x 16B)
            int u = t - 1024;
            int half = u >> 10, idx = u & 1023, r = idx >> 2, c = idx & 3;
            src = (half ? Bl : Bh) + (size_t)(n0 + r) * 1024 + ko + c * 8;
            dst = stg + 2 * A_TILE_B + half * B_TILE_B + r * 80 + c * 16;
        }
        cp16(dst, src);
    }
    asm volatile("cp.async.commit_group;" ::: "memory");
}

template<int MODE>
__global__ __launch_bounds__(256, 1) void gemm_mma(float* __restrict__ outp_)
{
    extern __shared__ __align__(128) char dsm[];
    const uint32_t sb = smem_u32(dsm);
    const int tid = threadIdx.x, wid = tid >> 5, lane = tid & 31;
    const int warp_m = wid >> 2, warp_n = wid & 3;
    const int m0 = blockIdx.x * 128, n0 = blockIdx.y * 256, z = blockIdx.z;

    const __nv_bfloat16* Bh = g_wt_h + ((size_t)(MODE ? 3 : z) << 20);
    const __nv_bfloat16* Bl = g_wt_l + ((size_t)(MODE ? 3 : z) << 20);
    const __nv_bfloat16* Ah = (MODE == 0) ? g_xhi : g_Ahi;
    const __nv_bfloat16* Al = (MODE == 0) ? g_xlo : g_Alo;

    const uint32_t a_off = (uint32_t)(warp_m * 64 + (lane & 15)) * 80 + (lane >> 4) * 16;
    const uint32_t b_off = (uint32_t)(warp_n * 64 + (lane >> 4) * 8 + (lane & 7)) * 80
                         + ((lane >> 3) & 1) * 16;

    float acc[4][8][4];
#pragma unroll
    for (int i = 0; i < 4; i++)
#pragma unroll
        for (int j = 0; j < 8; j++)
#pragma unroll
            for (int k = 0; k < 4; k++) acc[i][j][k] = 0.f;

    copy_chunk(tid, sb, 0, m0, n0, Ah, Al, Bh, Bl);
    copy_chunk(tid, sb + STG_BYTES, 1, m0, n0, Ah, Al, Bh, Bl);

    for (int kc = 0; kc < KC; kc++) {
        if (kc + 1 < KC) {
            asm volatile("cp.async.wait_group 1;" ::: "memory");
        } else {
            asm volatile("cp.async.wait_group 0;" ::: "memory");
        }
        __syncthreads();
        if (kc + 2 < KC)
            copy_chunk(tid, sb + (uint32_t)((kc + 2) % 3) * STG_BYTES, kc + 2,
                       m0, n0, Ah, Al, Bh, Bl);

        const uint32_t stg = sb + (uint32_t)(kc % 3) * STG_BYTES;
        const uint32_t sB = stg + 2 * A_TILE_B;
#pragma unroll
        for (int ks = 0; ks < 2; ks++) {
            uint32_t ah[4][4], al[4][4], bh[4][4], bl[4][4];
#pragma unroll
            for (int mt = 0; mt < 4; mt++) {
                ldsm4(ah[mt], stg + 0 * A_TILE_B + a_off + mt * (16 * 80) + ks * 32);
                ldsm4(al[mt], stg + 1 * A_TILE_B + a_off + mt * (16 * 80) + ks * 32);
            }
#pragma unroll
            for (int pr = 0; pr < 4; pr++) {
                ldsm4(bh[pr], sB + 0 * B_TILE_B + b_off + pr * (16 * 80) + ks * 32);
                ldsm4(bl[pr], sB + 1 * B_TILE_B + b_off + pr * (16 * 80) + ks * 32);
            }
#pragma unroll
            for (int mt = 0; mt < 4; mt++)
#pragma unroll
                for (int nt = 0; nt < 8; nt++) {
                    float* c = acc[mt][nt];
                    const uint32_t* ph = &bh[nt >> 1][(nt & 1) * 2];
                    const uint32_t* pl = &bl[nt >> 1][(nt & 1) * 2];
                    mma16816(c, ah[mt], ph);
                    mma16816(c, ah[mt], pl);
                    mma16816(c, al[mt], ph);
                }
        }
        __syncthreads();
    }

    const int tg = lane >> 2, tq = lane & 3;
#pragma unroll
    for (int mt = 0; mt < 4; mt++) {
#pragma unroll
        for (int nt = 0; nt < 8; nt++) {
            int row = m0 + warp_m * 64 + mt * 16 + tg;
            int col = n0 + warp_n * 64 + nt * 8 + tq * 2;
            if (MODE == 0) {
                const float scale = (z == 0) ? QSCALE : 1.0f;
                int bb = row >> 11, ss = row & 2047, hh = col >> 6, dk = col & 63;
                size_t base = (size_t)z * QKV_ELE
                            + (((size_t)(bb * NH + hh)) * SEQ + ss) * DKH + dk;
                float v0 = acc[mt][nt][0] * scale, v1 = acc[mt][nt][1] * scale;
                float v2 = acc[mt][nt][2] * scale, v3 = acc[mt][nt][3] * scale;
                __nv_bfloat162 h0 = __floats2bfloat162_rn(v0, v1);
                __nv_bfloat162 h1 = __floats2bfloat162_rn(v2, v3);
                __nv_bfloat162 l0 = __floats2bfloat162_rn(v0 - __low2float(h0),
                                                          v1 - __high2float(h0));
                __nv_bfloat162 l1 = __floats2bfloat162_rn(v2 - __low2float(h1),
                                                          v3 - __high2float(h1));
                *(__nv_bfloat162*)&g_qkvh[base]           = h0;
                *(__nv_bfloat162*)&g_qkvh[base + 8 * DKH] = h1;
                *(__nv_bfloat162*)&g_qkvl[base]           = l0;
                *(__nv_bfloat162*)&g_qkvl[base + 8 * DKH] = l1;
            } else {
                float* dst0 = outp_ + (size_t)row * DM + col;
                float* dst1 = outp_ + (size_t)(row + 8) * DM + col;
                *(float2*)dst0 = make_float2(acc[mt][nt][0], acc[mt][nt][1]);
                *(float2*)dst1 = make_float2(acc[mt][nt][2], acc[mt][nt][3]);
            }
        }
    }
}

// ---------------- causal flash attention on HMMA (validated R7) -------------
// BM=128 (8 warps x 16 rows), BN=64, d=64. bf16x3 for QK^T and PV.
#define AT_STRIDE 144
#define Q_TILE_B   (128 * AT_STRIDE)        // 18432
#define KV_ARR_B   (64 * AT_STRIDE)         // 9216
#define KV_STAGE_B (4 * KV_ARR_B)           // 36864
#define ATT_SMEM   (2 * Q_TILE_B + 2 * KV_STAGE_B)   // 110592

__device__ __forceinline__ void load_kv(int tid, uint32_t stg, int j,
    const __nv_bfloat16* Khg, const __nv_bfloat16* Klg,
    const __nv_bfloat16* Vhg, const __nv_bfloat16* Vlg)
{
#pragma unroll
    for (int it = 0; it < 8; it++) {
        int i = tid + it * 256;
        int arr = i >> 9, r = (i >> 3) & 63, c = i & 7;
        const __nv_bfloat16* src = (arr == 0 ? Khg : arr == 1 ? Klg
                                  : arr == 2 ? Vhg : Vlg) + ((size_t)(j * 64 + r)) * DKH + c * 8;
        cp16(stg + arr * KV_ARR_B + r * AT_STRIDE + c * 16, src);
    }
    asm volatile("cp.async.commit_group;" ::: "memory");
}

__global__ __launch_bounds__(256, 1) void attn_mma()
{
    extern __shared__ __align__(128) char dsm[];
    const uint32_t sb = smem_u32(dsm);
    const uint32_t sQh = sb, sQl = sb + Q_TILE_B;
    const uint32_t sKV = sb + 2 * Q_TILE_B;

    const int qi = (int)gridDim.x - 1 - (int)blockIdx.x;   // heavy tiles first
    const int q0 = qi * 128;
    const int bh = blockIdx.y;
    const int b = bh >> 4, h = bh & 15;
    const int tid = threadIdx.x, w = tid >> 5, lane = tid & 31;

    const __nv_bfloat16* Qhg = g_qkvh + ((size_t)bh * SEQ + q0) * DKH;
    const __nv_bfloat16* Qlg = g_qkvl + ((size_t)bh * SEQ + q0) * DKH;
    const __nv_bfloat16* Khg = g_qkvh + QKV_ELE     + (size_t)bh * SEQ * DKH;
    const __nv_bfloat16* Klg = g_qkvl + QKV_ELE     + (size_t)bh * SEQ * DKH;
    const __nv_bfloat16* Vhg = g_qkvh + 2 * QKV_ELE + (size_t)bh * SEQ * DKH;
    const __nv_bfloat16* Vlg = g_qkvl + 2 * QKV_ELE + (size_t)bh * SEQ * DKH;

    // Q (hi+lo) -> smem, group 0
#pragma unroll
    for (int it = 0; it < 8; it++) {
        int i = tid + it * 256;
        int half = i >> 10, r = (i >> 3) & 127, c = i & 7;
        const __nv_bfloat16* src = (half ? Qlg : Qhg) + (size_t)r * DKH + c * 8;
        cp16((half ? sQl : sQh) + r * AT_STRIDE + c * 16, src);
    }
    asm volatile("cp.async.commit_group;" ::: "memory");

    load_kv(tid, sKV, 0, Khg, Klg, Vhg, Vlg);

    float O[8][4];
#pragma unroll
    for (int i = 0; i < 8; i++)
#pragma unroll
        for (int j = 0; j < 4; j++) O[i][j] = 0.f;
    float m0 = -1e30f, m1 = -1e30f, l0 = 0.f, l1 = 0.f;

    const uint32_t qa_base = (uint32_t)(w * 16 + (lane & 15)) * AT_STRIDE + (lane >> 4) * 16;
    const uint32_t kb_base = (uint32_t)((lane & 7) + ((lane >> 4) & 1) * 8) * AT_STRIDE
                           + ((lane >> 3) & 1) * 16;
    const uint32_t vb_base = (uint32_t)(lane & 15) * AT_STRIDE + (lane >> 4) * 16;

    const int njt = 2 * qi + 2;
    for (int j = 0; j < njt; j++) {
        const uint32_t st = sKV + (uint32_t)(j & 1) * KV_STAGE_B;
        if (j + 1 < njt) {
            load_kv(tid, sKV + (uint32_t)((j + 1) & 1) * KV_STAGE_B, j + 1,
                    Khg, Klg, Vhg, Vlg);
            asm volatile("cp.async.wait_group 1;" ::: "memory");
        } else {
            asm volatile("cp.async.wait_group 0;" ::: "memory");
        }
        __syncthreads();

        // ---- S = Qs @ K^T (fp32 via bf16x3) ----
        float s[8][4];
#pragma unroll
        for (int i = 0; i < 8; i++)
#pragma unroll
            for (int jj = 0; jj < 4; jj++) s[i][jj] = 0.f;

#pragma unroll
        for (int ks = 0; ks < 4; ks++) {
            uint32_t qh[4], ql[4];
            ldsm4(qh, sQh + qa_base + ks * 32);
            ldsm4(ql, sQl + qa_base + ks * 32);
#pragma unroll
            for (int ng = 0; ng < 4; ng++) {
                uint32_t kh[4], kl[4];
                uint32_t ko = kb_base + ng * (16 * AT_STRIDE) + ks * 32;
                ldsm4(kh, st + 0 * KV_ARR_B + ko);
                ldsm4(kl, st + 1 * KV_ARR_B + ko);
                mma16816(s[2 * ng],     qh, &kh[0]);
                mma16816(s[2 * ng],     qh, &kl[0]);
                mma16816(s[2 * ng],     ql, &kh[0]);
                mma16816(s[2 * ng + 1], qh, &kh[2]);
                mma16816(s[2 * ng + 1], qh, &kl[2]);
                mma16816(s[2 * ng + 1], ql, &kh[2]);
            }
        }

        // ---- causal mask (diagonal-region tiles only) ----
        if (j >= 2 * qi) {
            int r0 = q0 + w * 16 + (lane >> 2);
            int cb = j * 64 + (lane & 3) * 2;
#pragma unroll
            for (int nt = 0; nt < 8; nt++)
#pragma unroll
                for (int cc = 0; cc < 2; cc++) {
                    int col = cb + nt * 8 + cc;
                    if (col > r0)     s[nt][cc]     = -1e30f;
                    if (col > r0 + 8) s[nt][2 + cc] = -1e30f;
                }
        }

        // ---- online softmax (base-2; scale folded into Q) ----
        float mx0 = -1e30f, mx1 = -1e30f;
#pragma unroll
        for (int nt = 0; nt < 8; nt++) {
            mx0 = fmaxf(mx0, fmaxf(s[nt][0], s[nt][1]));
            mx1 = fmaxf(mx1, fmaxf(s[nt][2], s[nt][3]));
        }
        mx0 = fmaxf(mx0, __shfl_xor_sync(0xffffffffu, mx0, 1));
        mx0 = fmaxf(mx0, __shfl_xor_sync(0xffffffffu, mx0, 2));
        mx1 = fmaxf(mx1, __shfl_xor_sync(0xffffffffu, mx1, 1));
        mx1 = fmaxf(mx1, __shfl_xor_sync(0xffffffffu, mx1, 2));
        float mn0 = fmaxf(m0, mx0), mn1 = fmaxf(m1, mx1);
        float a0 = ex2(m0 - mn0), a1 = ex2(m1 - mn1);
        float sm0 = 0.f, sm1 = 0.f;
#pragma unroll
        for (int nt = 0; nt < 8; nt++) {
            s[nt][0] = ex2(s[nt][0] - mn0); sm0 += s[nt][0];
            s[nt][1] = ex2(s[nt][1] - mn0); sm0 += s[nt][1];
            s[nt][2] = ex2(s[nt][2] - mn1); sm1 += s[nt][2];
            s[nt][3] = ex2(s[nt][3] - mn1); sm1 += s[nt][3];
        }
        sm0 += __shfl_xor_sync(0xffffffffu, sm0, 1);
        sm0 += __shfl_xor_sync(0xffffffffu, sm0, 2);
        sm1 += __shfl_xor_sync(0xffffffffu, sm1, 1);
        sm1 += __shfl_xor_sync(0xffffffffu, sm1, 2);
        l0 = l0 * a0 + sm0; l1 = l1 * a1 + sm1;
        m0 = mn0; m1 = mn1;
#pragma unroll
        for (int nt = 0; nt < 8; nt++) {
            O[nt][0] *= a0; O[nt][1] *= a0;
            O[nt][2] *= a1; O[nt][3] *= a1;
        }

        // ---- O += P @ V (P split hi/lo in registers, V split in smem) ----
#pragma unroll
        for (int ks = 0; ks < 4; ks++) {
            uint32_t ph[4], pl[4];
            {
                __nv_bfloat162 t;
                t = __floats2bfloat162_rn(s[2 * ks][0], s[2 * ks][1]);
                ph[0] = b2u(t);
                pl[0] = b2u(__floats2bfloat162_rn(s[2 * ks][0] - __low2float(t),
                                                  s[2 * ks][1] - __high2float(t)));
                t = __floats2bfloat162_rn(s[2 * ks][2], s[2 * ks][3]);
                ph[1] = b2u(t);
                pl[1] = b2u(__floats2bfloat162_rn(s[2 * ks][2] - __low2float(t),
                                                  s[2 * ks][3] - __high2float(t)));
                t = __floats2bfloat162_rn(s[2 * ks + 1][0], s[2 * ks + 1][1]);
                ph[2] = b2u(t);
                pl[2] = b2u(__floats2bfloat162_rn(s[2 * ks + 1][0] - __low2float(t),
                                                  s[2 * ks + 1][1] - __high2float(t)));
                t = __floats2bfloat162_rn(s[2 * ks + 1][2], s[2 * ks + 1][3]);
                ph[3] = b2u(t);
                pl[3] = b2u(__floats2bfloat162_rn(s[2 * ks + 1][2] - __low2float(t),
                                                  s[2 * ks + 1][3] - __high2float(t)));
            }
#pragma unroll
            for (int ng = 0; ng < 4; ng++) {
                uint32_t vh[4], vl[4];
                uint32_t vo = vb_base + ks * (16 * AT_STRIDE) + ng * 32;
                ldsm4t(vh, st + 2 * KV_ARR_B + vo);
                ldsm4t(vl, st + 3 * KV_ARR_B + vo);
                mma16816(O[2 * ng],     ph, &vh[0]);
                mma16816(O[2 * ng],     ph, &vl[0]);
                mma16816(O[2 * ng],     pl, &vh[0]);
                mma16816(O[2 * ng + 1], ph, &vh[2]);
                mma16816(O[2 * ng + 1], ph, &vl[2]);
                mma16816(O[2 * ng + 1], pl, &vh[2]);
            }
        }
        __syncthreads();
    }

    // ---- epilogue: normalize + bf16 hi/lo for the output projection ----
    float inv0 = 1.0f / l0, inv1 = 1.0f / l1;
    int r0 = q0 + w * 16 + (lane >> 2);
    size_t rb0 = ((size_t)b * SEQ + r0) * DM + h * 64;
    size_t rb1 = rb0 + (size_t)8 * DM;
#pragma unroll
    for (int nt = 0; nt < 8; nt++) {
        int c0 = nt * 8 + (lane & 3) * 2;
        float v0 = O[nt][0] * inv0, v1 = O[nt][1] * inv0;
        float v2 = O[nt][2] * inv1, v3 = O[nt][3] * inv1;
        __nv_bfloat162 h0 = __floats2bfloat162_rn(v0, v1);
        __nv_bfloat162 h1 = __floats2bfloat162_rn(v2, v3);
        *(__nv_bfloat162*)&g_Ahi[rb0 + c0] = h0;
        *(__nv_bfloat162*)&g_Ahi[rb1 + c0] = h1;
        *(__nv_bfloat162*)&g_Alo[rb0 + c0] =
            __floats2bfloat162_rn(v0 - __low2float(h0), v1 - __high2float(h0));
        *(__nv_bfloat162*)&g_Alo[rb1 + c0] =
            __floats2bfloat162_rn(v2 - __low2float(h1), v3 - __high2float(h1));
    }
}

// ---------------------------------------------------------------------------
extern "C" void kernel_launch(void* const* d_in, const int* in_sizes, int n_in,
                              void* d_out, int out_size)
{
    const float* x  = (const float*)d_in[0];
    const float* Wq = (const float*)d_in[1];
    const float* Wk = (const float*)d_in[2];
    const float* Wv = (const float*)d_in[3];
    const float* Wo = (const float*)d_in[4];
    float* out = (float*)d_out;

    cudaFuncSetAttribute(gemm_mma<0>, cudaFuncAttributeMaxDynamicSharedMemorySize, GEMM_SMEM);
    cudaFuncSetAttribute(gemm_mma<1>, cudaFuncAttributeMaxDynamicSharedMemorySize, GEMM_SMEM);
    cudaFuncSetAttribute(attn_mma,    cudaFuncAttributeMaxDynamicSharedMemorySize, ATT_SMEM);

    split_x_kernel<<<8192, 256>>>(x);
    tsplit_kernel<<<dim3(2, 32, 16), dim3(32, 8)>>>(Wq, 0, 1024, 64);
    tsplit_kernel<<<dim3(2, 32, 16), dim3(32, 8)>>>(Wk, 1, 1024, 64);
    tsplit_kernel<<<dim3(2, 32, 16), dim3(32, 8)>>>(Wv, 2, 1024, 64);
    tsplit_kernel<<<dim3(32, 32, 1), dim3(32, 8)>>>(Wo, 3, 1024, 1024);

    gemm_mma<0><<<dim3(64, 4, 3), 256, GEMM_SMEM>>>(nullptr);
    attn_mma<<<dim3(SEQ / 128, BATCH * NH), 256, ATT_SMEM>>>();
    gemm_mma<1><<<dim3(64, 4, 1), 256, GEMM_SMEM>>>(out);
}

// round 9
// speedup vs baseline: 3.3539x; 1.2263x over previous
#include <cuda_runtime.h>
#include <cuda_bf16.h>
#include <cuda_fp16.h>
#include <math.h>
#include <stdint.h>
#include <string.h>

#define BATCH 4
#define SEQ   2048
#define DIN   1024
#define NH    16
#define DKH   64
#define DM    1024
#define QKV_ELE ((size_t)BATCH*NH*SEQ*DKH)   // 8388608
#define QSCALE 0.18033688011112042f          // 0.125 * log2(e): softmax in base 2

// ---------------- scratch globals (no allocation allowed) -------------------
__device__ __align__(128) __half g_xfh[(size_t)BATCH*SEQ*DIN];   // x fp16 hi
__device__ __align__(128) __half g_xfl[(size_t)BATCH*SEQ*DIN];   // x fp16 lo
__device__ __align__(128) __half g_wf[(size_t)4<<20];            // Wq,Wk,Wv,Wo^T fp16
__device__ __align__(128) __nv_bfloat16 g_qkvh[3*QKV_ELE];       // Q,K,V bf16 hi
__device__ __align__(128) __nv_bfloat16 g_qkvl[3*QKV_ELE];       // lo
__device__ __align__(128) __half g_Afh[(size_t)BATCH*SEQ*DM];    // attn out fp16 hi
__device__ __align__(128) __half g_Afl[(size_t)BATCH*SEQ*DM];    // lo

// ---------------- PTX helpers (sm_100 baseline: ldmatrix / mma.sync) --------
__device__ __forceinline__ uint32_t smem_u32(const void* p) {
    uint32_t a;
    asm("{ .reg .u64 t; cvta.to.shared.u64 t, %1; cvt.u32.u64 %0, t; }" : "=r"(a) : "l"(p));
    return a;
}
__device__ __forceinline__ void ldsm4(uint32_t* f, uint32_t addr) {
    asm volatile("ldmatrix.sync.aligned.m8n8.x4.shared.b16 {%0,%1,%2,%3}, [%4];"
                 : "=r"(f[0]), "=r"(f[1]), "=r"(f[2]), "=r"(f[3]) : "r"(addr));
}
__device__ __forceinline__ void ldsm4t(uint32_t* f, uint32_t addr) {
    asm volatile("ldmatrix.sync.aligned.m8n8.x4.trans.shared.b16 {%0,%1,%2,%3}, [%4];"
                 : "=r"(f[0]), "=r"(f[1]), "=r"(f[2]), "=r"(f[3]) : "r"(addr));
}
__device__ __forceinline__ void mma16816(float* c, const uint32_t* a, const uint32_t* b) {
    asm volatile(
        "mma.sync.aligned.m16n8k16.row.col.f32.bf16.bf16.f32 "
        "{%0,%1,%2,%3}, {%4,%5,%6,%7}, {%8,%9}, {%0,%1,%2,%3};"
        : "+f"(c[0]), "+f"(c[1]), "+f"(c[2]), "+f"(c[3])
        : "r"(a[0]), "r"(a[1]), "r"(a[2]), "r"(a[3]), "r"(b[0]), "r"(b[1]));
}
__device__ __forceinline__ void mma16816h(float* c, const uint32_t* a, const uint32_t* b) {
    asm volatile(
        "mma.sync.aligned.m16n8k16.row.col.f32.f16.f16.f32 "
        "{%0,%1,%2,%3}, {%4,%5,%6,%7}, {%8,%9}, {%0,%1,%2,%3};"
        : "+f"(c[0]), "+f"(c[1]), "+f"(c[2]), "+f"(c[3])
        : "r"(a[0]), "r"(a[1]), "r"(a[2]), "r"(a[3]), "r"(b[0]), "r"(b[1]));
}
__device__ __forceinline__ void cp16(uint32_t dst, const void* src) {
    asm volatile("cp.async.cg.shared.global [%0], [%1], 16;" :: "r"(dst), "l"(src));
}
__device__ __forceinline__ float ex2(float x) {
    float y; asm("ex2.approx.ftz.f32 %0, %1;" : "=f"(y) : "f"(x)); return y;
}
__device__ __forceinline__ uint32_t b2u(__nv_bfloat162 v) {
    uint32_t u; memcpy(&u, &v, 4); return u;
}

// ---------------- prep: fp32 -> fp16 hi/lo split for x ----------------------
__global__ void split_x_kernel(const float* __restrict__ x) {
    size_t i0 = ((size_t)blockIdx.x * 256 + threadIdx.x) * 4;
    float4 v = *(const float4*)(x + i0);
    float vv[4] = {v.x, v.y, v.z, v.w};
    __half h[4], l[4];
#pragma unroll
    for (int j = 0; j < 4; j++) {
        h[j] = __float2half_rn(vv[j]);
        l[j] = __float2half_rn(vv[j] - __half2float(h[j]));
    }
    *(uint2*)(g_xfh + i0) = *(uint2*)h;
    *(uint2*)(g_xfl + i0) = *(uint2*)l;
}

// transpose matrix z ([R][C] -> [C][R]) to fp16 single into g_wf[which]
__global__ void tsplit_kernel(const float* __restrict__ in, int which, int R, int C) {
    __shared__ float t[32][33];
    const int z = blockIdx.z;
    const int c0 = blockIdx.x * 32, r0 = blockIdx.y * 32;
    const int tx = threadIdx.x, ty = threadIdx.y;
    const float* inp = in + (size_t)z * R * C;
#pragma unroll
    for (int k = 0; k < 4; k++)
        t[ty + 8 * k][tx] = inp[(size_t)(r0 + ty + 8 * k) * C + c0 + tx];
    __syncthreads();
    __half* oh = g_wf + ((size_t)which << 20) + (size_t)z * R * C;
#pragma unroll
    for (int k = 0; k < 4; k++)
        oh[(size_t)(c0 + ty + 8 * k) * R + r0 + tx] = __float2half_rn(t[tx][ty + 8 * k]);
}

// ---------------- HMMA GEMM: C = A @ B^T, fp16x2 (A exact pair, B fp16) -----
// Block 128(M) x 256(N), 8 warps (2M x 4N), warp tile 64x64, k-chunk 32,
// 3-stage cp.async ring. Row stride 80 B (validated conflict-free).
// MODE 0: A = x fp16 pair, B = Wq/Wk/Wv^T (z), out bf16 hi/lo per-head.
// MODE 1: A = attn out fp16 pair, B = Wo^T, out row-major fp32 (d_out).
#define KC 32
#define A_TILE_B 10240               // 128 rows * 80 B
#define B_TILE_B 20480               // 256 rows * 80 B
#define STG_BYTES (2 * A_TILE_B + B_TILE_B)       // 40960
#define GEMM_SMEM (3 * STG_BYTES)                 // 122880

__device__ __forceinline__ void copy_chunk(int tid, uint32_t stg, int kc, int m0, int n0,
    const __half* Ah, const __half* Al, const __half* B)
{
    const int ko = kc * 32;
#pragma unroll
    for (int i = 0; i < 8; i++) {
        int t = tid + i * 256;
        const __half* src; uint32_t dst;
        if (t < 1024) {        // A: 2 halves x (128 rows x 4 x 16B)
            int half_ = t >> 9, idx = t & 511, r = idx >> 2, c = idx & 3;
            src = (half_ ? Al : Ah) + (size_t)(m0 + r) * 1024 + ko + c * 8;
            dst = stg + half_ * A_TILE_B + r * 80 + c * 16;
        } else {               // B: 256 rows x 4 x 16B
            int u = t - 1024;
            int r = u >> 2, c = u & 3;
            src = B + (size_t)(n0 + r) * 1024 + ko + c * 8;
            dst = stg + 2 * A_TILE_B + r * 80 + c * 16;
        }
        cp16(dst, src);
    }
    asm volatile("cp.async.commit_group;" ::: "memory");
}

template<int MODE>
__global__ __launch_bounds__(256, 1) void gemm_mma(float* __restrict__ outp_)
{
    extern __shared__ __align__(128) char dsm[];
    const uint32_t sb = smem_u32(dsm);
    const int tid = threadIdx.x, wid = tid >> 5, lane = tid & 31;
    const int warp_m = wid >> 2, warp_n = wid & 3;
    const int m0 = blockIdx.x * 128, n0 = blockIdx.y * 256, z = blockIdx.z;

    const __half* B  = g_wf + ((size_t)(MODE ? 3 : z) << 20);
    const __half* Ah = (MODE == 0) ? g_xfh : g_Afh;
    const __half* Al = (MODE == 0) ? g_xfl : g_Afl;

    const uint32_t a_off = (uint32_t)(warp_m * 64 + (lane & 15)) * 80 + (lane >> 4) * 16;
    const uint32_t b_off = (uint32_t)(warp_n * 64 + (lane >> 4) * 8 + (lane & 7)) * 80
                         + ((lane >> 3) & 1) * 16;

    float acc[4][8][4];
#pragma unroll
    for (int i = 0; i < 4; i++)
#pragma unroll
        for (int j = 0; j < 8; j++)
#pragma unroll
            for (int k = 0; k < 4; k++) acc[i][j][k] = 0.f;

    copy_chunk(tid, sb, 0, m0, n0, Ah, Al, B);
    copy_chunk(tid, sb + STG_BYTES, 1, m0, n0, Ah, Al, B);

    for (int kc = 0; kc < KC; kc++) {
        if (kc + 1 < KC) {
            asm volatile("cp.async.wait_group 1;" ::: "memory");
        } else {
            asm volatile("cp.async.wait_group 0;" ::: "memory");
        }
        __syncthreads();
        if (kc + 2 < KC)
            copy_chunk(tid, sb + (uint32_t)((kc + 2) % 3) * STG_BYTES, kc + 2,
                       m0, n0, Ah, Al, B);

        const uint32_t stg = sb + (uint32_t)(kc % 3) * STG_BYTES;
        const uint32_t sB = stg + 2 * A_TILE_B;
#pragma unroll
        for (int ks = 0; ks < 2; ks++) {
            uint32_t ah[4][4], al[4][4], bb[4][4];
#pragma unroll
            for (int mt = 0; mt < 4; mt++) {
                ldsm4(ah[mt], stg + 0 * A_TILE_B + a_off + mt * (16 * 80) + ks * 32);
                ldsm4(al[mt], stg + 1 * A_TILE_B + a_off + mt * (16 * 80) + ks * 32);
            }
#pragma unroll
            for (int pr = 0; pr < 4; pr++)
                ldsm4(bb[pr], sB + b_off + pr * (16 * 80) + ks * 32);
#pragma unroll
            for (int mt = 0; mt < 4; mt++)
#pragma unroll
                for (int nt = 0; nt < 8; nt++) {
                    float* c = acc[mt][nt];
                    const uint32_t* pb = &bb[nt >> 1][(nt & 1) * 2];
                    mma16816h(c, ah[mt], pb);   // A_hi * B
                    mma16816h(c, al[mt], pb);   // A_lo * B (exact A reconstruction)
                }
        }
        __syncthreads();
    }

    const int tg = lane >> 2, tq = lane & 3;
#pragma unroll
    for (int mt = 0; mt < 4; mt++) {
#pragma unroll
        for (int nt = 0; nt < 8; nt++) {
            int row = m0 + warp_m * 64 + mt * 16 + tg;
            int col = n0 + warp_n * 64 + nt * 8 + tq * 2;
            if (MODE == 0) {
                const float scale = (z == 0) ? QSCALE : 1.0f;
                int bb_ = row >> 11, ss = row & 2047, hh = col >> 6, dk = col & 63;
                size_t base = (size_t)z * QKV_ELE
                            + (((size_t)(bb_ * NH + hh)) * SEQ + ss) * DKH + dk;
                float v0 = acc[mt][nt][0] * scale, v1 = acc[mt][nt][1] * scale;
                float v2 = acc[mt][nt][2] * scale, v3 = acc[mt][nt][3] * scale;
                __nv_bfloat162 h0 = __floats2bfloat162_rn(v0, v1);
                __nv_bfloat162 h1 = __floats2bfloat162_rn(v2, v3);
                __nv_bfloat162 l0 = __floats2bfloat162_rn(v0 - __low2float(h0),
                                                          v1 - __high2float(h0));
                __nv_bfloat162 l1 = __floats2bfloat162_rn(v2 - __low2float(h1),
                                                          v3 - __high2float(h1));
                *(__nv_bfloat162*)&g_qkvh[base]           = h0;
                *(__nv_bfloat162*)&g_qkvh[base + 8 * DKH] = h1;
                *(__nv_bfloat162*)&g_qkvl[base]           = l0;
                *(__nv_bfloat162*)&g_qkvl[base + 8 * DKH] = l1;
            } else {
                float* dst0 = outp_ + (size_t)row * DM + col;
                float* dst1 = outp_ + (size_t)(row + 8) * DM + col;
                *(float2*)dst0 = make_float2(acc[mt][nt][0], acc[mt][nt][1]);
                *(float2*)dst1 = make_float2(acc[mt][nt][2], acc[mt][nt][3]);
            }
        }
    }
}

// ---------------- causal flash attention on HMMA (validated R7/R8) ----------
// BM=128 (8 warps x 16 rows), BN=64, d=64. bf16x3 for QK^T and PV.
#define AT_STRIDE 144
#define Q_TILE_B   (128 * AT_STRIDE)        // 18432
#define KV_ARR_B   (64 * AT_STRIDE)         // 9216
#define KV_STAGE_B (4 * KV_ARR_B)           // 36864
#define ATT_SMEM   (2 * Q_TILE_B + 2 * KV_STAGE_B)   // 110592

__device__ __forceinline__ void load_kv(int tid, uint32_t stg, int j,
    const __nv_bfloat16* Khg, const __nv_bfloat16* Klg,
    const __nv_bfloat16* Vhg, const __nv_bfloat16* Vlg)
{
#pragma unroll
    for (int it = 0; it < 8; it++) {
        int i = tid + it * 256;
        int arr = i >> 9, r = (i >> 3) & 63, c = i & 7;
        const __nv_bfloat16* src = (arr == 0 ? Khg : arr == 1 ? Klg
                                  : arr == 2 ? Vhg : Vlg) + ((size_t)(j * 64 + r)) * DKH + c * 8;
        cp16(stg + arr * KV_ARR_B + r * AT_STRIDE + c * 16, src);
    }
    asm volatile("cp.async.commit_group;" ::: "memory");
}

__global__ __launch_bounds__(256, 1) void attn_mma()
{
    extern __shared__ __align__(128) char dsm[];
    const uint32_t sb = smem_u32(dsm);
    const uint32_t sQh = sb, sQl = sb + Q_TILE_B;
    const uint32_t sKV = sb + 2 * Q_TILE_B;

    const int qi = (int)gridDim.x - 1 - (int)blockIdx.x;   // heavy tiles first
    const int q0 = qi * 128;
    const int bh = blockIdx.y;
    const int b = bh >> 4, h = bh & 15;
    const int tid = threadIdx.x, w = tid >> 5, lane = tid & 31;

    const __nv_bfloat16* Qhg = g_qkvh + ((size_t)bh * SEQ + q0) * DKH;
    const __nv_bfloat16* Qlg = g_qkvl + ((size_t)bh * SEQ + q0) * DKH;
    const __nv_bfloat16* Khg = g_qkvh + QKV_ELE     + (size_t)bh * SEQ * DKH;
    const __nv_bfloat16* Klg = g_qkvl + QKV_ELE     + (size_t)bh * SEQ * DKH;
    const __nv_bfloat16* Vhg = g_qkvh + 2 * QKV_ELE + (size_t)bh * SEQ * DKH;
    const __nv_bfloat16* Vlg = g_qkvl + 2 * QKV_ELE + (size_t)bh * SEQ * DKH;

    // Q (hi+lo) -> smem, group 0
#pragma unroll
    for (int it = 0; it < 8; it++) {
        int i = tid + it * 256;
        int half_ = i >> 10, r = (i >> 3) & 127, c = i & 7;
        const __nv_bfloat16* src = (half_ ? Qlg : Qhg) + (size_t)r * DKH + c * 8;
        cp16((half_ ? sQl : sQh) + r * AT_STRIDE + c * 16, src);
    }
    asm volatile("cp.async.commit_group;" ::: "memory");

    load_kv(tid, sKV, 0, Khg, Klg, Vhg, Vlg);

    float O[8][4];
#pragma unroll
    for (int i = 0; i < 8; i++)
#pragma unroll
        for (int j = 0; j < 4; j++) O[i][j] = 0.f;
    float m0 = -1e30f, m1 = -1e30f, l0 = 0.f, l1 = 0.f;

    const uint32_t qa_base = (uint32_t)(w * 16 + (lane & 15)) * AT_STRIDE + (lane >> 4) * 16;
    const uint32_t kb_base = (uint32_t)((lane & 7) + ((lane >> 4) & 1) * 8) * AT_STRIDE
                           + ((lane >> 3) & 1) * 16;
    const uint32_t vb_base = (uint32_t)(lane & 15) * AT_STRIDE + (lane >> 4) * 16;

    const int njt = 2 * qi + 2;
    for (int j = 0; j < njt; j++) {
        const uint32_t st = sKV + (uint32_t)(j & 1) * KV_STAGE_B;
        if (j + 1 < njt) {
            load_kv(tid, sKV + (uint32_t)((j + 1) & 1) * KV_STAGE_B, j + 1,
                    Khg, Klg, Vhg, Vlg);
            asm volatile("cp.async.wait_group 1;" ::: "memory");
        } else {
            asm volatile("cp.async.wait_group 0;" ::: "memory");
        }
        __syncthreads();

        // ---- S = Qs @ K^T (fp32 via bf16x3) ----
        float s[8][4];
#pragma unroll
        for (int i = 0; i < 8; i++)
#pragma unroll
            for (int jj = 0; jj < 4; jj++) s[i][jj] = 0.f;

#pragma unroll
        for (int ks = 0; ks < 4; ks++) {
            uint32_t qh[4], ql[4];
            ldsm4(qh, sQh + qa_base + ks * 32);
            ldsm4(ql, sQl + qa_base + ks * 32);
#pragma unroll
            for (int ng = 0; ng < 4; ng++) {
                uint32_t kh[4], kl[4];
                uint32_t ko = kb_base + ng * (16 * AT_STRIDE) + ks * 32;
                ldsm4(kh, st + 0 * KV_ARR_B + ko);
                ldsm4(kl, st + 1 * KV_ARR_B + ko);
                mma16816(s[2 * ng],     qh, &kh[0]);
                mma16816(s[2 * ng],     qh, &kl[0]);
                mma16816(s[2 * ng],     ql, &kh[0]);
                mma16816(s[2 * ng + 1], qh, &kh[2]);
                mma16816(s[2 * ng + 1], qh, &kl[2]);
                mma16816(s[2 * ng + 1], ql, &kh[2]);
            }
        }

        // ---- causal mask (diagonal-region tiles only) ----
        if (j >= 2 * qi) {
            int r0 = q0 + w * 16 + (lane >> 2);
            int cb = j * 64 + (lane & 3) * 2;
#pragma unroll
            for (int nt = 0; nt < 8; nt++)
#pragma unroll
                for (int cc = 0; cc < 2; cc++) {
                    int col = cb + nt * 8 + cc;
                    if (col > r0)     s[nt][cc]     = -1e30f;
                    if (col > r0 + 8) s[nt][2 + cc] = -1e30f;
                }
        }

        // ---- online softmax (base-2; scale folded into Q) ----
        float mx0 = -1e30f, mx1 = -1e30f;
#pragma unroll
        for (int nt = 0; nt < 8; nt++) {
            mx0 = fmaxf(mx0, fmaxf(s[nt][0], s[nt][1]));
            mx1 = fmaxf(mx1, fmaxf(s[nt][2], s[nt][3]));
        }
        mx0 = fmaxf(mx0, __shfl_xor_sync(0xffffffffu, mx0, 1));
        mx0 = fmaxf(mx0, __shfl_xor_sync(0xffffffffu, mx0, 2));
        mx1 = fmaxf(mx1, __shfl_xor_sync(0xffffffffu, mx1, 1));
        mx1 = fmaxf(mx1, __shfl_xor_sync(0xffffffffu, mx1, 2));
        float mn0 = fmaxf(m0, mx0), mn1 = fmaxf(m1, mx1);
        float a0 = ex2(m0 - mn0), a1 = ex2(m1 - mn1);
        float sm0 = 0.f, sm1 = 0.f;
#pragma unroll
        for (int nt = 0; nt < 8; nt++) {
            s[nt][0] = ex2(s[nt][0] - mn0); sm0 += s[nt][0];
            s[nt][1] = ex2(s[nt][1] - mn0); sm0 += s[nt][1];
            s[nt][2] = ex2(s[nt][2] - mn1); sm1 += s[nt][2];
            s[nt][3] = ex2(s[nt][3] - mn1); sm1 += s[nt][3];
        }
        sm0 += __shfl_xor_sync(0xffffffffu, sm0, 1);
        sm0 += __shfl_xor_sync(0xffffffffu, sm0, 2);
        sm1 += __shfl_xor_sync(0xffffffffu, sm1, 1);
        sm1 += __shfl_xor_sync(0xffffffffu, sm1, 2);
        l0 = l0 * a0 + sm0; l1 = l1 * a1 + sm1;
        m0 = mn0; m1 = mn1;
#pragma unroll
        for (int nt = 0; nt < 8; nt++) {
            O[nt][0] *= a0; O[nt][1] *= a0;
            O[nt][2] *= a1; O[nt][3] *= a1;
        }

        // ---- O += P @ V (P split hi/lo in registers, V split in smem) ----
#pragma unroll
        for (int ks = 0; ks < 4; ks++) {
            uint32_t ph[4], pl[4];
            {
                __nv_bfloat162 t;
                t = __floats2bfloat162_rn(s[2 * ks][0], s[2 * ks][1]);
                ph[0] = b2u(t);
                pl[0] = b2u(__floats2bfloat162_rn(s[2 * ks][0] - __low2float(t),
                                                  s[2 * ks][1] - __high2float(t)));
                t = __floats2bfloat162_rn(s[2 * ks][2], s[2 * ks][3]);
                ph[1] = b2u(t);
                pl[1] = b2u(__floats2bfloat162_rn(s[2 * ks][2] - __low2float(t),
                                                  s[2 * ks][3] - __high2float(t)));
                t = __floats2bfloat162_rn(s[2 * ks + 1][0], s[2 * ks + 1][1]);
                ph[2] = b2u(t);
                pl[2] = b2u(__floats2bfloat162_rn(s[2 * ks + 1][0] - __low2float(t),
                                                  s[2 * ks + 1][1] - __high2float(t)));
                t = __floats2bfloat162_rn(s[2 * ks + 1][2], s[2 * ks + 1][3]);
                ph[3] = b2u(t);
                pl[3] = b2u(__floats2bfloat162_rn(s[2 * ks + 1][2] - __low2float(t),
                                                  s[2 * ks + 1][3] - __high2float(t)));
            }
#pragma unroll
            for (int ng = 0; ng < 4; ng++) {
                uint32_t vh[4], vl[4];
                uint32_t vo = vb_base + ks * (16 * AT_STRIDE) + ng * 32;
                ldsm4t(vh, st + 2 * KV_ARR_B + vo);
                ldsm4t(vl, st + 3 * KV_ARR_B + vo);
                mma16816(O[2 * ng],     ph, &vh[0]);
                mma16816(O[2 * ng],     ph, &vl[0]);
                mma16816(O[2 * ng],     pl, &vh[0]);
                mma16816(O[2 * ng + 1], ph, &vh[2]);
                mma16816(O[2 * ng + 1], ph, &vl[2]);
                mma16816(O[2 * ng + 1], pl, &vh[2]);
            }
        }
        __syncthreads();
    }

    // ---- epilogue: normalize + fp16 hi/lo for the output projection ----
    float inv0 = 1.0f / l0, inv1 = 1.0f / l1;
    int r0 = q0 + w * 16 + (lane >> 2);
    size_t rb0 = ((size_t)b * SEQ + r0) * DM + h * 64;
    size_t rb1 = rb0 + (size_t)8 * DM;
#pragma unroll
    for (int nt = 0; nt < 8; nt++) {
        int c0 = nt * 8 + (lane & 3) * 2;
        float v0 = O[nt][0] * inv0, v1 = O[nt][1] * inv0;
        float v2 = O[nt][2] * inv1, v3 = O[nt][3] * inv1;
        __half2 h0 = __floats2half2_rn(v0, v1);
        __half2 h1 = __floats2half2_rn(v2, v3);
        *(__half2*)&g_Afh[rb0 + c0] = h0;
        *(__half2*)&g_Afh[rb1 + c0] = h1;
        *(__half2*)&g_Afl[rb0 + c0] =
            __floats2half2_rn(v0 - __low2float(h0), v1 - __high2float(h0));
        *(__half2*)&g_Afl[rb1 + c0] =
            __floats2half2_rn(v2 - __low2float(h1), v3 - __high2float(h1));
    }
}

// ---------------------------------------------------------------------------
extern "C" void kernel_launch(void* const* d_in, const int* in_sizes, int n_in,
                              void* d_out, int out_size)
{
    const float* x  = (const float*)d_in[0];
    const float* Wq = (const float*)d_in[1];
    const float* Wk = (const float*)d_in[2];
    const float* Wv = (const float*)d_in[3];
    const float* Wo = (const float*)d_in[4];
    float* out = (float*)d_out;

    cudaFuncSetAttribute(gemm_mma<0>, cudaFuncAttributeMaxDynamicSharedMemorySize, GEMM_SMEM);
    cudaFuncSetAttribute(gemm_mma<1>, cudaFuncAttributeMaxDynamicSharedMemorySize, GEMM_SMEM);
    cudaFuncSetAttribute(attn_mma,    cudaFuncAttributeMaxDynamicSharedMemorySize, ATT_SMEM);

    split_x_kernel<<<8192, 256>>>(x);
    tsplit_kernel<<<dim3(2, 32, 16), dim3(32, 8)>>>(Wq, 0, 1024, 64);
    tsplit_kernel<<<dim3(2, 32, 16), dim3(32, 8)>>>(Wk, 1, 1024, 64);
    tsplit_kernel<<<dim3(2, 32, 16), dim3(32, 8)>>>(Wv, 2, 1024, 64);
    tsplit_kernel<<<dim3(32, 32, 1), dim3(32, 8)>>>(Wo, 3, 1024, 1024);

    gemm_mma<0><<<dim3(64, 4, 3), 256, GEMM_SMEM>>>(nullptr);
    attn_mma<<<dim3(SEQ / 128, BATCH * NH), 256, ATT_SMEM>>>();
    gemm_mma<1><<<dim3(64, 4, 1), 256, GEMM_SMEM>>>(out);
}

// round 10
// speedup vs baseline: 3.6883x; 1.0997x over previous
#include <cuda_runtime.h>
#include <cuda_bf16.h>
#include <cuda_fp16.h>
#include <math.h>
#include <stdint.h>
#include <string.h>

#define BATCH 4
#define SEQ   2048
#define DIN   1024
#define NH    16
#define DKH   64
#define DM    1024
#define QKV_ELE ((size_t)BATCH*NH*SEQ*DKH)   // 8388608
#define QSCALE 0.18033688011112042f          // 0.125 * log2(e): softmax in base 2

// ---------------- scratch globals (no allocation allowed) -------------------
__device__ __align__(128) __half g_xfh[(size_t)BATCH*SEQ*DIN];   // x fp16 hi
__device__ __align__(128) __half g_xfl[(size_t)BATCH*SEQ*DIN];   // x fp16 lo
__device__ __align__(128) __half g_wf[(size_t)4<<20];            // Wq,Wk,Wv,Wo^T fp16
__device__ __align__(128) __half g_qkvh[3*QKV_ELE];              // Q,K hi + V single
__device__ __align__(128) __half g_qkvl[3*QKV_ELE];              // Q,K lo (V slot unused)
__device__ __align__(128) __half g_Afh[(size_t)BATCH*SEQ*DM];    // attn out fp16 hi
__device__ __align__(128) __half g_Afl[(size_t)BATCH*SEQ*DM];    // lo

// ---------------- PTX helpers (sm_100 baseline: ldmatrix / mma.sync) --------
__device__ __forceinline__ uint32_t smem_u32(const void* p) {
    uint32_t a;
    asm("{ .reg .u64 t; cvta.to.shared.u64 t, %1; cvt.u32.u64 %0, t; }" : "=r"(a) : "l"(p));
    return a;
}
__device__ __forceinline__ void ldsm4(uint32_t* f, uint32_t addr) {
    asm volatile("ldmatrix.sync.aligned.m8n8.x4.shared.b16 {%0,%1,%2,%3}, [%4];"
                 : "=r"(f[0]), "=r"(f[1]), "=r"(f[2]), "=r"(f[3]) : "r"(addr));
}
__device__ __forceinline__ void ldsm4t(uint32_t* f, uint32_t addr) {
    asm volatile("ldmatrix.sync.aligned.m8n8.x4.trans.shared.b16 {%0,%1,%2,%3}, [%4];"
                 : "=r"(f[0]), "=r"(f[1]), "=r"(f[2]), "=r"(f[3]) : "r"(addr));
}
__device__ __forceinline__ void mma16816h(float* c, const uint32_t* a, const uint32_t* b) {
    asm volatile(
        "mma.sync.aligned.m16n8k16.row.col.f32.f16.f16.f32 "
        "{%0,%1,%2,%3}, {%4,%5,%6,%7}, {%8,%9}, {%0,%1,%2,%3};"
        : "+f"(c[0]), "+f"(c[1]), "+f"(c[2]), "+f"(c[3])
        : "r"(a[0]), "r"(a[1]), "r"(a[2]), "r"(a[3]), "r"(b[0]), "r"(b[1]));
}
__device__ __forceinline__ void cp16(uint32_t dst, const void* src) {
    asm volatile("cp.async.cg.shared.global [%0], [%1], 16;" :: "r"(dst), "l"(src));
}
__device__ __forceinline__ float ex2(float x) {
    float y; asm("ex2.approx.ftz.f32 %0, %1;" : "=f"(y) : "f"(x)); return y;
}
__device__ __forceinline__ uint32_t h2u(__half2 v) {
    uint32_t u; memcpy(&u, &v, 4); return u;
}

// ---------------- prep: fp32 -> fp16 hi/lo split for x ----------------------
__global__ void split_x_kernel(const float* __restrict__ x) {
    size_t i0 = ((size_t)blockIdx.x * 256 + threadIdx.x) * 4;
    float4 v = *(const float4*)(x + i0);
    float vv[4] = {v.x, v.y, v.z, v.w};
    __half h[4], l[4];
#pragma unroll
    for (int j = 0; j < 4; j++) {
        h[j] = __float2half_rn(vv[j]);
        l[j] = __float2half_rn(vv[j] - __half2float(h[j]));
    }
    *(uint2*)(g_xfh + i0) = *(uint2*)h;
    *(uint2*)(g_xfl + i0) = *(uint2*)l;
}

// transpose [R][C] -> [C][R] to fp16 into g_wf[which] (generic, used for Wo)
__global__ void tsplit_kernel(const float* __restrict__ in, int which, int R, int C) {
    __shared__ float t[32][33];
    const int z = blockIdx.z;
    const int c0 = blockIdx.x * 32, r0 = blockIdx.y * 32;
    const int tx = threadIdx.x, ty = threadIdx.y;
    const float* inp = in + (size_t)z * R * C;
#pragma unroll
    for (int k = 0; k < 4; k++)
        t[ty + 8 * k][tx] = inp[(size_t)(r0 + ty + 8 * k) * C + c0 + tx];
    __syncthreads();
    __half* oh = g_wf + ((size_t)which << 20) + (size_t)z * R * C;
#pragma unroll
    for (int k = 0; k < 4; k++)
        oh[(size_t)(c0 + ty + 8 * k) * R + r0 + tx] = __float2half_rn(t[tx][ty + 8 * k]);
}

// fused Wq/Wk/Wv transpose: grid (2, 32, 48), z>>4 selects matrix
__global__ void tsplit_qkv_kernel(const float* __restrict__ Wq,
                                  const float* __restrict__ Wk,
                                  const float* __restrict__ Wv) {
    __shared__ float t[32][33];
    const int sel = blockIdx.z >> 4, z = blockIdx.z & 15;
    const int R = 1024, C = 64;
    const int c0 = blockIdx.x * 32, r0 = blockIdx.y * 32;
    const int tx = threadIdx.x, ty = threadIdx.y;
    const float* inp = (sel == 0 ? Wq : sel == 1 ? Wk : Wv) + (size_t)z * R * C;
#pragma unroll
    for (int k = 0; k < 4; k++)
        t[ty + 8 * k][tx] = inp[(size_t)(r0 + ty + 8 * k) * C + c0 + tx];
    __syncthreads();
    __half* oh = g_wf + ((size_t)sel << 20) + (size_t)z * R * C;
#pragma unroll
    for (int k = 0; k < 4; k++)
        oh[(size_t)(c0 + ty + 8 * k) * R + r0 + tx] = __float2half_rn(t[tx][ty + 8 * k]);
}

// ---------------- HMMA GEMM: C = A @ B^T, fp16x2 (A exact pair, B fp16) -----
// Block 128(M) x 256(N), 8 warps (2M x 4N), warp tile 64x64, k-chunk 32,
// 3-stage cp.async ring. Row stride 80 B (validated conflict-free).
// MODE 0: A = x fp16 pair, B = Wq/Wk/Wv^T (z), out fp16 per-head (Q pre-scaled;
//         Q,K as hi/lo pair; V single).
// MODE 1: A = attn out fp16 pair, B = Wo^T, out row-major fp32 (d_out).
#define KC 32
#define A_TILE_B 10240               // 128 rows * 80 B
#define B_TILE_B 20480               // 256 rows * 80 B
#define STG_BYTES (2 * A_TILE_B + B_TILE_B)       // 40960
#define GEMM_SMEM (3 * STG_BYTES)                 // 122880

__device__ __forceinline__ void copy_chunk(int tid, uint32_t stg, int kc, int m0, int n0,
    const __half* Ah, const __half* Al, const __half* B)
{
    const int ko = kc * 32;
#pragma unroll
    for (int i = 0; i < 8; i++) {
        int t = tid + i * 256;
        const __half* src; uint32_t dst;
        if (t < 1024) {        // A: 2 halves x (128 rows x 4 x 16B)
            int half_ = t >> 9, idx = t & 511, r = idx >> 2, c = idx & 3;
            src = (half_ ? Al : Ah) + (size_t)(m0 + r) * 1024 + ko + c * 8;
            dst = stg + half_ * A_TILE_B + r * 80 + c * 16;
        } else {               // B: 256 rows x 4 x 16B
            int u = t - 1024;
            int r = u >> 2, c = u & 3;
            src = B + (size_t)(n0 + r) * 1024 + ko + c * 8;
            dst = stg + 2 * A_TILE_B + r * 80 + c * 16;
        }
        cp16(dst, src);
    }
    asm volatile("cp.async.commit_group;" ::: "memory");
}

template<int MODE>
__global__ __launch_bounds__(256, 1) void gemm_mma(float* __restrict__ outp_)
{
    extern __shared__ __align__(128) char dsm[];
    const uint32_t sb = smem_u32(dsm);
    const int tid = threadIdx.x, wid = tid >> 5, lane = tid & 31;
    const int warp_m = wid >> 2, warp_n = wid & 3;
    const int m0 = blockIdx.x * 128, n0 = blockIdx.y * 256, z = blockIdx.z;

    const __half* B  = g_wf + ((size_t)(MODE ? 3 : z) << 20);
    const __half* Ah = (MODE == 0) ? g_xfh : g_Afh;
    const __half* Al = (MODE == 0) ? g_xfl : g_Afl;

    const uint32_t a_off = (uint32_t)(warp_m * 64 + (lane & 15)) * 80 + (lane >> 4) * 16;
    const uint32_t b_off = (uint32_t)(warp_n * 64 + (lane >> 4) * 8 + (lane & 7)) * 80
                         + ((lane >> 3) & 1) * 16;

    float acc[4][8][4];
#pragma unroll
    for (int i = 0; i < 4; i++)
#pragma unroll
        for (int j = 0; j < 8; j++)
#pragma unroll
            for (int k = 0; k < 4; k++) acc[i][j][k] = 0.f;

    copy_chunk(tid, sb, 0, m0, n0, Ah, Al, B);
    copy_chunk(tid, sb + STG_BYTES, 1, m0, n0, Ah, Al, B);

    for (int kc = 0; kc < KC; kc++) {
        if (kc + 1 < KC) {
            asm volatile("cp.async.wait_group 1;" ::: "memory");
        } else {
            asm volatile("cp.async.wait_group 0;" ::: "memory");
        }
        __syncthreads();
        if (kc + 2 < KC)
            copy_chunk(tid, sb + (uint32_t)((kc + 2) % 3) * STG_BYTES, kc + 2,
                       m0, n0, Ah, Al, B);

        const uint32_t stg = sb + (uint32_t)(kc % 3) * STG_BYTES;
        const uint32_t sB = stg + 2 * A_TILE_B;
#pragma unroll
        for (int ks = 0; ks < 2; ks++) {
            uint32_t ah[4][4], al[4][4], bb[4][4];
#pragma unroll
            for (int mt = 0; mt < 4; mt++) {
                ldsm4(ah[mt], stg + 0 * A_TILE_B + a_off + mt * (16 * 80) + ks * 32);
                ldsm4(al[mt], stg + 1 * A_TILE_B + a_off + mt * (16 * 80) + ks * 32);
            }
#pragma unroll
            for (int pr = 0; pr < 4; pr++)
                ldsm4(bb[pr], sB + b_off + pr * (16 * 80) + ks * 32);
#pragma unroll
            for (int mt = 0; mt < 4; mt++)
#pragma unroll
                for (int nt = 0; nt < 8; nt++) {
                    float* c = acc[mt][nt];
                    const uint32_t* pb = &bb[nt >> 1][(nt & 1) * 2];
                    mma16816h(c, ah[mt], pb);   // A_hi * B
                    mma16816h(c, al[mt], pb);   // A_lo * B (exact A reconstruction)
                }
        }
        __syncthreads();
    }

    const int tg = lane >> 2, tq = lane & 3;
#pragma unroll
    for (int mt = 0; mt < 4; mt++) {
#pragma unroll
        for (int nt = 0; nt < 8; nt++) {
            int row = m0 + warp_m * 64 + mt * 16 + tg;
            int col = n0 + warp_n * 64 + nt * 8 + tq * 2;
            if (MODE == 0) {
                const float scale = (z == 0) ? QSCALE : 1.0f;
                int bb_ = row >> 11, ss = row & 2047, hh = col >> 6, dk = col & 63;
                size_t base = (size_t)z * QKV_ELE
                            + (((size_t)(bb_ * NH + hh)) * SEQ + ss) * DKH + dk;
                float v0 = acc[mt][nt][0] * scale, v1 = acc[mt][nt][1] * scale;
                float v2 = acc[mt][nt][2] * scale, v3 = acc[mt][nt][3] * scale;
                __half2 h0 = __floats2half2_rn(v0, v1);
                __half2 h1 = __floats2half2_rn(v2, v3);
                *(__half2*)&g_qkvh[base]           = h0;
                *(__half2*)&g_qkvh[base + 8 * DKH] = h1;
                if (z < 2) {   // only Q,K need the lo half (V used single-fp16)
                    *(__half2*)&g_qkvl[base] =
                        __floats2half2_rn(v0 - __low2float(h0), v1 - __high2float(h0));
                    *(__half2*)&g_qkvl[base + 8 * DKH] =
                        __floats2half2_rn(v2 - __low2float(h1), v3 - __high2float(h1));
                }
            } else {
                float* dst0 = outp_ + (size_t)row * DM + col;
                float* dst1 = outp_ + (size_t)(row + 8) * DM + col;
                *(float2*)dst0 = make_float2(acc[mt][nt][0], acc[mt][nt][1]);
                *(float2*)dst1 = make_float2(acc[mt][nt][2], acc[mt][nt][3]);
            }
        }
    }
}

// ---------------- causal flash attention on HMMA ----------------------------
// BM=128 (8 warps x 16 rows), BN=64, d=64.
// QK^T: fp16x3 (Q pair x K pair, drop lo*lo -> ~2^-22). PV: fp16x2 (P pair x V).
#define AT_STRIDE 144
#define Q_TILE_B   (128 * AT_STRIDE)        // 18432
#define KV_ARR_B   (64 * AT_STRIDE)         // 9216
#define KV_STAGE_B (3 * KV_ARR_B)           // 27648: K_hi | K_lo | V
#define ATT_SMEM   (2 * Q_TILE_B + 2 * KV_STAGE_B)   // 92160 -> 2 CTAs/SM

__device__ __forceinline__ void load_kv(int tid, uint32_t stg, int j,
    const __half* Khg, const __half* Klg, const __half* Vg)
{
#pragma unroll
    for (int it = 0; it < 6; it++) {
        int i = tid + it * 256;
        int arr = i >> 9, r = (i >> 3) & 63, c = i & 7;
        const __half* src = (arr == 0 ? Khg : arr == 1 ? Klg : Vg)
                          + ((size_t)(j * 64 + r)) * DKH + c * 8;
        cp16(stg + arr * KV_ARR_B + r * AT_STRIDE + c * 16, src);
    }
    asm volatile("cp.async.commit_group;" ::: "memory");
}

__global__ __launch_bounds__(256, 2) void attn_mma()
{
    extern __shared__ __align__(128) char dsm[];
    const uint32_t sb = smem_u32(dsm);
    const uint32_t sQh = sb, sQl = sb + Q_TILE_B;
    const uint32_t sKV = sb + 2 * Q_TILE_B;

    const int qi = (int)gridDim.x - 1 - (int)blockIdx.x;   // heavy tiles first
    const int q0 = qi * 128;
    const int bh = blockIdx.y;
    const int b = bh >> 4, h = bh & 15;
    const int tid = threadIdx.x, w = tid >> 5, lane = tid & 31;

    const __half* Qhg = g_qkvh + ((size_t)bh * SEQ + q0) * DKH;
    const __half* Qlg = g_qkvl + ((size_t)bh * SEQ + q0) * DKH;
    const __half* Khg = g_qkvh + QKV_ELE     + (size_t)bh * SEQ * DKH;
    const __half* Klg = g_qkvl + QKV_ELE     + (size_t)bh * SEQ * DKH;
    const __half* Vg  = g_qkvh + 2 * QKV_ELE + (size_t)bh * SEQ * DKH;

    // Q (hi+lo) -> smem, group 0
#pragma unroll
    for (int it = 0; it < 8; it++) {
        int i = tid + it * 256;
        int half_ = i >> 10, r = (i >> 3) & 127, c = i & 7;
        const __half* src = (half_ ? Qlg : Qhg) + (size_t)r * DKH + c * 8;
        cp16((half_ ? sQl : sQh) + r * AT_STRIDE + c * 16, src);
    }
    asm volatile("cp.async.commit_group;" ::: "memory");

    load_kv(tid, sKV, 0, Khg, Klg, Vg);

    float O[8][4];
#pragma unroll
    for (int i = 0; i < 8; i++)
#pragma unroll
        for (int j = 0; j < 4; j++) O[i][j] = 0.f;
    float m0 = -1e30f, m1 = -1e30f, l0 = 0.f, l1 = 0.f;

    const uint32_t qa_base = (uint32_t)(w * 16 + (lane & 15)) * AT_STRIDE + (lane >> 4) * 16;
    const uint32_t kb_base = (uint32_t)((lane & 7) + ((lane >> 4) & 1) * 8) * AT_STRIDE
                           + ((lane >> 3) & 1) * 16;
    const uint32_t vb_base = (uint32_t)(lane & 15) * AT_STRIDE + (lane >> 4) * 16;

    const int njt = 2 * qi + 2;
    for (int j = 0; j < njt; j++) {
        const uint32_t st = sKV + (uint32_t)(j & 1) * KV_STAGE_B;
        if (j + 1 < njt) {
            load_kv(tid, sKV + (uint32_t)((j + 1) & 1) * KV_STAGE_B, j + 1,
                    Khg, Klg, Vg);
            asm volatile("cp.async.wait_group 1;" ::: "memory");
        } else {
            asm volatile("cp.async.wait_group 0;" ::: "memory");
        }
        __syncthreads();

        // ---- S = Qs @ K^T (fp16x3: qh*kh + qh*kl + ql*kh) ----
        float s[8][4];
#pragma unroll
        for (int i = 0; i < 8; i++)
#pragma unroll
            for (int jj = 0; jj < 4; jj++) s[i][jj] = 0.f;

#pragma unroll
        for (int ks = 0; ks < 4; ks++) {
            uint32_t qh[4], ql[4];
            ldsm4(qh, sQh + qa_base + ks * 32);
            ldsm4(ql, sQl + qa_base + ks * 32);
#pragma unroll
            for (int ng = 0; ng < 4; ng++) {
                uint32_t kh[4], kl[4];
                uint32_t ko = kb_base + ng * (16 * AT_STRIDE) + ks * 32;
                ldsm4(kh, st + 0 * KV_ARR_B + ko);
                ldsm4(kl, st + 1 * KV_ARR_B + ko);
                mma16816h(s[2 * ng],     qh, &kh[0]);
                mma16816h(s[2 * ng],     qh, &kl[0]);
                mma16816h(s[2 * ng],     ql, &kh[0]);
                mma16816h(s[2 * ng + 1], qh, &kh[2]);
                mma16816h(s[2 * ng + 1], qh, &kl[2]);
                mma16816h(s[2 * ng + 1], ql, &kh[2]);
            }
        }

        // ---- causal mask (diagonal-region tiles only) ----
        if (j >= 2 * qi) {
            int r0 = q0 + w * 16 + (lane >> 2);
            int cb = j * 64 + (lane & 3) * 2;
#pragma unroll
            for (int nt = 0; nt < 8; nt++)
#pragma unroll
                for (int cc = 0; cc < 2; cc++) {
                    int col = cb + nt * 8 + cc;
                    if (col > r0)     s[nt][cc]     = -1e30f;
                    if (col > r0 + 8) s[nt][2 + cc] = -1e30f;
                }
        }

        // ---- online softmax (base-2; scale folded into Q) ----
        float mx0 = -1e30f, mx1 = -1e30f;
#pragma unroll
        for (int nt = 0; nt < 8; nt++) {
            mx0 = fmaxf(mx0, fmaxf(s[nt][0], s[nt][1]));
            mx1 = fmaxf(mx1, fmaxf(s[nt][2], s[nt][3]));
        }
        mx0 = fmaxf(mx0, __shfl_xor_sync(0xffffffffu, mx0, 1));
        mx0 = fmaxf(mx0, __shfl_xor_sync(0xffffffffu, mx0, 2));
        mx1 = fmaxf(mx1, __shfl_xor_sync(0xffffffffu, mx1, 1));
        mx1 = fmaxf(mx1, __shfl_xor_sync(0xffffffffu, mx1, 2));
        float mn0 = fmaxf(m0, mx0), mn1 = fmaxf(m1, mx1);
        float a0 = ex2(m0 - mn0), a1 = ex2(m1 - mn1);
        float sm0 = 0.f, sm1 = 0.f;
#pragma unroll
        for (int nt = 0; nt < 8; nt++) {
            s[nt][0] = ex2(s[nt][0] - mn0); sm0 += s[nt][0];
            s[nt][1] = ex2(s[nt][1] - mn0); sm0 += s[nt][1];
            s[nt][2] = ex2(s[nt][2] - mn1); sm1 += s[nt][2];
            s[nt][3] = ex2(s[nt][3] - mn1); sm1 += s[nt][3];
        }
        sm0 += __shfl_xor_sync(0xffffffffu, sm0, 1);
        sm0 += __shfl_xor_sync(0xffffffffu, sm0, 2);
        sm1 += __shfl_xor_sync(0xffffffffu, sm1, 1);
        sm1 += __shfl_xor_sync(0xffffffffu, sm1, 2);
        l0 = l0 * a0 + sm0; l1 = l1 * a1 + sm1;
        m0 = mn0; m1 = mn1;
#pragma unroll
        for (int nt = 0; nt < 8; nt++) {
            O[nt][0] *= a0; O[nt][1] *= a0;
            O[nt][2] *= a1; O[nt][3] *= a1;
        }

        // ---- O += P @ V (fp16x2: P exact pair in regs, V single in smem) ----
#pragma unroll
        for (int ks = 0; ks < 4; ks++) {
            uint32_t ph[4], pl[4];
            {
                __half2 t;
                t = __floats2half2_rn(s[2 * ks][0], s[2 * ks][1]);
                ph[0] = h2u(t);
                pl[0] = h2u(__floats2half2_rn(s[2 * ks][0] - __low2float(t),
                                              s[2 * ks][1] - __high2float(t)));
                t = __floats2half2_rn(s[2 * ks][2], s[2 * ks][3]);
                ph[1] = h2u(t);
                pl[1] = h2u(__floats2half2_rn(s[2 * ks][2] - __low2float(t),
                                              s[2 * ks][3] - __high2float(t)));
                t = __floats2half2_rn(s[2 * ks + 1][0], s[2 * ks + 1][1]);
                ph[2] = h2u(t);
                pl[2] = h2u(__floats2half2_rn(s[2 * ks + 1][0] - __low2float(t),
                                              s[2 * ks + 1][1] - __high2float(t)));
                t = __floats2half2_rn(s[2 * ks + 1][2], s[2 * ks + 1][3]);
                ph[3] = h2u(t);
                pl[3] = h2u(__floats2half2_rn(s[2 * ks + 1][2] - __low2float(t),
                                              s[2 * ks + 1][3] - __high2float(t)));
            }
#pragma unroll
            for (int ng = 0; ng < 4; ng++) {
                uint32_t vh[4];
                uint32_t vo = vb_base + ks * (16 * AT_STRIDE) + ng * 32;
                ldsm4t(vh, st + 2 * KV_ARR_B + vo);
                mma16816h(O[2 * ng],     ph, &vh[0]);
                mma16816h(O[2 * ng],     pl, &vh[0]);
                mma16816h(O[2 * ng + 1], ph, &vh[2]);
                mma16816h(O[2 * ng + 1], pl, &vh[2]);
            }
        }
        __syncthreads();
    }

    // ---- epilogue: normalize + fp16 hi/lo for the output projection ----
    float inv0 = 1.0f / l0, inv1 = 1.0f / l1;
    int r0 = q0 + w * 16 + (lane >> 2);
    size_t rb0 = ((size_t)b * SEQ + r0) * DM + h * 64;
    size_t rb1 = rb0 + (size_t)8 * DM;
#pragma unroll
    for (int nt = 0; nt < 8; nt++) {
        int c0 = nt * 8 + (lane & 3) * 2;
        float v0 = O[nt][0] * inv0, v1 = O[nt][1] * inv0;
        float v2 = O[nt][2] * inv1, v3 = O[nt][3] * inv1;
        __half2 h0 = __floats2half2_rn(v0, v1);
        __half2 h1 = __floats2half2_rn(v2, v3);
        *(__half2*)&g_Afh[rb0 + c0] = h0;
        *(__half2*)&g_Afh[rb1 + c0] = h1;
        *(__half2*)&g_Afl[rb0 + c0] =
            __floats2half2_rn(v0 - __low2float(h0), v1 - __high2float(h0));
        *(__half2*)&g_Afl[rb1 + c0] =
            __floats2half2_rn(v2 - __low2float(h1), v3 - __high2float(h1));
    }
}

// ---------------------------------------------------------------------------
extern "C" void kernel_launch(void* const* d_in, const int* in_sizes, int n_in,
                              void* d_out, int out_size)
{
    const float* x  = (const float*)d_in[0];
    const float* Wq = (const float*)d_in[1];
    const float* Wk = (const float*)d_in[2];
    const float* Wv = (const float*)d_in[3];
    const float* Wo = (const float*)d_in[4];
    float* out = (float*)d_out;

    cudaFuncSetAttribute(gemm_mma<0>, cudaFuncAttributeMaxDynamicSharedMemorySize, GEMM_SMEM);
    cudaFuncSetAttribute(gemm_mma<1>, cudaFuncAttributeMaxDynamicSharedMemorySize, GEMM_SMEM);
    cudaFuncSetAttribute(attn_mma,    cudaFuncAttributeMaxDynamicSharedMemorySize, ATT_SMEM);

    split_x_kernel<<<8192, 256>>>(x);
    tsplit_qkv_kernel<<<dim3(2, 32, 48), dim3(32, 8)>>>(Wq, Wk, Wv);
    tsplit_kernel<<<dim3(32, 32, 1), dim3(32, 8)>>>(Wo, 3, 1024, 1024);

    gemm_mma<0><<<dim3(64, 4, 3), 256, GEMM_SMEM>>>(nullptr);
    attn_mma<<<dim3(SEQ / 128, BATCH * NH), 256, ATT_SMEM>>>();
    gemm_mma<1><<<dim3(64, 4, 1), 256, GEMM_SMEM>>>(out);
}

// round 11
// speedup vs baseline: 3.9430x; 1.0690x over previous
#include <cuda_runtime.h>
#include <cuda_bf16.h>
#include <cuda_fp16.h>
#include <math.h>
#include <stdint.h>
#include <string.h>

#define BATCH 4
#define SEQ   2048
#define DIN   1024
#define NH    16
#define DKH   64
#define DM    1024
#define QKV_ELE ((size_t)BATCH*NH*SEQ*DKH)   // 8388608
#define QSCALE 0.18033688011112042f          // 0.125 * log2(e): softmax in base 2

// ---------------- scratch globals (no allocation allowed) -------------------
__device__ __align__(128) __half g_xfh[(size_t)BATCH*SEQ*DIN];   // x fp16 hi
__device__ __align__(128) __half g_xfl[(size_t)BATCH*SEQ*DIN];   // x fp16 lo
__device__ __align__(128) __half g_wf[(size_t)4<<20];            // Wq,Wk,Wv,Wo^T fp16
__device__ __align__(128) __half g_qkvh[3*QKV_ELE];              // Q hi | K | V
__device__ __align__(128) __half g_qkvl[QKV_ELE];                // Q lo only
__device__ __align__(128) __half g_Afh[(size_t)BATCH*SEQ*DM];    // attn out fp16 hi
__device__ __align__(128) __half g_Afl[(size_t)BATCH*SEQ*DM];    // lo

// ---------------- PTX helpers (sm_100 baseline: ldmatrix / mma.sync) --------
__device__ __forceinline__ uint32_t smem_u32(const void* p) {
    uint32_t a;
    asm("{ .reg .u64 t; cvta.to.shared.u64 t, %1; cvt.u32.u64 %0, t; }" : "=r"(a) : "l"(p));
    return a;
}
__device__ __forceinline__ void ldsm4(uint32_t* f, uint32_t addr) {
    asm volatile("ldmatrix.sync.aligned.m8n8.x4.shared.b16 {%0,%1,%2,%3}, [%4];"
                 : "=r"(f[0]), "=r"(f[1]), "=r"(f[2]), "=r"(f[3]) : "r"(addr));
}
__device__ __forceinline__ void ldsm4t(uint32_t* f, uint32_t addr) {
    asm volatile("ldmatrix.sync.aligned.m8n8.x4.trans.shared.b16 {%0,%1,%2,%3}, [%4];"
                 : "=r"(f[0]), "=r"(f[1]), "=r"(f[2]), "=r"(f[3]) : "r"(addr));
}
__device__ __forceinline__ void mma16816h(float* c, const uint32_t* a, const uint32_t* b) {
    asm volatile(
        "mma.sync.aligned.m16n8k16.row.col.f32.f16.f16.f32 "
        "{%0,%1,%2,%3}, {%4,%5,%6,%7}, {%8,%9}, {%0,%1,%2,%3};"
        : "+f"(c[0]), "+f"(c[1]), "+f"(c[2]), "+f"(c[3])
        : "r"(a[0]), "r"(a[1]), "r"(a[2]), "r"(a[3]), "r"(b[0]), "r"(b[1]));
}
__device__ __forceinline__ void cp16(uint32_t dst, const void* src) {
    asm volatile("cp.async.cg.shared.global [%0], [%1], 16;" :: "r"(dst), "l"(src));
}
__device__ __forceinline__ float ex2(float x) {
    float y; asm("ex2.approx.ftz.f32 %0, %1;" : "=f"(y) : "f"(x)); return y;
}
__device__ __forceinline__ uint32_t h2u(__half2 v) {
    uint32_t u; memcpy(&u, &v, 4); return u;
}

// ---------------- prep: fp32 -> fp16 hi/lo split for x ----------------------
__global__ void split_x_kernel(const float* __restrict__ x) {
    size_t i0 = ((size_t)blockIdx.x * 256 + threadIdx.x) * 4;
    float4 v = *(const float4*)(x + i0);
    float vv[4] = {v.x, v.y, v.z, v.w};
    __half h[4], l[4];
#pragma unroll
    for (int j = 0; j < 4; j++) {
        h[j] = __float2half_rn(vv[j]);
        l[j] = __float2half_rn(vv[j] - __half2float(h[j]));
    }
    *(uint2*)(g_xfh + i0) = *(uint2*)h;
    *(uint2*)(g_xfl + i0) = *(uint2*)l;
}

// transpose [R][C] -> [C][R] to fp16 into g_wf[which] (generic, used for Wo)
__global__ void tsplit_kernel(const float* __restrict__ in, int which, int R, int C) {
    __shared__ float t[32][33];
    const int z = blockIdx.z;
    const int c0 = blockIdx.x * 32, r0 = blockIdx.y * 32;
    const int tx = threadIdx.x, ty = threadIdx.y;
    const float* inp = in + (size_t)z * R * C;
#pragma unroll
    for (int k = 0; k < 4; k++)
        t[ty + 8 * k][tx] = inp[(size_t)(r0 + ty + 8 * k) * C + c0 + tx];
    __syncthreads();
    __half* oh = g_wf + ((size_t)which << 20) + (size_t)z * R * C;
#pragma unroll
    for (int k = 0; k < 4; k++)
        oh[(size_t)(c0 + ty + 8 * k) * R + r0 + tx] = __float2half_rn(t[tx][ty + 8 * k]);
}

// fused Wq/Wk/Wv transpose: grid (2, 32, 48), z>>4 selects matrix
__global__ void tsplit_qkv_kernel(const float* __restrict__ Wq,
                                  const float* __restrict__ Wk,
                                  const float* __restrict__ Wv) {
    __shared__ float t[32][33];
    const int sel = blockIdx.z >> 4, z = blockIdx.z & 15;
    const int R = 1024, C = 64;
    const int c0 = blockIdx.x * 32, r0 = blockIdx.y * 32;
    const int tx = threadIdx.x, ty = threadIdx.y;
    const float* inp = (sel == 0 ? Wq : sel == 1 ? Wk : Wv) + (size_t)z * R * C;
#pragma unroll
    for (int k = 0; k < 4; k++)
        t[ty + 8 * k][tx] = inp[(size_t)(r0 + ty + 8 * k) * C + c0 + tx];
    __syncthreads();
    __half* oh = g_wf + ((size_t)sel << 20) + (size_t)z * R * C;
#pragma unroll
    for (int k = 0; k < 4; k++)
        oh[(size_t)(c0 + ty + 8 * k) * R + r0 + tx] = __float2half_rn(t[tx][ty + 8 * k]);
}

// ---------------- HMMA GEMM: C = A @ B^T, fp16, fp32 accum ------------------
// Block 128(M) x 256(N), 8 warps (2M x 4N), warp tile 64x64, k-chunk 32,
// 3-stage cp.async ring. Row stride 80 B (validated conflict-free).
// MODE 0: A = x fp16 pair, B = Wq/Wk/Wv^T (z).
//   z==0 (Q): two passes (exact A), out fp16 hi/lo pair, pre-scaled by QSCALE.
//   z==1,2 (K,V): single pass (x_hi), out single fp16.
// MODE 1: A = attn out fp16 pair (two passes), B = Wo^T, out fp32 (d_out).
#define KC 32
#define A_TILE_B 10240               // 128 rows * 80 B
#define B_TILE_B 20480               // 256 rows * 80 B
#define STG_BYTES (2 * A_TILE_B + B_TILE_B)       // 40960
#define GEMM_SMEM (3 * STG_BYTES)                 // 122880

__device__ __forceinline__ void copy_chunk(int tid, uint32_t stg, int kc, int m0, int n0,
    const __half* Ah, const __half* Al, const __half* B)
{
    const int ko = kc * 32;
#pragma unroll
    for (int i = 0; i < 8; i++) {
        int t = tid + i * 256;
        const __half* src; uint32_t dst;
        if (t < 1024) {        // A: 2 halves x (128 rows x 4 x 16B)
            int half_ = t >> 9, idx = t & 511, r = idx >> 2, c = idx & 3;
            src = (half_ ? Al : Ah) + (size_t)(m0 + r) * 1024 + ko + c * 8;
            dst = stg + half_ * A_TILE_B + r * 80 + c * 16;
        } else {               // B: 256 rows x 4 x 16B
            int u = t - 1024;
            int r = u >> 2, c = u & 3;
            src = B + (size_t)(n0 + r) * 1024 + ko + c * 8;
            dst = stg + 2 * A_TILE_B + r * 80 + c * 16;
        }
        cp16(dst, src);
    }
    asm volatile("cp.async.commit_group;" ::: "memory");
}

template<int MODE>
__global__ __launch_bounds__(256, 1) void gemm_mma(float* __restrict__ outp_)
{
    extern __shared__ __align__(128) char dsm[];
    const uint32_t sb = smem_u32(dsm);
    const int tid = threadIdx.x, wid = tid >> 5, lane = tid & 31;
    const int warp_m = wid >> 2, warp_n = wid & 3;
    const int m0 = blockIdx.x * 128, n0 = blockIdx.y * 256, z = blockIdx.z;
    const bool twopass = (MODE == 1) || (z == 0);

    const __half* B  = g_wf + ((size_t)(MODE ? 3 : z) << 20);
    const __half* Ah = (MODE == 0) ? g_xfh : g_Afh;
    const __half* Al = (MODE == 0) ? g_xfl : g_Afl;

    const uint32_t a_off = (uint32_t)(warp_m * 64 + (lane & 15)) * 80 + (lane >> 4) * 16;
    const uint32_t b_off = (uint32_t)(warp_n * 64 + (lane >> 4) * 8 + (lane & 7)) * 80
                         + ((lane >> 3) & 1) * 16;

    float acc[4][8][4];
#pragma unroll
    for (int i = 0; i < 4; i++)
#pragma unroll
        for (int j = 0; j < 8; j++)
#pragma unroll
            for (int k = 0; k < 4; k++) acc[i][j][k] = 0.f;

    copy_chunk(tid, sb, 0, m0, n0, Ah, Al, B);
    copy_chunk(tid, sb + STG_BYTES, 1, m0, n0, Ah, Al, B);

    for (int kc = 0; kc < KC; kc++) {
        if (kc + 1 < KC) {
            asm volatile("cp.async.wait_group 1;" ::: "memory");
        } else {
            asm volatile("cp.async.wait_group 0;" ::: "memory");
        }
        __syncthreads();
        if (kc + 2 < KC)
            copy_chunk(tid, sb + (uint32_t)((kc + 2) % 3) * STG_BYTES, kc + 2,
                       m0, n0, Ah, Al, B);

        const uint32_t stg = sb + (uint32_t)(kc % 3) * STG_BYTES;
        const uint32_t sB = stg + 2 * A_TILE_B;
#pragma unroll
        for (int ks = 0; ks < 2; ks++) {
            uint32_t ah[4][4], al[4][4], bb[4][4];
#pragma unroll
            for (int mt = 0; mt < 4; mt++) {
                ldsm4(ah[mt], stg + 0 * A_TILE_B + a_off + mt * (16 * 80) + ks * 32);
                if (twopass)
                    ldsm4(al[mt], stg + 1 * A_TILE_B + a_off + mt * (16 * 80) + ks * 32);
            }
#pragma unroll
            for (int pr = 0; pr < 4; pr++)
                ldsm4(bb[pr], sB + b_off + pr * (16 * 80) + ks * 32);
#pragma unroll
            for (int mt = 0; mt < 4; mt++)
#pragma unroll
                for (int nt = 0; nt < 8; nt++) {
                    float* c = acc[mt][nt];
                    const uint32_t* pb = &bb[nt >> 1][(nt & 1) * 2];
                    mma16816h(c, ah[mt], pb);                 // A_hi * B
                    if (twopass) mma16816h(c, al[mt], pb);    // A_lo * B
                }
        }
        __syncthreads();
    }

    const int tg = lane >> 2, tq = lane & 3;
#pragma unroll
    for (int mt = 0; mt < 4; mt++) {
#pragma unroll
        for (int nt = 0; nt < 8; nt++) {
            int row = m0 + warp_m * 64 + mt * 16 + tg;
            int col = n0 + warp_n * 64 + nt * 8 + tq * 2;
            if (MODE == 0) {
                const float scale = (z == 0) ? QSCALE : 1.0f;
                int bb_ = row >> 11, ss = row & 2047, hh = col >> 6, dk = col & 63;
                size_t base = (size_t)z * QKV_ELE
                            + (((size_t)(bb_ * NH + hh)) * SEQ + ss) * DKH + dk;
                float v0 = acc[mt][nt][0] * scale, v1 = acc[mt][nt][1] * scale;
                float v2 = acc[mt][nt][2] * scale, v3 = acc[mt][nt][3] * scale;
                __half2 h0 = __floats2half2_rn(v0, v1);
                __half2 h1 = __floats2half2_rn(v2, v3);
                *(__half2*)&g_qkvh[base]           = h0;
                *(__half2*)&g_qkvh[base + 8 * DKH] = h1;
                if (z == 0) {   // only Q keeps an exact lo half
                    *(__half2*)&g_qkvl[base] =
                        __floats2half2_rn(v0 - __low2float(h0), v1 - __high2float(h0));
                    *(__half2*)&g_qkvl[base + 8 * DKH] =
                        __floats2half2_rn(v2 - __low2float(h1), v3 - __high2float(h1));
                }
            } else {
                float* dst0 = outp_ + (size_t)row * DM + col;
                float* dst1 = outp_ + (size_t)(row + 8) * DM + col;
                *(float2*)dst0 = make_float2(acc[mt][nt][0], acc[mt][nt][1]);
                *(float2*)dst1 = make_float2(acc[mt][nt][2], acc[mt][nt][3]);
            }
        }
    }
}

// ---------------- causal flash attention on HMMA ----------------------------
// BM=128 (8 warps x 16 rows), BN=64, d=64.
// QK^T: fp16x2 (Q exact pair x K single). PV: fp16x2 (P exact pair x V single).
#define AT_STRIDE 144
#define Q_TILE_B   (128 * AT_STRIDE)        // 18432
#define KV_ARR_B   (64 * AT_STRIDE)         // 9216
#define KV_STAGE_B (2 * KV_ARR_B)           // 18432: K | V
#define ATT_SMEM   (2 * Q_TILE_B + 2 * KV_STAGE_B)   // 73728 -> 2 CTAs/SM

__device__ __forceinline__ void load_kv(int tid, uint32_t stg, int j,
    const __half* Kg, const __half* Vg)
{
#pragma unroll
    for (int it = 0; it < 4; it++) {
        int i = tid + it * 256;
        int arr = i >> 9, r = (i >> 3) & 63, c = i & 7;
        const __half* src = (arr == 0 ? Kg : Vg)
                          + ((size_t)(j * 64 + r)) * DKH + c * 8;
        cp16(stg + arr * KV_ARR_B + r * AT_STRIDE + c * 16, src);
    }
    asm volatile("cp.async.commit_group;" ::: "memory");
}

__global__ __launch_bounds__(256, 2) void attn_mma()
{
    extern __shared__ __align__(128) char dsm[];
    const uint32_t sb = smem_u32(dsm);
    const uint32_t sQh = sb, sQl = sb + Q_TILE_B;
    const uint32_t sKV = sb + 2 * Q_TILE_B;

    const int qi = (int)gridDim.x - 1 - (int)blockIdx.x;   // heavy tiles first
    const int q0 = qi * 128;
    const int bh = blockIdx.y;
    const int b = bh >> 4, h = bh & 15;
    const int tid = threadIdx.x, w = tid >> 5, lane = tid & 31;

    const __half* Qhg = g_qkvh + ((size_t)bh * SEQ + q0) * DKH;
    const __half* Qlg = g_qkvl + ((size_t)bh * SEQ + q0) * DKH;
    const __half* Kg  = g_qkvh + QKV_ELE     + (size_t)bh * SEQ * DKH;
    const __half* Vg  = g_qkvh + 2 * QKV_ELE + (size_t)bh * SEQ * DKH;

    // Q (hi+lo) -> smem, group 0
#pragma unroll
    for (int it = 0; it < 8; it++) {
        int i = tid + it * 256;
        int half_ = i >> 10, r = (i >> 3) & 127, c = i & 7;
        const __half* src = (half_ ? Qlg : Qhg) + (size_t)r * DKH + c * 8;
        cp16((half_ ? sQl : sQh) + r * AT_STRIDE + c * 16, src);
    }
    asm volatile("cp.async.commit_group;" ::: "memory");

    load_kv(tid, sKV, 0, Kg, Vg);

    float O[8][4];
#pragma unroll
    for (int i = 0; i < 8; i++)
#pragma unroll
        for (int j = 0; j < 4; j++) O[i][j] = 0.f;
    float m0 = -1e30f, m1 = -1e30f, l0 = 0.f, l1 = 0.f;

    const uint32_t qa_base = (uint32_t)(w * 16 + (lane & 15)) * AT_STRIDE + (lane >> 4) * 16;
    const uint32_t kb_base = (uint32_t)((lane & 7) + ((lane >> 4) & 1) * 8) * AT_STRIDE
                           + ((lane >> 3) & 1) * 16;
    const uint32_t vb_base = (uint32_t)(lane & 15) * AT_STRIDE + (lane >> 4) * 16;

    const int njt = 2 * qi + 2;
    for (int j = 0; j < njt; j++) {
        const uint32_t st = sKV + (uint32_t)(j & 1) * KV_STAGE_B;
        if (j + 1 < njt) {
            load_kv(tid, sKV + (uint32_t)((j + 1) & 1) * KV_STAGE_B, j + 1, Kg, Vg);
            asm volatile("cp.async.wait_group 1;" ::: "memory");
        } else {
            asm volatile("cp.async.wait_group 0;" ::: "memory");
        }
        __syncthreads();

        // ---- S = Qs @ K^T (fp16x2: qh*k + ql*k, Q exact pair) ----
        float s[8][4];
#pragma unroll
        for (int i = 0; i < 8; i++)
#pragma unroll
            for (int jj = 0; jj < 4; jj++) s[i][jj] = 0.f;

#pragma unroll
        for (int ks = 0; ks < 4; ks++) {
            uint32_t qh[4], ql[4];
            ldsm4(qh, sQh + qa_base + ks * 32);
            ldsm4(ql, sQl + qa_base + ks * 32);
#pragma unroll
            for (int ng = 0; ng < 4; ng++) {
                uint32_t kk[4];
                uint32_t ko = kb_base + ng * (16 * AT_STRIDE) + ks * 32;
                ldsm4(kk, st + 0 * KV_ARR_B + ko);
                mma16816h(s[2 * ng],     qh, &kk[0]);
                mma16816h(s[2 * ng],     ql, &kk[0]);
                mma16816h(s[2 * ng + 1], qh, &kk[2]);
                mma16816h(s[2 * ng + 1], ql, &kk[2]);
            }
        }

        // ---- causal mask (diagonal-region tiles only) ----
        if (j >= 2 * qi) {
            int r0 = q0 + w * 16 + (lane >> 2);
            int cb = j * 64 + (lane & 3) * 2;
#pragma unroll
            for (int nt = 0; nt < 8; nt++)
#pragma unroll
                for (int cc = 0; cc < 2; cc++) {
                    int col = cb + nt * 8 + cc;
                    if (col > r0)     s[nt][cc]     = -1e30f;
                    if (col > r0 + 8) s[nt][2 + cc] = -1e30f;
                }
        }

        // ---- online softmax (base-2; scale folded into Q) ----
        float mx0 = -1e30f, mx1 = -1e30f;
#pragma unroll
        for (int nt = 0; nt < 8; nt++) {
            mx0 = fmaxf(mx0, fmaxf(s[nt][0], s[nt][1]));
            mx1 = fmaxf(mx1, fmaxf(s[nt][2], s[nt][3]));
        }
        mx0 = fmaxf(mx0, __shfl_xor_sync(0xffffffffu, mx0, 1));
        mx0 = fmaxf(mx0, __shfl_xor_sync(0xffffffffu, mx0, 2));
        mx1 = fmaxf(mx1, __shfl_xor_sync(0xffffffffu, mx1, 1));
        mx1 = fmaxf(mx1, __shfl_xor_sync(0xffffffffu, mx1, 2));
        float mn0 = fmaxf(m0, mx0), mn1 = fmaxf(m1, mx1);
        float a0 = ex2(m0 - mn0), a1 = ex2(m1 - mn1);
        float sm0 = 0.f, sm1 = 0.f;
#pragma unroll
        for (int nt = 0; nt < 8; nt++) {
            s[nt][0] = ex2(s[nt][0] - mn0); sm0 += s[nt][0];
            s[nt][1] = ex2(s[nt][1] - mn0); sm0 += s[nt][1];
            s[nt][2] = ex2(s[nt][2] - mn1); sm1 += s[nt][2];
            s[nt][3] = ex2(s[nt][3] - mn1); sm1 += s[nt][3];
        }
        sm0 += __shfl_xor_sync(0xffffffffu, sm0, 1);
        sm0 += __shfl_xor_sync(0xffffffffu, sm0, 2);
        sm1 += __shfl_xor_sync(0xffffffffu, sm1, 1);
        sm1 += __shfl_xor_sync(0xffffffffu, sm1, 2);
        l0 = l0 * a0 + sm0; l1 = l1 * a1 + sm1;
        m0 = mn0; m1 = mn1;
#pragma unroll
        for (int nt = 0; nt < 8; nt++) {
            O[nt][0] *= a0; O[nt][1] *= a0;
            O[nt][2] *= a1; O[nt][3] *= a1;
        }

        // ---- O += P @ V (fp16x2: P exact pair in regs, V single in smem) ----
#pragma unroll
        for (int ks = 0; ks < 4; ks++) {
            uint32_t ph[4], pl[4];
            {
                __half2 t;
                t = __floats2half2_rn(s[2 * ks][0], s[2 * ks][1]);
                ph[0] = h2u(t);
                pl[0] = h2u(__floats2half2_rn(s[2 * ks][0] - __low2float(t),
                                              s[2 * ks][1] - __high2float(t)));
                t = __floats2half2_rn(s[2 * ks][2], s[2 * ks][3]);
                ph[1] = h2u(t);
                pl[1] = h2u(__floats2half2_rn(s[2 * ks][2] - __low2float(t),
                                              s[2 * ks][3] - __high2float(t)));
                t = __floats2half2_rn(s[2 * ks + 1][0], s[2 * ks + 1][1]);
                ph[2] = h2u(t);
                pl[2] = h2u(__floats2half2_rn(s[2 * ks + 1][0] - __low2float(t),
                                              s[2 * ks + 1][1] - __high2float(t)));
                t = __floats2half2_rn(s[2 * ks + 1][2], s[2 * ks + 1][3]);
                ph[3] = h2u(t);
                pl[3] = h2u(__floats2half2_rn(s[2 * ks + 1][2] - __low2float(t),
                                              s[2 * ks + 1][3] - __high2float(t)));
            }
#pragma unroll
            for (int ng = 0; ng < 4; ng++) {
                uint32_t vh[4];
                uint32_t vo = vb_base + ks * (16 * AT_STRIDE) + ng * 32;
                ldsm4t(vh, st + 1 * KV_ARR_B + vo);
                mma16816h(O[2 * ng],     ph, &vh[0]);
                mma16816h(O[2 * ng],     pl, &vh[0]);
                mma16816h(O[2 * ng + 1], ph, &vh[2]);
                mma16816h(O[2 * ng + 1], pl, &vh[2]);
            }
        }
        __syncthreads();
    }

    // ---- epilogue: normalize + fp16 hi/lo for the output projection ----
    float inv0 = 1.0f / l0, inv1 = 1.0f / l1;
    int r0 = q0 + w * 16 + (lane >> 2);
    size_t rb0 = ((size_t)b * SEQ + r0) * DM + h * 64;
    size_t rb1 = rb0 + (size_t)8 * DM;
#pragma unroll
    for (int nt = 0; nt < 8; nt++) {
        int c0 = nt * 8 + (lane & 3) * 2;
        float v0 = O[nt][0] * inv0, v1 = O[nt][1] * inv0;
        float v2 = O[nt][2] * inv1, v3 = O[nt][3] * inv1;
        __half2 h0 = __floats2half2_rn(v0, v1);
        __half2 h1 = __floats2half2_rn(v2, v3);
        *(__half2*)&g_Afh[rb0 + c0] = h0;
        *(__half2*)&g_Afh[rb1 + c0] = h1;
        *(__half2*)&g_Afl[rb0 + c0] =
            __floats2half2_rn(v0 - __low2float(h0), v1 - __high2float(h0));
        *(__half2*)&g_Afl[rb1 + c0] =
            __floats2half2_rn(v2 - __low2float(h1), v3 - __high2float(h1));
    }
}

// ---------------------------------------------------------------------------
extern "C" void kernel_launch(void* const* d_in, const int* in_sizes, int n_in,
                              void* d_out, int out_size)
{
    const float* x  = (const float*)d_in[0];
    const float* Wq = (const float*)d_in[1];
    const float* Wk = (const float*)d_in[2];
    const float* Wv = (const float*)d_in[3];
    const float* Wo = (const float*)d_in[4];
    float* out = (float*)d_out;

    cudaFuncSetAttribute(gemm_mma<0>, cudaFuncAttributeMaxDynamicSharedMemorySize, GEMM_SMEM);
    cudaFuncSetAttribute(gemm_mma<1>, cudaFuncAttributeMaxDynamicSharedMemorySize, GEMM_SMEM);
    cudaFuncSetAttribute(attn_mma,    cudaFuncAttributeMaxDynamicSharedMemorySize, ATT_SMEM);

    split_x_kernel<<<8192, 256>>>(x);
    tsplit_qkv_kernel<<<dim3(2, 32, 48), dim3(32, 8)>>>(Wq, Wk, Wv);
    tsplit_kernel<<<dim3(32, 32, 1), dim3(32, 8)>>>(Wo, 3, 1024, 1024);

    gemm_mma<0><<<dim3(64, 4, 3), 256, GEMM_SMEM>>>(nullptr);
    attn_mma<<<dim3(SEQ / 128, BATCH * NH), 256, ATT_SMEM>>>();
    gemm_mma<1><<<dim3(64, 4, 1), 256, GEMM_SMEM>>>(out);
}

// round 12
// speedup vs baseline: 4.6239x; 1.1727x over previous
#include <cuda_runtime.h>
#include <cuda_bf16.h>
#include <cuda_fp16.h>
#include <math.h>
#include <stdint.h>
#include <string.h>

#define BATCH 4
#define SEQ   2048
#define DIN   1024
#define NH    16
#define DKH   64
#define DM    1024
#define QKV_ELE ((size_t)BATCH*NH*SEQ*DKH)   // 8388608
#define QSCALE 0.18033688011112042f          // 0.125 * log2(e): softmax in base 2

// ---------------- scratch globals (no allocation allowed) -------------------
__device__ __align__(128) __half g_xfh[(size_t)BATCH*SEQ*DIN];   // x fp16 hi
__device__ __align__(128) __half g_xfl[(size_t)BATCH*SEQ*DIN];   // x fp16 lo
__device__ __align__(128) __half g_wf[(size_t)4<<20];            // Wq,Wk,Wv,Wo^T fp16
__device__ __align__(128) __half g_qkvh[3*QKV_ELE];              // Q hi | K | V
__device__ __align__(128) __half g_qkvl[QKV_ELE];                // Q lo only
__device__ __align__(128) __half g_Afh[(size_t)BATCH*SEQ*DM];    // attn out fp16 hi
__device__ __align__(128) __half g_Afl[(size_t)BATCH*SEQ*DM];    // lo

// ---------------- PTX helpers (sm_100 baseline: ldmatrix / mma.sync) --------
__device__ __forceinline__ uint32_t smem_u32(const void* p) {
    uint32_t a;
    asm("{ .reg .u64 t; cvta.to.shared.u64 t, %1; cvt.u32.u64 %0, t; }" : "=r"(a) : "l"(p));
    return a;
}
__device__ __forceinline__ void ldsm4(uint32_t* f, uint32_t addr) {
    asm volatile("ldmatrix.sync.aligned.m8n8.x4.shared.b16 {%0,%1,%2,%3}, [%4];"
                 : "=r"(f[0]), "=r"(f[1]), "=r"(f[2]), "=r"(f[3]) : "r"(addr));
}
__device__ __forceinline__ void ldsm4t(uint32_t* f, uint32_t addr) {
    asm volatile("ldmatrix.sync.aligned.m8n8.x4.trans.shared.b16 {%0,%1,%2,%3}, [%4];"
                 : "=r"(f[0]), "=r"(f[1]), "=r"(f[2]), "=r"(f[3]) : "r"(addr));
}
__device__ __forceinline__ void mma16816h(float* c, const uint32_t* a, const uint32_t* b) {
    asm volatile(
        "mma.sync.aligned.m16n8k16.row.col.f32.f16.f16.f32 "
        "{%0,%1,%2,%3}, {%4,%5,%6,%7}, {%8,%9}, {%0,%1,%2,%3};"
        : "+f"(c[0]), "+f"(c[1]), "+f"(c[2]), "+f"(c[3])
        : "r"(a[0]), "r"(a[1]), "r"(a[2]), "r"(a[3]), "r"(b[0]), "r"(b[1]));
}
__device__ __forceinline__ void cp16(uint32_t dst, const void* src) {
    asm volatile("cp.async.cg.shared.global [%0], [%1], 16;" :: "r"(dst), "l"(src));
}
__device__ __forceinline__ float ex2(float x) {
    float y; asm("ex2.approx.ftz.f32 %0, %1;" : "=f"(y) : "f"(x)); return y;
}
__device__ __forceinline__ uint32_t h2u(__half2 v) {
    uint32_t u; memcpy(&u, &v, 4); return u;
}

// ---------------- prep: fp32 -> fp16 hi/lo split for x ----------------------
__global__ void split_x_kernel(const float* __restrict__ x) {
    size_t i0 = ((size_t)blockIdx.x * 256 + threadIdx.x) * 4;
    float4 v = *(const float4*)(x + i0);
    float vv[4] = {v.x, v.y, v.z, v.w};
    __half h[4], l[4];
#pragma unroll
    for (int j = 0; j < 4; j++) {
        h[j] = __float2half_rn(vv[j]);
        l[j] = __float2half_rn(vv[j] - __half2float(h[j]));
    }
    *(uint2*)(g_xfh + i0) = *(uint2*)h;
    *(uint2*)(g_xfl + i0) = *(uint2*)l;
}

// transpose [R][C] -> [C][R] to fp16 into g_wf[which] (generic, used for Wo)
__global__ void tsplit_kernel(const float* __restrict__ in, int which, int R, int C) {
    __shared__ float t[32][33];
    const int z = blockIdx.z;
    const int c0 = blockIdx.x * 32, r0 = blockIdx.y * 32;
    const int tx = threadIdx.x, ty = threadIdx.y;
    const float* inp = in + (size_t)z * R * C;
#pragma unroll
    for (int k = 0; k < 4; k++)
        t[ty + 8 * k][tx] = inp[(size_t)(r0 + ty + 8 * k) * C + c0 + tx];
    __syncthreads();
    __half* oh = g_wf + ((size_t)which << 20) + (size_t)z * R * C;
#pragma unroll
    for (int k = 0; k < 4; k++)
        oh[(size_t)(c0 + ty + 8 * k) * R + r0 + tx] = __float2half_rn(t[tx][ty + 8 * k]);
}

// fused Wq/Wk/Wv transpose: grid (2, 32, 48), z>>4 selects matrix
__global__ void tsplit_qkv_kernel(const float* __restrict__ Wq,
                                  const float* __restrict__ Wk,
                                  const float* __restrict__ Wv) {
    __shared__ float t[32][33];
    const int sel = blockIdx.z >> 4, z = blockIdx.z & 15;
    const int R = 1024, C = 64;
    const int c0 = blockIdx.x * 32, r0 = blockIdx.y * 32;
    const int tx = threadIdx.x, ty = threadIdx.y;
    const float* inp = (sel == 0 ? Wq : sel == 1 ? Wk : Wv) + (size_t)z * R * C;
#pragma unroll
    for (int k = 0; k < 4; k++)
        t[ty + 8 * k][tx] = inp[(size_t)(r0 + ty + 8 * k) * C + c0 + tx];
    __syncthreads();
    __half* oh = g_wf + ((size_t)sel << 20) + (size_t)z * R * C;
#pragma unroll
    for (int k = 0; k < 4; k++)
        oh[(size_t)(c0 + ty + 8 * k) * R + r0 + tx] = __float2half_rn(t[tx][ty + 8 * k]);
}

// ---------------- HMMA GEMM (2-pass): C = A @ B^T, exact-A fp16 pair --------
// Block 128(M) x 256(N), 8 warps (2M x 4N), warp tile 64x64, k-chunk 32,
// 3-stage cp.async ring. Row stride 80 B (validated conflict-free).
// MODE 0: A = x fp16 pair, B = Wq^T; out Q fp16 hi/lo pair, pre-scaled QSCALE.
// MODE 1: A = attn out fp16 pair, B = Wo^T, out row-major fp32 (d_out).
#define KC 32
#define A_TILE_B 10240               // 128 rows * 80 B
#define B_TILE_B 20480               // 256 rows * 80 B
#define STG_BYTES (2 * A_TILE_B + B_TILE_B)       // 40960
#define GEMM_SMEM (3 * STG_BYTES)                 // 122880

__device__ __forceinline__ void copy_chunk(int tid, uint32_t stg, int kc, int m0, int n0,
    const __half* Ah, const __half* Al, const __half* B)
{
    const int ko = kc * 32;
#pragma unroll
    for (int i = 0; i < 8; i++) {
        int t = tid + i * 256;
        const __half* src; uint32_t dst;
        if (t < 1024) {        // A: 2 halves x (128 rows x 4 x 16B)
            int half_ = t >> 9, idx = t & 511, r = idx >> 2, c = idx & 3;
            src = (half_ ? Al : Ah) + (size_t)(m0 + r) * 1024 + ko + c * 8;
            dst = stg + half_ * A_TILE_B + r * 80 + c * 16;
        } else {               // B: 256 rows x 4 x 16B
            int u = t - 1024;
            int r = u >> 2, c = u & 3;
            src = B + (size_t)(n0 + r) * 1024 + ko + c * 8;
            dst = stg + 2 * A_TILE_B + r * 80 + c * 16;
        }
        cp16(dst, src);
    }
    asm volatile("cp.async.commit_group;" ::: "memory");
}

template<int MODE>
__global__ __launch_bounds__(256, 1) void gemm_mma(float* __restrict__ outp_)
{
    extern __shared__ __align__(128) char dsm[];
    const uint32_t sb = smem_u32(dsm);
    const int tid = threadIdx.x, wid = tid >> 5, lane = tid & 31;
    const int warp_m = wid >> 2, warp_n = wid & 3;
    const int m0 = blockIdx.x * 128, n0 = blockIdx.y * 256;

    const __half* B  = g_wf + ((size_t)(MODE ? 3 : 0) << 20);
    const __half* Ah = (MODE == 0) ? g_xfh : g_Afh;
    const __half* Al = (MODE == 0) ? g_xfl : g_Afl;

    const uint32_t a_off = (uint32_t)(warp_m * 64 + (lane & 15)) * 80 + (lane >> 4) * 16;
    const uint32_t b_off = (uint32_t)(warp_n * 64 + (lane >> 4) * 8 + (lane & 7)) * 80
                         + ((lane >> 3) & 1) * 16;

    float acc[4][8][4];
#pragma unroll
    for (int i = 0; i < 4; i++)
#pragma unroll
        for (int j = 0; j < 8; j++)
#pragma unroll
            for (int k = 0; k < 4; k++) acc[i][j][k] = 0.f;

    copy_chunk(tid, sb, 0, m0, n0, Ah, Al, B);
    copy_chunk(tid, sb + STG_BYTES, 1, m0, n0, Ah, Al, B);

    for (int kc = 0; kc < KC; kc++) {
        if (kc + 1 < KC) {
            asm volatile("cp.async.wait_group 1;" ::: "memory");
        } else {
            asm volatile("cp.async.wait_group 0;" ::: "memory");
        }
        __syncthreads();
        if (kc + 2 < KC)
            copy_chunk(tid, sb + (uint32_t)((kc + 2) % 3) * STG_BYTES, kc + 2,
                       m0, n0, Ah, Al, B);

        const uint32_t stg = sb + (uint32_t)(kc % 3) * STG_BYTES;
        const uint32_t sB = stg + 2 * A_TILE_B;
#pragma unroll
        for (int ks = 0; ks < 2; ks++) {
            uint32_t ah[4][4], al[4][4], bb[4][4];
#pragma unroll
            for (int mt = 0; mt < 4; mt++) {
                ldsm4(ah[mt], stg + 0 * A_TILE_B + a_off + mt * (16 * 80) + ks * 32);
                ldsm4(al[mt], stg + 1 * A_TILE_B + a_off + mt * (16 * 80) + ks * 32);
            }
#pragma unroll
            for (int pr = 0; pr < 4; pr++)
                ldsm4(bb[pr], sB + b_off + pr * (16 * 80) + ks * 32);
#pragma unroll
            for (int mt = 0; mt < 4; mt++)
#pragma unroll
                for (int nt = 0; nt < 8; nt++) {
                    float* c = acc[mt][nt];
                    const uint32_t* pb = &bb[nt >> 1][(nt & 1) * 2];
                    mma16816h(c, ah[mt], pb);   // A_hi * B
                    mma16816h(c, al[mt], pb);   // A_lo * B (exact A)
                }
        }
        __syncthreads();
    }

    const int tg = lane >> 2, tq = lane & 3;
#pragma unroll
    for (int mt = 0; mt < 4; mt++) {
#pragma unroll
        for (int nt = 0; nt < 8; nt++) {
            int row = m0 + warp_m * 64 + mt * 16 + tg;
            int col = n0 + warp_n * 64 + nt * 8 + tq * 2;
            if (MODE == 0) {
                int bb_ = row >> 11, ss = row & 2047, hh = col >> 6, dk = col & 63;
                size_t base = (((size_t)(bb_ * NH + hh)) * SEQ + ss) * DKH + dk;
                float v0 = acc[mt][nt][0] * QSCALE, v1 = acc[mt][nt][1] * QSCALE;
                float v2 = acc[mt][nt][2] * QSCALE, v3 = acc[mt][nt][3] * QSCALE;
                __half2 h0 = __floats2half2_rn(v0, v1);
                __half2 h1 = __floats2half2_rn(v2, v3);
                *(__half2*)&g_qkvh[base]           = h0;
                *(__half2*)&g_qkvh[base + 8 * DKH] = h1;
                *(__half2*)&g_qkvl[base] =
                    __floats2half2_rn(v0 - __low2float(h0), v1 - __high2float(h0));
                *(__half2*)&g_qkvl[base + 8 * DKH] =
                    __floats2half2_rn(v2 - __low2float(h1), v3 - __high2float(h1));
            } else {
                float* dst0 = outp_ + (size_t)row * DM + col;
                float* dst1 = outp_ + (size_t)(row + 8) * DM + col;
                *(float2*)dst0 = make_float2(acc[mt][nt][0], acc[mt][nt][1]);
                *(float2*)dst1 = make_float2(acc[mt][nt][2], acc[mt][nt][3]);
            }
        }
    }
}

// ---------------- K/V GEMM (single-pass x_hi), occupancy 2 ------------------
// Block 128(M) x 128(N), 8 warps (2M x 4N), warp tile 64x32 (R5-validated
// lane maps), k-chunk 32, 3-stage ring at 20.5 KB/stage -> 2 CTAs/SM.
// grid (64, 8, 2): z=0 -> K (Wk^T), z=1 -> V (Wv^T). Out single fp16 per-head.
#define KV_A_TILE 10240
#define KV_STG    (2 * KV_A_TILE)            // 20480: A | B
#define KV_SMEM   (3 * KV_STG)               // 61440

__device__ __forceinline__ void copy_chunk_kv(int tid, uint32_t stg, int kc,
    int m0, int n0, const __half* A, const __half* B)
{
    const int ko = kc * 32;
#pragma unroll
    for (int i = 0; i < 4; i++) {
        int t = tid + i * 256;
        const __half* src; uint32_t dst;
        if (t < 512) {         // A: 128 rows x 4 x 16B
            int r = t >> 2, c = t & 3;
            src = A + (size_t)(m0 + r) * 1024 + ko + c * 8;
            dst = stg + r * 80 + c * 16;
        } else {               // B: 128 rows x 4 x 16B
            int u = t - 512, r = u >> 2, c = u & 3;
            src = B + (size_t)(n0 + r) * 1024 + ko + c * 8;
            dst = stg + KV_A_TILE + r * 80 + c * 16;
        }
        cp16(dst, src);
    }
    asm volatile("cp.async.commit_group;" ::: "memory");
}

__global__ __launch_bounds__(256, 2) void gemm_kv()
{
    extern __shared__ __align__(128) char dsm[];
    const uint32_t sb = smem_u32(dsm);
    const int tid = threadIdx.x, wid = tid >> 5, lane = tid & 31;
    const int warp_m = wid >> 2, warp_n = wid & 3;
    const int m0 = blockIdx.x * 128, n0 = blockIdx.y * 128;
    const int z = blockIdx.z;            // 0=K, 1=V

    const __half* A = g_xfh;
    const __half* B = g_wf + ((size_t)(z + 1) << 20);

    const uint32_t a_off = (uint32_t)(warp_m * 64 + (lane & 15)) * 80 + (lane >> 4) * 16;
    const uint32_t b_off = (uint32_t)(warp_n * 32 + (lane >> 4) * 8 + (lane & 7)) * 80
                         + ((lane >> 3) & 1) * 16;

    float acc[4][4][4];
#pragma unroll
    for (int i = 0; i < 4; i++)
#pragma unroll
        for (int j = 0; j < 4; j++)
#pragma unroll
            for (int k = 0; k < 4; k++) acc[i][j][k] = 0.f;

    copy_chunk_kv(tid, sb, 0, m0, n0, A, B);
    copy_chunk_kv(tid, sb + KV_STG, 1, m0, n0, A, B);

    for (int kc = 0; kc < KC; kc++) {
        if (kc + 1 < KC) {
            asm volatile("cp.async.wait_group 1;" ::: "memory");
        } else {
            asm volatile("cp.async.wait_group 0;" ::: "memory");
        }
        __syncthreads();
        if (kc + 2 < KC)
            copy_chunk_kv(tid, sb + (uint32_t)((kc + 2) % 3) * KV_STG, kc + 2,
                          m0, n0, A, B);

        const uint32_t stg = sb + (uint32_t)(kc % 3) * KV_STG;
        const uint32_t sB = stg + KV_A_TILE;
#pragma unroll
        for (int ks = 0; ks < 2; ks++) {
            uint32_t ah[4][4], bb[2][4];
#pragma unroll
            for (int mt = 0; mt < 4; mt++)
                ldsm4(ah[mt], stg + a_off + mt * (16 * 80) + ks * 32);
#pragma unroll
            for (int pr = 0; pr < 2; pr++)
                ldsm4(bb[pr], sB + b_off + pr * (16 * 80) + ks * 32);
#pragma unroll
            for (int mt = 0; mt < 4; mt++)
#pragma unroll
                for (int nt = 0; nt < 4; nt++)
                    mma16816h(acc[mt][nt], ah[mt], &bb[nt >> 1][(nt & 1) * 2]);
        }
        __syncthreads();
    }

    const int tg = lane >> 2, tq = lane & 3;
#pragma unroll
    for (int mt = 0; mt < 4; mt++) {
#pragma unroll
        for (int nt = 0; nt < 4; nt++) {
            int row = m0 + warp_m * 64 + mt * 16 + tg;
            int col = n0 + warp_n * 32 + nt * 8 + tq * 2;
            int bb_ = row >> 11, ss = row & 2047, hh = col >> 6, dk = col & 63;
            size_t base = (size_t)(z + 1) * QKV_ELE
                        + (((size_t)(bb_ * NH + hh)) * SEQ + ss) * DKH + dk;
            *(__half2*)&g_qkvh[base] =
                __floats2half2_rn(acc[mt][nt][0], acc[mt][nt][1]);
            *(__half2*)&g_qkvh[base + 8 * DKH] =
                __floats2half2_rn(acc[mt][nt][2], acc[mt][nt][3]);
        }
    }
}

// ---------------- causal flash attention on HMMA ----------------------------
// BM=128 (8 warps x 16 rows), BN=64, d=64.
// QK^T: fp16x2 (Q exact pair x K single). PV: fp16x2 (P exact pair x V single).
#define AT_STRIDE 144
#define Q_TILE_B   (128 * AT_STRIDE)        // 18432
#define KV_ARR_B   (64 * AT_STRIDE)         // 9216
#define KV_STAGE_B (2 * KV_ARR_B)           // 18432: K | V
#define ATT_SMEM   (2 * Q_TILE_B + 2 * KV_STAGE_B)   // 73728 -> 2 CTAs/SM

__device__ __forceinline__ void load_kv(int tid, uint32_t stg, int j,
    const __half* Kg, const __half* Vg)
{
#pragma unroll
    for (int it = 0; it < 4; it++) {
        int i = tid + it * 256;
        int arr = i >> 9, r = (i >> 3) & 63, c = i & 7;
        const __half* src = (arr == 0 ? Kg : Vg)
                          + ((size_t)(j * 64 + r)) * DKH + c * 8;
        cp16(stg + arr * KV_ARR_B + r * AT_STRIDE + c * 16, src);
    }
    asm volatile("cp.async.commit_group;" ::: "memory");
}

__global__ __launch_bounds__(256, 2) void attn_mma()
{
    extern __shared__ __align__(128) char dsm[];
    const uint32_t sb = smem_u32(dsm);
    const uint32_t sQh = sb, sQl = sb + Q_TILE_B;
    const uint32_t sKV = sb + 2 * Q_TILE_B;

    const int qi = (int)gridDim.x - 1 - (int)blockIdx.x;   // heavy tiles first
    const int q0 = qi * 128;
    const int bh = blockIdx.y;
    const int b = bh >> 4, h = bh & 15;
    const int tid = threadIdx.x, w = tid >> 5, lane = tid & 31;

    const __half* Qhg = g_qkvh + ((size_t)bh * SEQ + q0) * DKH;
    const __half* Qlg = g_qkvl + ((size_t)bh * SEQ + q0) * DKH;
    const __half* Kg  = g_qkvh + QKV_ELE     + (size_t)bh * SEQ * DKH;
    const __half* Vg  = g_qkvh + 2 * QKV_ELE + (size_t)bh * SEQ * DKH;

    // Q (hi+lo) -> smem, group 0
#pragma unroll
    for (int it = 0; it < 8; it++) {
        int i = tid + it * 256;
        int half_ = i >> 10, r = (i >> 3) & 127, c = i & 7;
        const __half* src = (half_ ? Qlg : Qhg) + (size_t)r * DKH + c * 8;
        cp16((half_ ? sQl : sQh) + r * AT_STRIDE + c * 16, src);
    }
    asm volatile("cp.async.commit_group;" ::: "memory");

    load_kv(tid, sKV, 0, Kg, Vg);

    float O[8][4];
#pragma unroll
    for (int i = 0; i < 8; i++)
#pragma unroll
        for (int j = 0; j < 4; j++) O[i][j] = 0.f;
    float m0 = -1e30f, m1 = -1e30f, l0 = 0.f, l1 = 0.f;

    const uint32_t qa_base = (uint32_t)(w * 16 + (lane & 15)) * AT_STRIDE + (lane >> 4) * 16;
    const uint32_t kb_base = (uint32_t)((lane & 7) + ((lane >> 4) & 1) * 8) * AT_STRIDE
                           + ((lane >> 3) & 1) * 16;
    const uint32_t vb_base = (uint32_t)(lane & 15) * AT_STRIDE + (lane >> 4) * 16;

    const int njt = 2 * qi + 2;
    for (int j = 0; j < njt; j++) {
        const uint32_t st = sKV + (uint32_t)(j & 1) * KV_STAGE_B;
        if (j + 1 < njt) {
            load_kv(tid, sKV + (uint32_t)((j + 1) & 1) * KV_STAGE_B, j + 1, Kg, Vg);
            asm volatile("cp.async.wait_group 1;" ::: "memory");
        } else {
            asm volatile("cp.async.wait_group 0;" ::: "memory");
        }
        __syncthreads();

        // ---- S = Qs @ K^T (fp16x2: qh*k + ql*k, Q exact pair) ----
        float s[8][4];
#pragma unroll
        for (int i = 0; i < 8; i++)
#pragma unroll
            for (int jj = 0; jj < 4; jj++) s[i][jj] = 0.f;

#pragma unroll
        for (int ks = 0; ks < 4; ks++) {
            uint32_t qh[4], ql[4];
            ldsm4(qh, sQh + qa_base + ks * 32);
            ldsm4(ql, sQl + qa_base + ks * 32);
#pragma unroll
            for (int ng = 0; ng < 4; ng++) {
                uint32_t kk[4];
                uint32_t ko = kb_base + ng * (16 * AT_STRIDE) + ks * 32;
                ldsm4(kk, st + 0 * KV_ARR_B + ko);
                mma16816h(s[2 * ng],     qh, &kk[0]);
                mma16816h(s[2 * ng],     ql, &kk[0]);
                mma16816h(s[2 * ng + 1], qh, &kk[2]);
                mma16816h(s[2 * ng + 1], ql, &kk[2]);
            }
        }

        // ---- causal mask (diagonal-region tiles only) ----
        if (j >= 2 * qi) {
            int r0 = q0 + w * 16 + (lane >> 2);
            int cb = j * 64 + (lane & 3) * 2;
#pragma unroll
            for (int nt = 0; nt < 8; nt++)
#pragma unroll
                for (int cc = 0; cc < 2; cc++) {
                    int col = cb + nt * 8 + cc;
                    if (col > r0)     s[nt][cc]     = -1e30f;
                    if (col > r0 + 8) s[nt][2 + cc] = -1e30f;
                }
        }

        // ---- online softmax (base-2; scale folded into Q) ----
        float mx0 = -1e30f, mx1 = -1e30f;
#pragma unroll
        for (int nt = 0; nt < 8; nt++) {
            mx0 = fmaxf(mx0, fmaxf(s[nt][0], s[nt][1]));
            mx1 = fmaxf(mx1, fmaxf(s[nt][2], s[nt][3]));
        }
        mx0 = fmaxf(mx0, __shfl_xor_sync(0xffffffffu, mx0, 1));
        mx0 = fmaxf(mx0, __shfl_xor_sync(0xffffffffu, mx0, 2));
        mx1 = fmaxf(mx1, __shfl_xor_sync(0xffffffffu, mx1, 1));
        mx1 = fmaxf(mx1, __shfl_xor_sync(0xffffffffu, mx1, 2));
        float mn0 = fmaxf(m0, mx0), mn1 = fmaxf(m1, mx1);
        float a0 = ex2(m0 - mn0), a1 = ex2(m1 - mn1);
        float sm0 = 0.f, sm1 = 0.f;
#pragma unroll
        for (int nt = 0; nt < 8; nt++) {
            s[nt][0] = ex2(s[nt][0] - mn0); sm0 += s[nt][0];
            s[nt][1] = ex2(s[nt][1] - mn0); sm0 += s[nt][1];
            s[nt][2] = ex2(s[nt][2] - mn1); sm1 += s[nt][2];
            s[nt][3] = ex2(s[nt][3] - mn1); sm1 += s[nt][3];
        }
        sm0 += __shfl_xor_sync(0xffffffffu, sm0, 1);
        sm0 += __shfl_xor_sync(0xffffffffu, sm0, 2);
        sm1 += __shfl_xor_sync(0xffffffffu, sm1, 1);
        sm1 += __shfl_xor_sync(0xffffffffu, sm1, 2);
        l0 = l0 * a0 + sm0; l1 = l1 * a1 + sm1;
        m0 = mn0; m1 = mn1;
#pragma unroll
        for (int nt = 0; nt < 8; nt++) {
            O[nt][0] *= a0; O[nt][1] *= a0;
            O[nt][2] *= a1; O[nt][3] *= a1;
        }

        // ---- O += P @ V (fp16x2: P exact pair in regs, V single in smem) ----
#pragma unroll
        for (int ks = 0; ks < 4; ks++) {
            uint32_t ph[4], pl[4];
            {
                __half2 t;
                t = __floats2half2_rn(s[2 * ks][0], s[2 * ks][1]);
                ph[0] = h2u(t);
                pl[0] = h2u(__floats2half2_rn(s[2 * ks][0] - __low2float(t),
                                              s[2 * ks][1] - __high2float(t)));
                t = __floats2half2_rn(s[2 * ks][2], s[2 * ks][3]);
                ph[1] = h2u(t);
                pl[1] = h2u(__floats2half2_rn(s[2 * ks][2] - __low2float(t),
                                              s[2 * ks][3] - __high2float(t)));
                t = __floats2half2_rn(s[2 * ks + 1][0], s[2 * ks + 1][1]);
                ph[2] = h2u(t);
                pl[2] = h2u(__floats2half2_rn(s[2 * ks + 1][0] - __low2float(t),
                                              s[2 * ks + 1][1] - __high2float(t)));
                t = __floats2half2_rn(s[2 * ks + 1][2], s[2 * ks + 1][3]);
                ph[3] = h2u(t);
                pl[3] = h2u(__floats2half2_rn(s[2 * ks + 1][2] - __low2float(t),
                                              s[2 * ks + 1][3] - __high2float(t)));
            }
#pragma unroll
            for (int ng = 0; ng < 4; ng++) {
                uint32_t vh[4];
                uint32_t vo = vb_base + ks * (16 * AT_STRIDE) + ng * 32;
                ldsm4t(vh, st + 1 * KV_ARR_B + vo);
                mma16816h(O[2 * ng],     ph, &vh[0]);
                mma16816h(O[2 * ng],     pl, &vh[0]);
                mma16816h(O[2 * ng + 1], ph, &vh[2]);
                mma16816h(O[2 * ng + 1], pl, &vh[2]);
            }
        }
        __syncthreads();
    }

    // ---- epilogue: normalize + fp16 hi/lo for the output projection ----
    float inv0 = 1.0f / l0, inv1 = 1.0f / l1;
    int r0 = q0 + w * 16 + (lane >> 2);
    size_t rb0 = ((size_t)b * SEQ + r0) * DM + h * 64;
    size_t rb1 = rb0 + (size_t)8 * DM;
#pragma unroll
    for (int nt = 0; nt < 8; nt++) {
        int c0 = nt * 8 + (lane & 3) * 2;
        float v0 = O[nt][0] * inv0, v1 = O[nt][1] * inv0;
        float v2 = O[nt][2] * inv1, v3 = O[nt][3] * inv1;
        __half2 h0 = __floats2half2_rn(v0, v1);
        __half2 h1 = __floats2half2_rn(v2, v3);
        *(__half2*)&g_Afh[rb0 + c0] = h0;
        *(__half2*)&g_Afh[rb1 + c0] = h1;
        *(__half2*)&g_Afl[rb0 + c0] =
            __floats2half2_rn(v0 - __low2float(h0), v1 - __high2float(h0));
        *(__half2*)&g_Afl[rb1 + c0] =
            __floats2half2_rn(v2 - __low2float(h1), v3 - __high2float(h1));
    }
}

// ---------------------------------------------------------------------------
extern "C" void kernel_launch(void* const* d_in, const int* in_sizes, int n_in,
                              void* d_out, int out_size)
{
    const float* x  = (const float*)d_in[0];
    const float* Wq = (const float*)d_in[1];
    const float* Wk = (const float*)d_in[2];
    const float* Wv = (const float*)d_in[3];
    const float* Wo = (const float*)d_in[4];
    float* out = (float*)d_out;

    cudaFuncSetAttribute(gemm_mma<0>, cudaFuncAttributeMaxDynamicSharedMemorySize, GEMM_SMEM);
    cudaFuncSetAttribute(gemm_mma<1>, cudaFuncAttributeMaxDynamicSharedMemorySize, GEMM_SMEM);
    cudaFuncSetAttribute(gemm_kv,     cudaFuncAttributeMaxDynamicSharedMemorySize, KV_SMEM);
    cudaFuncSetAttribute(attn_mma,    cudaFuncAttributeMaxDynamicSharedMemorySize, ATT_SMEM);

    split_x_kernel<<<8192, 256>>>(x);
    tsplit_qkv_kernel<<<dim3(2, 32, 48), dim3(32, 8)>>>(Wq, Wk, Wv);
    tsplit_kernel<<<dim3(32, 32, 1), dim3(32, 8)>>>(Wo, 3, 1024, 1024);

    gemm_kv<<<dim3(64, 8, 2), 256, KV_SMEM>>>();
    gemm_mma<0><<<dim3(64, 4, 1), 256, GEMM_SMEM>>>(nullptr);
    attn_mma<<<dim3(SEQ / 128, BATCH * NH), 256, ATT_SMEM>>>();
    gemm_mma<1><<<dim3(64, 4, 1), 256, GEMM_SMEM>>>(out);
}

// round 14
// speedup vs baseline: 5.0484x; 1.0918x over previous
#include <cuda_runtime.h>
#include <cuda_bf16.h>
#include <cuda_fp16.h>
#include <math.h>
#include <stdint.h>
#include <string.h>

#define BATCH 4
#define SEQ   2048
#define DIN   1024
#define NH    16
#define DKH   64
#define DM    1024
#define QKV_ELE ((size_t)BATCH*NH*SEQ*DKH)   // 8388608
#define QSCALE 0.18033688011112042f          // 0.125 * log2(e): softmax in base 2

// ---------------- scratch globals (no allocation allowed) -------------------
__device__ __align__(128) __half g_xfh[(size_t)BATCH*SEQ*DIN];   // x fp16 hi
__device__ __align__(128) __half g_xfl[(size_t)BATCH*SEQ*DIN];   // x fp16 lo
__device__ __align__(128) __half g_wf[(size_t)4<<20];            // Wq,Wk,Wv,Wo^T fp16
__device__ __align__(128) __half g_qkvh[3*QKV_ELE];              // Q hi | K | V
__device__ __align__(128) __half g_qkvl[QKV_ELE];                // Q lo only
__device__ __align__(128) __half g_Afh[(size_t)BATCH*SEQ*DM];    // attn out fp16

// ---------------- PTX helpers (sm_100 baseline: ldmatrix / mma.sync) --------
__device__ __forceinline__ uint32_t smem_u32(const void* p) {
    uint32_t a;
    asm("{ .reg .u64 t; cvta.to.shared.u64 t, %1; cvt.u32.u64 %0, t; }" : "=r"(a) : "l"(p));
    return a;
}
__device__ __forceinline__ void ldsm4(uint32_t* f, uint32_t addr) {
    asm volatile("ldmatrix.sync.aligned.m8n8.x4.shared.b16 {%0,%1,%2,%3}, [%4];"
                 : "=r"(f[0]), "=r"(f[1]), "=r"(f[2]), "=r"(f[3]) : "r"(addr));
}
__device__ __forceinline__ void ldsm4t(uint32_t* f, uint32_t addr) {
    asm volatile("ldmatrix.sync.aligned.m8n8.x4.trans.shared.b16 {%0,%1,%2,%3}, [%4];"
                 : "=r"(f[0]), "=r"(f[1]), "=r"(f[2]), "=r"(f[3]) : "r"(addr));
}
__device__ __forceinline__ void mma16816h(float* c, const uint32_t* a, const uint32_t* b) {
    asm volatile(
        "mma.sync.aligned.m16n8k16.row.col.f32.f16.f16.f32 "
        "{%0,%1,%2,%3}, {%4,%5,%6,%7}, {%8,%9}, {%0,%1,%2,%3};"
        : "+f"(c[0]), "+f"(c[1]), "+f"(c[2]), "+f"(c[3])
        : "r"(a[0]), "r"(a[1]), "r"(a[2]), "r"(a[3]), "r"(b[0]), "r"(b[1]));
}
__device__ __forceinline__ void cp16(uint32_t dst, const void* src) {
    asm volatile("cp.async.cg.shared.global [%0], [%1], 16;" :: "r"(dst), "l"(src));
}
__device__ __forceinline__ float ex2(float x) {
    float y; asm("ex2.approx.ftz.f32 %0, %1;" : "=f"(y) : "f"(x)); return y;
}
__device__ __forceinline__ uint32_t h2u(__half2 v) {
    uint32_t u; memcpy(&u, &v, 4); return u;
}

// ---------------- prep: fp32 -> fp16 hi/lo split for x ----------------------
__global__ void split_x_kernel(const float* __restrict__ x) {
    size_t i0 = ((size_t)blockIdx.x * 256 + threadIdx.x) * 4;
    float4 v = *(const float4*)(x + i0);
    float vv[4] = {v.x, v.y, v.z, v.w};
    __half h[4], l[4];
#pragma unroll
    for (int j = 0; j < 4; j++) {
        h[j] = __float2half_rn(vv[j]);
        l[j] = __float2half_rn(vv[j] - __half2float(h[j]));
    }
    *(uint2*)(g_xfh + i0) = *(uint2*)h;
    *(uint2*)(g_xfl + i0) = *(uint2*)l;
}

// transpose [R][C] -> [C][R] to fp16 into g_wf[which] (generic, used for Wo)
__global__ void tsplit_kernel(const float* __restrict__ in, int which, int R, int C) {
    __shared__ float t[32][33];
    const int z = blockIdx.z;
    const int c0 = blockIdx.x * 32, r0 = blockIdx.y * 32;
    const int tx = threadIdx.x, ty = threadIdx.y;
    const float* inp = in + (size_t)z * R * C;
#pragma unroll
    for (int k = 0; k < 4; k++)
        t[ty + 8 * k][tx] = inp[(size_t)(r0 + ty + 8 * k) * C + c0 + tx];
    __syncthreads();
    __half* oh = g_wf + ((size_t)which << 20) + (size_t)z * R * C;
#pragma unroll
    for (int k = 0; k < 4; k++)
        oh[(size_t)(c0 + ty + 8 * k) * R + r0 + tx] = __float2half_rn(t[tx][ty + 8 * k]);
}

// fused Wq/Wk/Wv transpose: grid (2, 32, 48), z>>4 selects matrix
__global__ void tsplit_qkv_kernel(const float* __restrict__ Wq,
                                  const float* __restrict__ Wk,
                                  const float* __restrict__ Wv) {
    __shared__ float t[32][33];
    const int sel = blockIdx.z >> 4, z = blockIdx.z & 15;
    const int R = 1024, C = 64;
    const int c0 = blockIdx.x * 32, r0 = blockIdx.y * 32;
    const int tx = threadIdx.x, ty = threadIdx.y;
    const float* inp = (sel == 0 ? Wq : sel == 1 ? Wk : Wv) + (size_t)z * R * C;
#pragma unroll
    for (int k = 0; k < 4; k++)
        t[ty + 8 * k][tx] = inp[(size_t)(r0 + ty + 8 * k) * C + c0 + tx];
    __syncthreads();
    __half* oh = g_wf + ((size_t)sel << 20) + (size_t)z * R * C;
#pragma unroll
    for (int k = 0; k < 4; k++)
        oh[(size_t)(c0 + ty + 8 * k) * R + r0 + tx] = __float2half_rn(t[tx][ty + 8 * k]);
}

// ---------------- Q GEMM (2-pass exact-A): block 128x256, occ 1 -------------
#define KC 32
#define A_TILE_B 10240               // 128 rows * 80 B
#define B_TILE_B 20480               // 256 rows * 80 B
#define STG_BYTES (2 * A_TILE_B + B_TILE_B)       // 40960
#define GEMM_SMEM (3 * STG_BYTES)                 // 122880

__device__ __forceinline__ void copy_chunk(int tid, uint32_t stg, int kc, int m0, int n0,
    const __half* Ah, const __half* Al, const __half* B)
{
    const int ko = kc * 32;
#pragma unroll
    for (int i = 0; i < 8; i++) {
        int t = tid + i * 256;
        const __half* src; uint32_t dst;
        if (t < 1024) {        // A: 2 halves x (128 rows x 4 x 16B)
            int half_ = t >> 9, idx = t & 511, r = idx >> 2, c = idx & 3;
            src = (half_ ? Al : Ah) + (size_t)(m0 + r) * 1024 + ko + c * 8;
            dst = stg + half_ * A_TILE_B + r * 80 + c * 16;
        } else {               // B: 256 rows x 4 x 16B
            int u = t - 1024;
            int r = u >> 2, c = u & 3;
            src = B + (size_t)(n0 + r) * 1024 + ko + c * 8;
            dst = stg + 2 * A_TILE_B + r * 80 + c * 16;
        }
        cp16(dst, src);
    }
    asm volatile("cp.async.commit_group;" ::: "memory");
}

__global__ __launch_bounds__(256, 1) void gemm_q()
{
    extern __shared__ __align__(128) char dsm[];
    const uint32_t sb = smem_u32(dsm);
    const int tid = threadIdx.x, wid = tid >> 5, lane = tid & 31;
    const int warp_m = wid >> 2, warp_n = wid & 3;
    const int m0 = blockIdx.x * 128, n0 = blockIdx.y * 256;

    const __half* B  = g_wf;          // Wq^T
    const __half* Ah = g_xfh;
    const __half* Al = g_xfl;

    const uint32_t a_off = (uint32_t)(warp_m * 64 + (lane & 15)) * 80 + (lane >> 4) * 16;
    const uint32_t b_off = (uint32_t)(warp_n * 64 + (lane >> 4) * 8 + (lane & 7)) * 80
                         + ((lane >> 3) & 1) * 16;

    float acc[4][8][4];
#pragma unroll
    for (int i = 0; i < 4; i++)
#pragma unroll
        for (int j = 0; j < 8; j++)
#pragma unroll
            for (int k = 0; k < 4; k++) acc[i][j][k] = 0.f;

    copy_chunk(tid, sb, 0, m0, n0, Ah, Al, B);
    copy_chunk(tid, sb + STG_BYTES, 1, m0, n0, Ah, Al, B);

    for (int kc = 0; kc < KC; kc++) {
        if (kc + 1 < KC) {
            asm volatile("cp.async.wait_group 1;" ::: "memory");
        } else {
            asm volatile("cp.async.wait_group 0;" ::: "memory");
        }
        __syncthreads();
        if (kc + 2 < KC)
            copy_chunk(tid, sb + (uint32_t)((kc + 2) % 3) * STG_BYTES, kc + 2,
                       m0, n0, Ah, Al, B);

        const uint32_t stg = sb + (uint32_t)(kc % 3) * STG_BYTES;
        const uint32_t sB = stg + 2 * A_TILE_B;
#pragma unroll
        for (int ks = 0; ks < 2; ks++) {
            uint32_t ah[4][4], al[4][4], bb[4][4];
#pragma unroll
            for (int mt = 0; mt < 4; mt++) {
                ldsm4(ah[mt], stg + 0 * A_TILE_B + a_off + mt * (16 * 80) + ks * 32);
                ldsm4(al[mt], stg + 1 * A_TILE_B + a_off + mt * (16 * 80) + ks * 32);
            }
#pragma unroll
            for (int pr = 0; pr < 4; pr++)
                ldsm4(bb[pr], sB + b_off + pr * (16 * 80) + ks * 32);
#pragma unroll
            for (int mt = 0; mt < 4; mt++)
#pragma unroll
                for (int nt = 0; nt < 8; nt++) {
                    float* c = acc[mt][nt];
                    const uint32_t* pb = &bb[nt >> 1][(nt & 1) * 2];
                    mma16816h(c, ah[mt], pb);
                    mma16816h(c, al[mt], pb);
                }
        }
        __syncthreads();
    }

    const int tg = lane >> 2, tq = lane & 3;
#pragma unroll
    for (int mt = 0; mt < 4; mt++) {
#pragma unroll
        for (int nt = 0; nt < 8; nt++) {
            int row = m0 + warp_m * 64 + mt * 16 + tg;
            int col = n0 + warp_n * 64 + nt * 8 + tq * 2;
            int bb_ = row >> 11, ss = row & 2047, hh = col >> 6, dk = col & 63;
            size_t base = (((size_t)(bb_ * NH + hh)) * SEQ + ss) * DKH + dk;
            float v0 = acc[mt][nt][0] * QSCALE, v1 = acc[mt][nt][1] * QSCALE;
            float v2 = acc[mt][nt][2] * QSCALE, v3 = acc[mt][nt][3] * QSCALE;
            __half2 h0 = __floats2half2_rn(v0, v1);
            __half2 h1 = __floats2half2_rn(v2, v3);
            *(__half2*)&g_qkvh[base]           = h0;
            *(__half2*)&g_qkvh[base + 8 * DKH] = h1;
            *(__half2*)&g_qkvl[base] =
                __floats2half2_rn(v0 - __low2float(h0), v1 - __high2float(h0));
            *(__half2*)&g_qkvl[base + 8 * DKH] =
                __floats2half2_rn(v2 - __low2float(h1), v3 - __high2float(h1));
        }
    }
}

// ---------------- single-pass GEMM, occ 2 (K/V and output projection) -------
// Block 128(M) x 128(N), 8 warps (2M x 4N), warp tile 64x32, k-chunk 32,
// 3-stage ring at 20.5 KB/stage -> 2 CTAs/SM.
// PROJ=0: grid (64,8,2): z=0 -> K, z=1 -> V; A=x_hi, out per-head fp16.
// PROJ=1: grid (64,8,1): A=attn out fp16, B=Wo^T, out fp32 (d_out).
#define KV_A_TILE 10240
#define KV_STG    (2 * KV_A_TILE)            // 20480: A | B
#define KV_SMEM   (3 * KV_STG)               // 61440

__device__ __forceinline__ void copy_chunk_kv(int tid, uint32_t stg, int kc,
    int m0, int n0, const __half* A, const __half* B)
{
    const int ko = kc * 32;
#pragma unroll
    for (int i = 0; i < 4; i++) {
        int t = tid + i * 256;
        const __half* src; uint32_t dst;
        if (t < 512) {         // A: 128 rows x 4 x 16B
            int r = t >> 2, c = t & 3;
            src = A + (size_t)(m0 + r) * 1024 + ko + c * 8;
            dst = stg + r * 80 + c * 16;
        } else {               // B: 128 rows x 4 x 16B
            int u = t - 512, r = u >> 2, c = u & 3;
            src = B + (size_t)(n0 + r) * 1024 + ko + c * 8;
            dst = stg + KV_A_TILE + r * 80 + c * 16;
        }
        cp16(dst, src);
    }
    asm volatile("cp.async.commit_group;" ::: "memory");
}

template<int PROJ>
__global__ __launch_bounds__(256, 2) void gemm_sp(float* __restrict__ outp_)
{
    extern __shared__ __align__(128) char dsm[];
    const uint32_t sb = smem_u32(dsm);
    const int tid = threadIdx.x, wid = tid >> 5, lane = tid & 31;
    const int warp_m = wid >> 2, warp_n = wid & 3;
    const int m0 = blockIdx.x * 128, n0 = blockIdx.y * 128;
    const int z = blockIdx.z;            // PROJ=0: 0=K, 1=V

    const __half* A = PROJ ? g_Afh : g_xfh;
    const __half* B = g_wf + ((size_t)(PROJ ? 3 : z + 1) << 20);

    const uint32_t a_off = (uint32_t)(warp_m * 64 + (lane & 15)) * 80 + (lane >> 4) * 16;
    const uint32_t b_off = (uint32_t)(warp_n * 32 + (lane >> 4) * 8 + (lane & 7)) * 80
                         + ((lane >> 3) & 1) * 16;

    float acc[4][4][4];
#pragma unroll
    for (int i = 0; i < 4; i++)
#pragma unroll
        for (int j = 0; j < 4; j++)
#pragma unroll
            for (int k = 0; k < 4; k++) acc[i][j][k] = 0.f;

    copy_chunk_kv(tid, sb, 0, m0, n0, A, B);
    copy_chunk_kv(tid, sb + KV_STG, 1, m0, n0, A, B);

    for (int kc = 0; kc < KC; kc++) {
        if (kc + 1 < KC) {
            asm volatile("cp.async.wait_group 1;" ::: "memory");
        } else {
            asm volatile("cp.async.wait_group 0;" ::: "memory");
        }
        __syncthreads();
        if (kc + 2 < KC)
            copy_chunk_kv(tid, sb + (uint32_t)((kc + 2) % 3) * KV_STG, kc + 2,
                          m0, n0, A, B);

        const uint32_t stg = sb + (uint32_t)(kc % 3) * KV_STG;
        const uint32_t sB = stg + KV_A_TILE;
#pragma unroll
        for (int ks = 0; ks < 2; ks++) {
            uint32_t ah[4][4], bb[2][4];
#pragma unroll
            for (int mt = 0; mt < 4; mt++)
                ldsm4(ah[mt], stg + a_off + mt * (16 * 80) + ks * 32);
#pragma unroll
            for (int pr = 0; pr < 2; pr++)
                ldsm4(bb[pr], sB + b_off + pr * (16 * 80) + ks * 32);
#pragma unroll
            for (int mt = 0; mt < 4; mt++)
#pragma unroll
                for (int nt = 0; nt < 4; nt++)
                    mma16816h(acc[mt][nt], ah[mt], &bb[nt >> 1][(nt & 1) * 2]);
        }
        __syncthreads();
    }

    const int tg = lane >> 2, tq = lane & 3;
#pragma unroll
    for (int mt = 0; mt < 4; mt++) {
#pragma unroll
        for (int nt = 0; nt < 4; nt++) {
            int row = m0 + warp_m * 64 + mt * 16 + tg;
            int col = n0 + warp_n * 32 + nt * 8 + tq * 2;
            if (PROJ) {
                float* dst0 = outp_ + (size_t)row * DM + col;
                float* dst1 = outp_ + (size_t)(row + 8) * DM + col;
                *(float2*)dst0 = make_float2(acc[mt][nt][0], acc[mt][nt][1]);
                *(float2*)dst1 = make_float2(acc[mt][nt][2], acc[mt][nt][3]);
            } else {
                int bb_ = row >> 11, ss = row & 2047, hh = col >> 6, dk = col & 63;
                size_t base = (size_t)(z + 1) * QKV_ELE
                            + (((size_t)(bb_ * NH + hh)) * SEQ + ss) * DKH + dk;
                *(__half2*)&g_qkvh[base] =
                    __floats2half2_rn(acc[mt][nt][0], acc[mt][nt][1]);
                *(__half2*)&g_qkvh[base + 8 * DKH] =
                    __floats2half2_rn(acc[mt][nt][2], acc[mt][nt][3]);
            }
        }
    }
}

// ---------------- causal flash attention on HMMA ----------------------------
// BM=128 (8 warps x 16 rows), BN=64, d=64.
// QK^T: fp16x2 (Q exact pair x K single). PV: fp16x2 (P exact pair x V single).
#define AT_STRIDE 144
#define Q_TILE_B   (128 * AT_STRIDE)        // 18432
#define KV_ARR_B   (64 * AT_STRIDE)         // 9216
#define KV_STAGE_B (2 * KV_ARR_B)           // 18432: K | V
#define ATT_SMEM   (2 * Q_TILE_B + 2 * KV_STAGE_B)   // 73728 -> 2 CTAs/SM

__device__ __forceinline__ void load_kv(int tid, uint32_t stg, int j,
    const __half* Kg, const __half* Vg)
{
#pragma unroll
    for (int it = 0; it < 4; it++) {
        int i = tid + it * 256;
        int arr = i >> 9, r = (i >> 3) & 63, c = i & 7;
        const __half* src = (arr == 0 ? Kg : Vg)
                          + ((size_t)(j * 64 + r)) * DKH + c * 8;
        cp16(stg + arr * KV_ARR_B + r * AT_STRIDE + c * 16, src);
    }
    asm volatile("cp.async.commit_group;" ::: "memory");
}

__global__ __launch_bounds__(256, 2) void attn_mma()
{
    extern __shared__ __align__(128) char dsm[];
    const uint32_t sb = smem_u32(dsm);
    const uint32_t sQh = sb, sQl = sb + Q_TILE_B;
    const uint32_t sKV = sb + 2 * Q_TILE_B;

    const int qi = (int)gridDim.x - 1 - (int)blockIdx.x;   // heavy tiles first
    const int q0 = qi * 128;
    const int bh = blockIdx.y;
    const int b = bh >> 4, h = bh & 15;
    const int tid = threadIdx.x, w = tid >> 5, lane = tid & 31;

    const __half* Qhg = g_qkvh + ((size_t)bh * SEQ + q0) * DKH;
    const __half* Qlg = g_qkvl + ((size_t)bh * SEQ + q0) * DKH;
    const __half* Kg  = g_qkvh + QKV_ELE     + (size_t)bh * SEQ * DKH;
    const __half* Vg  = g_qkvh + 2 * QKV_ELE + (size_t)bh * SEQ * DKH;

    // Q (hi+lo) -> smem, group 0
#pragma unroll
    for (int it = 0; it < 8; it++) {
        int i = tid + it * 256;
        int half_ = i >> 10, r = (i >> 3) & 127, c = i & 7;
        const __half* src = (half_ ? Qlg : Qhg) + (size_t)r * DKH + c * 8;
        cp16((half_ ? sQl : sQh) + r * AT_STRIDE + c * 16, src);
    }
    asm volatile("cp.async.commit_group;" ::: "memory");

    load_kv(tid, sKV, 0, Kg, Vg);

    float O[8][4];
#pragma unroll
    for (int i = 0; i < 8; i++)
#pragma unroll
        for (int j = 0; j < 4; j++) O[i][j] = 0.f;
    float m0 = -1e30f, m1 = -1e30f, l0 = 0.f, l1 = 0.f;

    const uint32_t qa_base = (uint32_t)(w * 16 + (lane & 15)) * AT_STRIDE + (lane >> 4) * 16;
    const uint32_t kb_base = (uint32_t)((lane & 7) + ((lane >> 4) & 1) * 8) * AT_STRIDE
                           + ((lane >> 3) & 1) * 16;
    const uint32_t vb_base = (uint32_t)(lane & 15) * AT_STRIDE + (lane >> 4) * 16;

    const int njt = 2 * qi + 2;
    for (int j = 0; j < njt; j++) {
        const uint32_t st = sKV + (uint32_t)(j & 1) * KV_STAGE_B;
        if (j + 1 < njt) {
            load_kv(tid, sKV + (uint32_t)((j + 1) & 1) * KV_STAGE_B, j + 1, Kg, Vg);
            asm volatile("cp.async.wait_group 1;" ::: "memory");
        } else {
            asm volatile("cp.async.wait_group 0;" ::: "memory");
        }
        __syncthreads();

        // ---- S = Qs @ K^T (fp16x2: qh*k + ql*k, Q exact pair) ----
        float s[8][4];
#pragma unroll
        for (int i = 0; i < 8; i++)
#pragma unroll
            for (int jj = 0; jj < 4; jj++) s[i][jj] = 0.f;

#pragma unroll
        for (int ks = 0; ks < 4; ks++) {
            uint32_t qh[4], ql[4];
            ldsm4(qh, sQh + qa_base + ks * 32);
            ldsm4(ql, sQl + qa_base + ks * 32);
#pragma unroll
            for (int ng = 0; ng < 4; ng++) {
                uint32_t kk[4];
                uint32_t ko = kb_base + ng * (16 * AT_STRIDE) + ks * 32;
                ldsm4(kk, st + 0 * KV_ARR_B + ko);
                mma16816h(s[2 * ng],     qh, &kk[0]);
                mma16816h(s[2 * ng],     ql, &kk[0]);
                mma16816h(s[2 * ng + 1], qh, &kk[2]);
                mma16816h(s[2 * ng + 1], ql, &kk[2]);
            }
        }

        // ---- causal mask (diagonal-region tiles only) ----
        if (j >= 2 * qi) {
            int r0 = q0 + w * 16 + (lane >> 2);
            int cb = j * 64 + (lane & 3) * 2;
#pragma unroll
            for (int nt = 0; nt < 8; nt++)
#pragma unroll
                for (int cc = 0; cc < 2; cc++) {
                    int col = cb + nt * 8 + cc;
                    if (col > r0)     s[nt][cc]     = -1e30f;
                    if (col > r0 + 8) s[nt][2 + cc] = -1e30f;
                }
        }

        // ---- online softmax (base-2; scale folded into Q) ----
        float mx0 = -1e30f, mx1 = -1e30f;
#pragma unroll
        for (int nt = 0; nt < 8; nt++) {
            mx0 = fmaxf(mx0, fmaxf(s[nt][0], s[nt][1]));
            mx1 = fmaxf(mx1, fmaxf(s[nt][2], s[nt][3]));
        }
        mx0 = fmaxf(mx0, __shfl_xor_sync(0xffffffffu, mx0, 1));
        mx0 = fmaxf(mx0, __shfl_xor_sync(0xffffffffu, mx0, 2));
        mx1 = fmaxf(mx1, __shfl_xor_sync(0xffffffffu, mx1, 1));
        mx1 = fmaxf(mx1, __shfl_xor_sync(0xffffffffu, mx1, 2));
        float mn0 = fmaxf(m0, mx0), mn1 = fmaxf(m1, mx1);
        float a0 = ex2(m0 - mn0), a1 = ex2(m1 - mn1);
        float sm0 = 0.f, sm1 = 0.f;
#pragma unroll
        for (int nt = 0; nt < 8; nt++) {
            s[nt][0] = ex2(s[nt][0] - mn0); sm0 += s[nt][0];
            s[nt][1] = ex2(s[nt][1] - mn0); sm0 += s[nt][1];
            s[nt][2] = ex2(s[nt][2] - mn1); sm1 += s[nt][2];
            s[nt][3] = ex2(s[nt][3] - mn1); sm1 += s[nt][3];
        }
        sm0 += __shfl_xor_sync(0xffffffffu, sm0, 1);
        sm0 += __shfl_xor_sync(0xffffffffu, sm0, 2);
        sm1 += __shfl_xor_sync(0xffffffffu, sm1, 1);
        sm1 += __shfl_xor_sync(0xffffffffu, sm1, 2);
        l0 = l0 * a0 + sm0; l1 = l1 * a1 + sm1;
        m0 = mn0; m1 = mn1;
#pragma unroll
        for (int nt = 0; nt < 8; nt++) {
            O[nt][0] *= a0; O[nt][1] *= a0;
            O[nt][2] *= a1; O[nt][3] *= a1;
        }

        // ---- O += P @ V (fp16x2: P exact pair in regs, V single in smem) ----
#pragma unroll
        for (int ks = 0; ks < 4; ks++) {
            uint32_t ph[4], pl[4];
            {
                __half2 t;
                t = __floats2half2_rn(s[2 * ks][0], s[2 * ks][1]);
                ph[0] = h2u(t);
                pl[0] = h2u(__floats2half2_rn(s[2 * ks][0] - __low2float(t),
                                              s[2 * ks][1] - __high2float(t)));
                t = __floats2half2_rn(s[2 * ks][2], s[2 * ks][3]);
                ph[1] = h2u(t);
                pl[1] = h2u(__floats2half2_rn(s[2 * ks][2] - __low2float(t),
                                              s[2 * ks][3] - __high2float(t)));
                t = __floats2half2_rn(s[2 * ks + 1][0], s[2 * ks + 1][1]);
                ph[2] = h2u(t);
                pl[2] = h2u(__floats2half2_rn(s[2 * ks + 1][0] - __low2float(t),
                                              s[2 * ks + 1][1] - __high2float(t)));
                t = __floats2half2_rn(s[2 * ks + 1][2], s[2 * ks + 1][3]);
                ph[3] = h2u(t);
                pl[3] = h2u(__floats2half2_rn(s[2 * ks + 1][2] - __low2float(t),
                                              s[2 * ks + 1][3] - __high2float(t)));
            }
#pragma unroll
            for (int ng = 0; ng < 4; ng++) {
                uint32_t vh[4];
                uint32_t vo = vb_base + ks * (16 * AT_STRIDE) + ng * 32;
                ldsm4t(vh, st + 1 * KV_ARR_B + vo);
                mma16816h(O[2 * ng],     ph, &vh[0]);
                mma16816h(O[2 * ng],     pl, &vh[0]);
                mma16816h(O[2 * ng + 1], ph, &vh[2]);
                mma16816h(O[2 * ng + 1], pl, &vh[2]);
            }
        }
        __syncthreads();
    }

    // ---- epilogue: normalize + single fp16 for the output projection ----
    float inv0 = 1.0f / l0, inv1 = 1.0f / l1;
    int r0 = q0 + w * 16 + (lane >> 2);
    size_t rb0 = ((size_t)b * SEQ + r0) * DM + h * 64;
    size_t rb1 = rb0 + (size_t)8 * DM;
#pragma unroll
    for (int nt = 0; nt < 8; nt++) {
        int c0 = nt * 8 + (lane & 3) * 2;
        *(__half2*)&g_Afh[rb0 + c0] =
            __floats2half2_rn(O[nt][0] * inv0, O[nt][1] * inv0);
        *(__half2*)&g_Afh[rb1 + c0] =
            __floats2half2_rn(O[nt][2] * inv1, O[nt][3] * inv1);
    }
}

// ---------------------------------------------------------------------------
extern "C" void kernel_launch(void* const* d_in, const int* in_sizes, int n_in,
                              void* d_out, int out_size)
{
    const float* x  = (const float*)d_in[0];
    const float* Wq = (const float*)d_in[1];
    const float* Wk = (const float*)d_in[2];
    const float* Wv = (const float*)d_in[3];
    const float* Wo = (const float*)d_in[4];
    float* out = (float*)d_out;

    cudaFuncSetAttribute(gemm_q,     cudaFuncAttributeMaxDynamicSharedMemorySize, GEMM_SMEM);
    cudaFuncSetAttribute(gemm_sp<0>, cudaFuncAttributeMaxDynamicSharedMemorySize, KV_SMEM);
    cudaFuncSetAttribute(gemm_sp<1>, cudaFuncAttributeMaxDynamicSharedMemorySize, KV_SMEM);
    cudaFuncSetAttribute(attn_mma,   cudaFuncAttributeMaxDynamicSharedMemorySize, ATT_SMEM);

    split_x_kernel<<<8192, 256>>>(x);
    tsplit_qkv_kernel<<<dim3(2, 32, 48), dim3(32, 8)>>>(Wq, Wk, Wv);
    tsplit_kernel<<<dim3(32, 32, 1), dim3(32, 8)>>>(Wo, 3, 1024, 1024);

    gemm_sp<0><<<dim3(64, 8, 2), 256, KV_SMEM>>>(nullptr);
    gemm_q<<<dim3(64, 4, 1), 256, GEMM_SMEM>>>();
    attn_mma<<<dim3(SEQ / 128, BATCH * NH), 256, ATT_SMEM>>>();
    gemm_sp<1><<<dim3(64, 8, 1), 256, KV_SMEM>>>(out);
}

// round 15
// speedup vs baseline: 5.6244x; 1.1141x over previous
#include <cuda_runtime.h>
#include <cuda_bf16.h>
#include <cuda_fp16.h>
#include <math.h>
#include <stdint.h>
#include <string.h>

#define BATCH 4
#define SEQ   2048
#define DIN   1024
#define NH    16
#define DKH   64
#define DM    1024
#define QKV_ELE ((size_t)BATCH*NH*SEQ*DKH)   // 8388608
#define QSCALE 0.18033688011112042f          // 0.125 * log2(e): softmax in base 2

// ---------------- scratch globals (no allocation allowed) -------------------
__device__ __align__(128) __half g_xfh[(size_t)BATCH*SEQ*DIN];   // x fp16
__device__ __align__(128) __half g_wf[(size_t)4<<20];            // Wq,Wk,Wv,Wo^T fp16
__device__ __align__(128) __half g_qkvh[3*QKV_ELE];              // Q hi | K | V
__device__ __align__(128) __half g_qkvl[QKV_ELE];                // Q lo only
__device__ __align__(128) __half g_Afh[(size_t)BATCH*SEQ*DM];    // attn out fp16

// ---------------- PTX helpers (sm_100 baseline: ldmatrix / mma.sync) --------
__device__ __forceinline__ uint32_t smem_u32(const void* p) {
    uint32_t a;
    asm("{ .reg .u64 t; cvta.to.shared.u64 t, %1; cvt.u32.u64 %0, t; }" : "=r"(a) : "l"(p));
    return a;
}
__device__ __forceinline__ void ldsm4(uint32_t* f, uint32_t addr) {
    asm volatile("ldmatrix.sync.aligned.m8n8.x4.shared.b16 {%0,%1,%2,%3}, [%4];"
                 : "=r"(f[0]), "=r"(f[1]), "=r"(f[2]), "=r"(f[3]) : "r"(addr));
}
__device__ __forceinline__ void ldsm4t(uint32_t* f, uint32_t addr) {
    asm volatile("ldmatrix.sync.aligned.m8n8.x4.trans.shared.b16 {%0,%1,%2,%3}, [%4];"
                 : "=r"(f[0]), "=r"(f[1]), "=r"(f[2]), "=r"(f[3]) : "r"(addr));
}
__device__ __forceinline__ void mma16816h(float* c, const uint32_t* a, const uint32_t* b) {
    asm volatile(
        "mma.sync.aligned.m16n8k16.row.col.f32.f16.f16.f32 "
        "{%0,%1,%2,%3}, {%4,%5,%6,%7}, {%8,%9}, {%0,%1,%2,%3};"
        : "+f"(c[0]), "+f"(c[1]), "+f"(c[2]), "+f"(c[3])
        : "r"(a[0]), "r"(a[1]), "r"(a[2]), "r"(a[3]), "r"(b[0]), "r"(b[1]));
}
__device__ __forceinline__ void cp16(uint32_t dst, const void* src) {
    asm volatile("cp.async.cg.shared.global [%0], [%1], 16;" :: "r"(dst), "l"(src));
}
__device__ __forceinline__ float ex2(float x) {
    float y; asm("ex2.approx.ftz.f32 %0, %1;" : "=f"(y) : "f"(x)); return y;
}
__device__ __forceinline__ uint32_t h2u(__half2 v) {
    uint32_t u; memcpy(&u, &v, 4); return u;
}

// ---------------- prep: fp32 -> fp16 for x ----------------------------------
__global__ void split_x_kernel(const float* __restrict__ x) {
    size_t i0 = ((size_t)blockIdx.x * 256 + threadIdx.x) * 4;
    float4 v = *(const float4*)(x + i0);
    __half h[4] = { __float2half_rn(v.x), __float2half_rn(v.y),
                    __float2half_rn(v.z), __float2half_rn(v.w) };
    *(uint2*)(g_xfh + i0) = *(uint2*)h;
}

// transpose [R][C] -> [C][R] to fp16 into g_wf[which] (generic, used for Wo)
__global__ void tsplit_kernel(const float* __restrict__ in, int which, int R, int C) {
    __shared__ float t[32][33];
    const int z = blockIdx.z;
    const int c0 = blockIdx.x * 32, r0 = blockIdx.y * 32;
    const int tx = threadIdx.x, ty = threadIdx.y;
    const float* inp = in + (size_t)z * R * C;
#pragma unroll
    for (int k = 0; k < 4; k++)
        t[ty + 8 * k][tx] = inp[(size_t)(r0 + ty + 8 * k) * C + c0 + tx];
    __syncthreads();
    __half* oh = g_wf + ((size_t)which << 20) + (size_t)z * R * C;
#pragma unroll
    for (int k = 0; k < 4; k++)
        oh[(size_t)(c0 + ty + 8 * k) * R + r0 + tx] = __float2half_rn(t[tx][ty + 8 * k]);
}

// fused Wq/Wk/Wv transpose: grid (2, 32, 48), z>>4 selects matrix
__global__ void tsplit_qkv_kernel(const float* __restrict__ Wq,
                                  const float* __restrict__ Wk,
                                  const float* __restrict__ Wv) {
    __shared__ float t[32][33];
    const int sel = blockIdx.z >> 4, z = blockIdx.z & 15;
    const int R = 1024, C = 64;
    const int c0 = blockIdx.x * 32, r0 = blockIdx.y * 32;
    const int tx = threadIdx.x, ty = threadIdx.y;
    const float* inp = (sel == 0 ? Wq : sel == 1 ? Wk : Wv) + (size_t)z * R * C;
#pragma unroll
    for (int k = 0; k < 4; k++)
        t[ty + 8 * k][tx] = inp[(size_t)(r0 + ty + 8 * k) * C + c0 + tx];
    __syncthreads();
    __half* oh = g_wf + ((size_t)sel << 20) + (size_t)z * R * C;
#pragma unroll
    for (int k = 0; k < 4; k++)
        oh[(size_t)(c0 + ty + 8 * k) * R + r0 + tx] = __float2half_rn(t[tx][ty + 8 * k]);
}

// ---------------- single-pass GEMM, occ 2 (QKV and output projection) -------
// Block 128(M) x 128(N), 8 warps (2M x 4N), warp tile 64x32, k-chunk 32,
// 3-stage ring at 20.5 KB/stage -> 2 CTAs/SM.
// PROJ=0: grid (64,8,3): z=0 -> Q (pair out, QSCALE), z=1 -> K, z=2 -> V.
// PROJ=1: grid (64,8,1): A = attn out fp16, B = Wo^T, out fp32 (d_out).
#define KC 32
#define KV_A_TILE 10240
#define KV_STG    (2 * KV_A_TILE)            // 20480: A | B
#define KV_SMEM   (3 * KV_STG)               // 61440

__device__ __forceinline__ void copy_chunk_sp(int tid, uint32_t stg, int kc,
    int m0, int n0, const __half* A, const __half* B)
{
    const int ko = kc * 32;
#pragma unroll
    for (int i = 0; i < 4; i++) {
        int t = tid + i * 256;
        const __half* src; uint32_t dst;
        if (t < 512) {         // A: 128 rows x 4 x 16B
            int r = t >> 2, c = t & 3;
            src = A + (size_t)(m0 + r) * 1024 + ko + c * 8;
            dst = stg + r * 80 + c * 16;
        } else {               // B: 128 rows x 4 x 16B
            int u = t - 512, r = u >> 2, c = u & 3;
            src = B + (size_t)(n0 + r) * 1024 + ko + c * 8;
            dst = stg + KV_A_TILE + r * 80 + c * 16;
        }
        cp16(dst, src);
    }
    asm volatile("cp.async.commit_group;" ::: "memory");
}

template<int PROJ>
__global__ __launch_bounds__(256, 2) void gemm_sp(float* __restrict__ outp_)
{
    extern __shared__ __align__(128) char dsm[];
    const uint32_t sb = smem_u32(dsm);
    const int tid = threadIdx.x, wid = tid >> 5, lane = tid & 31;
    const int warp_m = wid >> 2, warp_n = wid & 3;
    const int m0 = blockIdx.x * 128, n0 = blockIdx.y * 128;
    const int z = blockIdx.z;            // PROJ=0: 0=Q, 1=K, 2=V

    const __half* A = PROJ ? g_Afh : g_xfh;
    const __half* B = g_wf + ((size_t)(PROJ ? 3 : z) << 20);

    const uint32_t a_off = (uint32_t)(warp_m * 64 + (lane & 15)) * 80 + (lane >> 4) * 16;
    const uint32_t b_off = (uint32_t)(warp_n * 32 + (lane >> 4) * 8 + (lane & 7)) * 80
                         + ((lane >> 3) & 1) * 16;

    float acc[4][4][4];
#pragma unroll
    for (int i = 0; i < 4; i++)
#pragma unroll
        for (int j = 0; j < 4; j++)
#pragma unroll
            for (int k = 0; k < 4; k++) acc[i][j][k] = 0.f;

    copy_chunk_sp(tid, sb, 0, m0, n0, A, B);
    copy_chunk_sp(tid, sb + KV_STG, 1, m0, n0, A, B);

    for (int kc = 0; kc < KC; kc++) {
        if (kc + 1 < KC) {
            asm volatile("cp.async.wait_group 1;" ::: "memory");
        } else {
            asm volatile("cp.async.wait_group 0;" ::: "memory");
        }
        __syncthreads();
        if (kc + 2 < KC)
            copy_chunk_sp(tid, sb + (uint32_t)((kc + 2) % 3) * KV_STG, kc + 2,
                          m0, n0, A, B);

        const uint32_t stg = sb + (uint32_t)(kc % 3) * KV_STG;
        const uint32_t sB = stg + KV_A_TILE;
#pragma unroll
        for (int ks = 0; ks < 2; ks++) {
            uint32_t ah[4][4], bb[2][4];
#pragma unroll
            for (int mt = 0; mt < 4; mt++)
                ldsm4(ah[mt], stg + a_off + mt * (16 * 80) + ks * 32);
#pragma unroll
            for (int pr = 0; pr < 2; pr++)
                ldsm4(bb[pr], sB + b_off + pr * (16 * 80) + ks * 32);
#pragma unroll
            for (int mt = 0; mt < 4; mt++)
#pragma unroll
                for (int nt = 0; nt < 4; nt++)
                    mma16816h(acc[mt][nt], ah[mt], &bb[nt >> 1][(nt & 1) * 2]);
        }
        __syncthreads();
    }

    const int tg = lane >> 2, tq = lane & 3;
#pragma unroll
    for (int mt = 0; mt < 4; mt++) {
#pragma unroll
        for (int nt = 0; nt < 4; nt++) {
            int row = m0 + warp_m * 64 + mt * 16 + tg;
            int col = n0 + warp_n * 32 + nt * 8 + tq * 2;
            if (PROJ) {
                float* dst0 = outp_ + (size_t)row * DM + col;
                float* dst1 = outp_ + (size_t)(row + 8) * DM + col;
                *(float2*)dst0 = make_float2(acc[mt][nt][0], acc[mt][nt][1]);
                *(float2*)dst1 = make_float2(acc[mt][nt][2], acc[mt][nt][3]);
            } else {
                int bb_ = row >> 11, ss = row & 2047, hh = col >> 6, dk = col & 63;
                size_t base = (size_t)z * QKV_ELE
                            + (((size_t)(bb_ * NH + hh)) * SEQ + ss) * DKH + dk;
                if (z == 0) {   // Q: pre-scale + exact hi/lo pair for attention
                    float v0 = acc[mt][nt][0] * QSCALE, v1 = acc[mt][nt][1] * QSCALE;
                    float v2 = acc[mt][nt][2] * QSCALE, v3 = acc[mt][nt][3] * QSCALE;
                    __half2 h0 = __floats2half2_rn(v0, v1);
                    __half2 h1 = __floats2half2_rn(v2, v3);
                    *(__half2*)&g_qkvh[base]           = h0;
                    *(__half2*)&g_qkvh[base + 8 * DKH] = h1;
                    *(__half2*)&g_qkvl[base] =
                        __floats2half2_rn(v0 - __low2float(h0), v1 - __high2float(h0));
                    *(__half2*)&g_qkvl[base + 8 * DKH] =
                        __floats2half2_rn(v2 - __low2float(h1), v3 - __high2float(h1));
                } else {        // K, V: single fp16
                    *(__half2*)&g_qkvh[base] =
                        __floats2half2_rn(acc[mt][nt][0], acc[mt][nt][1]);
                    *(__half2*)&g_qkvh[base + 8 * DKH] =
                        __floats2half2_rn(acc[mt][nt][2], acc[mt][nt][3]);
                }
            }
        }
    }
}

// ---------------- causal flash attention on HMMA ----------------------------
// BM=128 (8 warps x 16 rows), BN=64, d=64.
// QK^T: fp16x2 (Q exact pair x K single). PV: fp16x2 (P exact pair x V single).
#define AT_STRIDE 144
#define Q_TILE_B   (128 * AT_STRIDE)        // 18432
#define KV_ARR_B   (64 * AT_STRIDE)         // 9216
#define KV_STAGE_B (2 * KV_ARR_B)           // 18432: K | V
#define ATT_SMEM   (2 * Q_TILE_B + 2 * KV_STAGE_B)   // 73728 -> 2 CTAs/SM

__device__ __forceinline__ void load_kv(int tid, uint32_t stg, int j,
    const __half* Kg, const __half* Vg)
{
#pragma unroll
    for (int it = 0; it < 4; it++) {
        int i = tid + it * 256;
        int arr = i >> 9, r = (i >> 3) & 63, c = i & 7;
        const __half* src = (arr == 0 ? Kg : Vg)
                          + ((size_t)(j * 64 + r)) * DKH + c * 8;
        cp16(stg + arr * KV_ARR_B + r * AT_STRIDE + c * 16, src);
    }
    asm volatile("cp.async.commit_group;" ::: "memory");
}

__global__ __launch_bounds__(256, 2) void attn_mma()
{
    extern __shared__ __align__(128) char dsm[];
    const uint32_t sb = smem_u32(dsm);
    const uint32_t sQh = sb, sQl = sb + Q_TILE_B;
    const uint32_t sKV = sb + 2 * Q_TILE_B;

    const int qi = (int)gridDim.x - 1 - (int)blockIdx.x;   // heavy tiles first
    const int q0 = qi * 128;
    const int bh = blockIdx.y;
    const int b = bh >> 4, h = bh & 15;
    const int tid = threadIdx.x, w = tid >> 5, lane = tid & 31;

    const __half* Qhg = g_qkvh + ((size_t)bh * SEQ + q0) * DKH;
    const __half* Qlg = g_qkvl + ((size_t)bh * SEQ + q0) * DKH;
    const __half* Kg  = g_qkvh + QKV_ELE     + (size_t)bh * SEQ * DKH;
    const __half* Vg  = g_qkvh + 2 * QKV_ELE + (size_t)bh * SEQ * DKH;

    // Q (hi+lo) -> smem, group 0
#pragma unroll
    for (int it = 0; it < 8; it++) {
        int i = tid + it * 256;
        int half_ = i >> 10, r = (i >> 3) & 127, c = i & 7;
        const __half* src = (half_ ? Qlg : Qhg) + (size_t)r * DKH + c * 8;
        cp16((half_ ? sQl : sQh) + r * AT_STRIDE + c * 16, src);
    }
    asm volatile("cp.async.commit_group;" ::: "memory");

    load_kv(tid, sKV, 0, Kg, Vg);

    float O[8][4];
#pragma unroll
    for (int i = 0; i < 8; i++)
#pragma unroll
        for (int j = 0; j < 4; j++) O[i][j] = 0.f;
    float m0 = -1e30f, m1 = -1e30f, l0 = 0.f, l1 = 0.f;

    const uint32_t qa_base = (uint32_t)(w * 16 + (lane & 15)) * AT_STRIDE + (lane >> 4) * 16;
    const uint32_t kb_base = (uint32_t)((lane & 7) + ((lane >> 4) & 1) * 8) * AT_STRIDE
                           + ((lane >> 3) & 1) * 16;
    const uint32_t vb_base = (uint32_t)(lane & 15) * AT_STRIDE + (lane >> 4) * 16;

    const int njt = 2 * qi + 2;
    for (int j = 0; j < njt; j++) {
        const uint32_t st = sKV + (uint32_t)(j & 1) * KV_STAGE_B;
        if (j + 1 < njt) {
            load_kv(tid, sKV + (uint32_t)((j + 1) & 1) * KV_STAGE_B, j + 1, Kg, Vg);
            asm volatile("cp.async.wait_group 1;" ::: "memory");
        } else {
            asm volatile("cp.async.wait_group 0;" ::: "memory");
        }
        __syncthreads();

        // ---- S = Qs @ K^T (fp16x2: qh*k + ql*k, Q exact pair) ----
        float s[8][4];
#pragma unroll
        for (int i = 0; i < 8; i++)
#pragma unroll
            for (int jj = 0; jj < 4; jj++) s[i][jj] = 0.f;

#pragma unroll
        for (int ks = 0; ks < 4; ks++) {
            uint32_t qh[4], ql[4];
            ldsm4(qh, sQh + qa_base + ks * 32);
            ldsm4(ql, sQl + qa_base + ks * 32);
#pragma unroll
            for (int ng = 0; ng < 4; ng++) {
                uint32_t kk[4];
                uint32_t ko = kb_base + ng * (16 * AT_STRIDE) + ks * 32;
                ldsm4(kk, st + 0 * KV_ARR_B + ko);
                mma16816h(s[2 * ng],     qh, &kk[0]);
                mma16816h(s[2 * ng],     ql, &kk[0]);
                mma16816h(s[2 * ng + 1], qh, &kk[2]);
                mma16816h(s[2 * ng + 1], ql, &kk[2]);
            }
        }

        // ---- causal mask (diagonal-region tiles only) ----
        if (j >= 2 * qi) {
            int r0 = q0 + w * 16 + (lane >> 2);
            int cb = j * 64 + (lane & 3) * 2;
#pragma unroll
            for (int nt = 0; nt < 8; nt++)
#pragma unroll
                for (int cc = 0; cc < 2; cc++) {
                    int col = cb + nt * 8 + cc;
                    if (col > r0)     s[nt][cc]     = -1e30f;
                    if (col > r0 + 8) s[nt][2 + cc] = -1e30f;
                }
        }

        // ---- online softmax (base-2; scale folded into Q) ----
        float mx0 = -1e30f, mx1 = -1e30f;
#pragma unroll
        for (int nt = 0; nt < 8; nt++) {
            mx0 = fmaxf(mx0, fmaxf(s[nt][0], s[nt][1]));
            mx1 = fmaxf(mx1, fmaxf(s[nt][2], s[nt][3]));
        }
        mx0 = fmaxf(mx0, __shfl_xor_sync(0xffffffffu, mx0, 1));
        mx0 = fmaxf(mx0, __shfl_xor_sync(0xffffffffu, mx0, 2));
        mx1 = fmaxf(mx1, __shfl_xor_sync(0xffffffffu, mx1, 1));
        mx1 = fmaxf(mx1, __shfl_xor_sync(0xffffffffu, mx1, 2));
        float mn0 = fmaxf(m0, mx0), mn1 = fmaxf(m1, mx1);
        float a0 = ex2(m0 - mn0), a1 = ex2(m1 - mn1);
        float sm0 = 0.f, sm1 = 0.f;
#pragma unroll
        for (int nt = 0; nt < 8; nt++) {
            s[nt][0] = ex2(s[nt][0] - mn0); sm0 += s[nt][0];
            s[nt][1] = ex2(s[nt][1] - mn0); sm0 += s[nt][1];
            s[nt][2] = ex2(s[nt][2] - mn1); sm1 += s[nt][2];
            s[nt][3] = ex2(s[nt][3] - mn1); sm1 += s[nt][3];
        }
        sm0 += __shfl_xor_sync(0xffffffffu, sm0, 1);
        sm0 += __shfl_xor_sync(0xffffffffu, sm0, 2);
        sm1 += __shfl_xor_sync(0xffffffffu, sm1, 1);
        sm1 += __shfl_xor_sync(0xffffffffu, sm1, 2);
        l0 = l0 * a0 + sm0; l1 = l1 * a1 + sm1;
        m0 = mn0; m1 = mn1;
#pragma unroll
        for (int nt = 0; nt < 8; nt++) {
            O[nt][0] *= a0; O[nt][1] *= a0;
            O[nt][2] *= a1; O[nt][3] *= a1;
        }

        // ---- O += P @ V (fp16x2: P exact pair in regs, V single in smem) ----
#pragma unroll
        for (int ks = 0; ks < 4; ks++) {
            uint32_t ph[4], pl[4];
            {
                __half2 t;
                t = __floats2half2_rn(s[2 * ks][0], s[2 * ks][1]);
                ph[0] = h2u(t);
                pl[0] = h2u(__floats2half2_rn(s[2 * ks][0] - __low2float(t),
                                              s[2 * ks][1] - __high2float(t)));
                t = __floats2half2_rn(s[2 * ks][2], s[2 * ks][3]);
                ph[1] = h2u(t);
                pl[1] = h2u(__floats2half2_rn(s[2 * ks][2] - __low2float(t),
                                              s[2 * ks][3] - __high2float(t)));
                t = __floats2half2_rn(s[2 * ks + 1][0], s[2 * ks + 1][1]);
                ph[2] = h2u(t);
                pl[2] = h2u(__floats2half2_rn(s[2 * ks + 1][0] - __low2float(t),
                                              s[2 * ks + 1][1] - __high2float(t)));
                t = __floats2half2_rn(s[2 * ks + 1][2], s[2 * ks + 1][3]);
                ph[3] = h2u(t);
                pl[3] = h2u(__floats2half2_rn(s[2 * ks + 1][2] - __low2float(t),
                                              s[2 * ks + 1][3] - __high2float(t)));
            }
#pragma unroll
            for (int ng = 0; ng < 4; ng++) {
                uint32_t vh[4];
                uint32_t vo = vb_base + ks * (16 * AT_STRIDE) + ng * 32;
                ldsm4t(vh, st + 1 * KV_ARR_B + vo);
                mma16816h(O[2 * ng],     ph, &vh[0]);
                mma16816h(O[2 * ng],     pl, &vh[0]);
                mma16816h(O[2 * ng + 1], ph, &vh[2]);
                mma16816h(O[2 * ng + 1], pl, &vh[2]);
            }
        }
        __syncthreads();
    }

    // ---- epilogue: normalize + single fp16 for the output projection ----
    float inv0 = 1.0f / l0, inv1 = 1.0f / l1;
    int r0 = q0 + w * 16 + (lane >> 2);
    size_t rb0 = ((size_t)b * SEQ + r0) * DM + h * 64;
    size_t rb1 = rb0 + (size_t)8 * DM;
#pragma unroll
    for (int nt = 0; nt < 8; nt++) {
        int c0 = nt * 8 + (lane & 3) * 2;
        *(__half2*)&g_Afh[rb0 + c0] =
            __floats2half2_rn(O[nt][0] * inv0, O[nt][1] * inv0);
        *(__half2*)&g_Afh[rb1 + c0] =
            __floats2half2_rn(O[nt][2] * inv1, O[nt][3] * inv1);
    }
}

// ---------------------------------------------------------------------------
extern "C" void kernel_launch(void* const* d_in, const int* in_sizes, int n_in,
                              void* d_out, int out_size)
{
    const float* x  = (const float*)d_in[0];
    const float* Wq = (const float*)d_in[1];
    const float* Wk = (const float*)d_in[2];
    const float* Wv = (const float*)d_in[3];
    const float* Wo = (const float*)d_in[4];
    float* out = (float*)d_out;

    cudaFuncSetAttribute(gemm_sp<0>, cudaFuncAttributeMaxDynamicSharedMemorySize, KV_SMEM);
    cudaFuncSetAttribute(gemm_sp<1>, cudaFuncAttributeMaxDynamicSharedMemorySize, KV_SMEM);
    cudaFuncSetAttribute(attn_mma,   cudaFuncAttributeMaxDynamicSharedMemorySize, ATT_SMEM);

    split_x_kernel<<<8192, 256>>>(x);
    tsplit_qkv_kernel<<<dim3(2, 32, 48), dim3(32, 8)>>>(Wq, Wk, Wv);
    tsplit_kernel<<<dim3(32, 32, 1), dim3(32, 8)>>>(Wo, 3, 1024, 1024);

    gemm_sp<0><<<dim3(64, 8, 3), 256, KV_SMEM>>>(nullptr);
    attn_mma<<<dim3(SEQ / 128, BATCH * NH), 256, ATT_SMEM>>>();
    gemm_sp<1><<<dim3(64, 8, 1), 256, KV_SMEM>>>(out);
}

// round 17
// speedup vs baseline: 6.6061x; 1.1745x over previous
#include <cuda_runtime.h>
#include <cuda_bf16.h>
#include <cuda_fp16.h>
#include <math.h>
#include <stdint.h>
#include <string.h>

#define BATCH 4
#define SEQ   2048
#define DIN   1024
#define NH    16
#define DKH   64
#define DM    1024
#define QKV_ELE ((size_t)BATCH*NH*SEQ*DKH)   // 8388608
#define QSCALE 0.18033688011112042f          // 0.125 * log2(e): softmax in base 2

// ---------------- scratch globals (no allocation allowed) -------------------
__device__ __align__(128) __half g_xfh[(size_t)BATCH*SEQ*DIN];   // x fp16
__device__ __align__(128) __half g_wf[(size_t)4<<20];            // Wq,Wk,Wv,Wo^T fp16
__device__ __align__(128) __half g_qkvh[3*QKV_ELE];              // Q | K | V fp16
__device__ __align__(128) __half g_Afh[(size_t)BATCH*SEQ*DM];    // attn out fp16

// ---------------- PTX helpers (sm_100 baseline: ldmatrix / mma.sync) --------
__device__ __forceinline__ uint32_t smem_u32(const void* p) {
    uint32_t a;
    asm("{ .reg .u64 t; cvta.to.shared.u64 t, %1; cvt.u32.u64 %0, t; }" : "=r"(a) : "l"(p));
    return a;
}
__device__ __forceinline__ void ldsm4(uint32_t* f, uint32_t addr) {
    asm volatile("ldmatrix.sync.aligned.m8n8.x4.shared.b16 {%0,%1,%2,%3}, [%4];"
                 : "=r"(f[0]), "=r"(f[1]), "=r"(f[2]), "=r"(f[3]) : "r"(addr));
}
__device__ __forceinline__ void ldsm4t(uint32_t* f, uint32_t addr) {
    asm volatile("ldmatrix.sync.aligned.m8n8.x4.trans.shared.b16 {%0,%1,%2,%3}, [%4];"
                 : "=r"(f[0]), "=r"(f[1]), "=r"(f[2]), "=r"(f[3]) : "r"(addr));
}
__device__ __forceinline__ void mma16816h(float* c, const uint32_t* a, const uint32_t* b) {
    asm volatile(
        "mma.sync.aligned.m16n8k16.row.col.f32.f16.f16.f32 "
        "{%0,%1,%2,%3}, {%4,%5,%6,%7}, {%8,%9}, {%0,%1,%2,%3};"
        : "+f"(c[0]), "+f"(c[1]), "+f"(c[2]), "+f"(c[3])
        : "r"(a[0]), "r"(a[1]), "r"(a[2]), "r"(a[3]), "r"(b[0]), "r"(b[1]));
}
__device__ __forceinline__ void cp16(uint32_t dst, const void* src) {
    asm volatile("cp.async.cg.shared.global [%0], [%1], 16;" :: "r"(dst), "l"(src));
}
__device__ __forceinline__ float ex2(float x) {
    float y; asm("ex2.approx.ftz.f32 %0, %1;" : "=f"(y) : "f"(x)); return y;
}
__device__ __forceinline__ uint32_t h2u(__half2 v) {
    uint32_t u; memcpy(&u, &v, 4); return u;
}

// ---------------- prep: fp32 -> fp16 for x ----------------------------------
__global__ void split_x_kernel(const float* __restrict__ x) {
    size_t i0 = ((size_t)blockIdx.x * 256 + threadIdx.x) * 4;
    float4 v = *(const float4*)(x + i0);
    __half h[4] = { __float2half_rn(v.x), __float2half_rn(v.y),
                    __float2half_rn(v.z), __float2half_rn(v.w) };
    *(uint2*)(g_xfh + i0) = *(uint2*)h;
}

// transpose [R][C] -> [C][R] to fp16 into g_wf[which] (generic, used for Wo)
__global__ void tsplit_kernel(const float* __restrict__ in, int which, int R, int C) {
    __shared__ float t[32][33];
    const int z = blockIdx.z;
    const int c0 = blockIdx.x * 32, r0 = blockIdx.y * 32;
    const int tx = threadIdx.x, ty = threadIdx.y;
    const float* inp = in + (size_t)z * R * C;
#pragma unroll
    for (int k = 0; k < 4; k++)
        t[ty + 8 * k][tx] = inp[(size_t)(r0 + ty + 8 * k) * C + c0 + tx];
    __syncthreads();
    __half* oh = g_wf + ((size_t)which << 20) + (size_t)z * R * C;
#pragma unroll
    for (int k = 0; k < 4; k++)
        oh[(size_t)(c0 + ty + 8 * k) * R + r0 + tx] = __float2half_rn(t[tx][ty + 8 * k]);
}

// fused Wq/Wk/Wv transpose: grid (2, 32, 48), z>>4 selects matrix
__global__ void tsplit_qkv_kernel(const float* __restrict__ Wq,
                                  const float* __restrict__ Wk,
                                  const float* __restrict__ Wv) {
    __shared__ float t[32][33];
    const int sel = blockIdx.z >> 4, z = blockIdx.z & 15;
    const int R = 1024, C = 64;
    const int c0 = blockIdx.x * 32, r0 = blockIdx.y * 32;
    const int tx = threadIdx.x, ty = threadIdx.y;
    const float* inp = (sel == 0 ? Wq : sel == 1 ? Wk : Wv) + (size_t)z * R * C;
#pragma unroll
    for (int k = 0; k < 4; k++)
        t[ty + 8 * k][tx] = inp[(size_t)(r0 + ty + 8 * k) * C + c0 + tx];
    __syncthreads();
    __half* oh = g_wf + ((size_t)sel << 20) + (size_t)z * R * C;
#pragma unroll
    for (int k = 0; k < 4; k++)
        oh[(size_t)(c0 + ty + 8 * k) * R + r0 + tx] = __float2half_rn(t[tx][ty + 8 * k]);
}

// ---------------- single-pass GEMM, occ 2 (QKV and output projection) -------
// Block 128(M) x 128(N), 8 warps (2M x 4N), warp tile 64x32, k-chunk 64,
// 3-stage cp.async ring at 36.9 KB/stage -> 2 CTAs/SM (221 KB).
// Row stride 144 B (128 B data + 16 pad; odd 16B-stride -> ldsm conflict-free).
// PROJ=0: grid (64,8,3): z=0 -> Q (QSCALE), z=1 -> K, z=2 -> V; out fp16.
// PROJ=1: grid (64,8,1): A = attn out fp16, B = Wo^T, out fp32 (d_out).
#define KC 16
#define SP_STRIDE 144
#define SP_TILE  (128 * SP_STRIDE)           // 18432
#define SP_STG   (2 * SP_TILE)               // 36864: A | B
#define SP_SMEM  (3 * SP_STG)                // 110592

__device__ __forceinline__ void copy_chunk_sp(int tid, uint32_t stg, int kc,
    int m0, int n0, const __half* A, const __half* B)
{
    const int ko = kc * 64;
#pragma unroll
    for (int i = 0; i < 8; i++) {
        int t = tid + i * 256;
        const __half* src; uint32_t dst;
        if (t < 1024) {        // A: 128 rows x 8 x 16B
            int r = t >> 3, c = t & 7;
            src = A + (size_t)(m0 + r) * 1024 + ko + c * 8;
            dst = stg + r * SP_STRIDE + c * 16;
        } else {               // B: 128 rows x 8 x 16B
            int u = t - 1024, r = u >> 3, c = u & 7;
            src = B + (size_t)(n0 + r) * 1024 + ko + c * 8;
            dst = stg + SP_TILE + r * SP_STRIDE + c * 16;
        }
        cp16(dst, src);
    }
    asm volatile("cp.async.commit_group;" ::: "memory");
}

template<int PROJ>
__global__ __launch_bounds__(256, 2) void gemm_sp(float* __restrict__ outp_)
{
    extern __shared__ __align__(128) char dsm[];
    const uint32_t sb = smem_u32(dsm);
    const int tid = threadIdx.x, wid = tid >> 5, lane = tid & 31;
    const int warp_m = wid >> 2, warp_n = wid & 3;
    const int m0 = blockIdx.x * 128, n0 = blockIdx.y * 128;
    const int z = blockIdx.z;            // PROJ=0: 0=Q, 1=K, 2=V

    const __half* A = PROJ ? g_Afh : g_xfh;
    const __half* B = g_wf + ((size_t)(PROJ ? 3 : z) << 20);

    const uint32_t a_off = (uint32_t)(warp_m * 64 + (lane & 15)) * SP_STRIDE
                         + (lane >> 4) * 16;
    const uint32_t b_off = (uint32_t)(warp_n * 32 + (lane >> 4) * 8 + (lane & 7)) * SP_STRIDE
                         + ((lane >> 3) & 1) * 16;

    float acc[4][4][4];
#pragma unroll
    for (int i = 0; i < 4; i++)
#pragma unroll
        for (int j = 0; j < 4; j++)
#pragma unroll
            for (int k = 0; k < 4; k++) acc[i][j][k] = 0.f;

    copy_chunk_sp(tid, sb, 0, m0, n0, A, B);
    copy_chunk_sp(tid, sb + SP_STG, 1, m0, n0, A, B);

    for (int kc = 0; kc < KC; kc++) {
        if (kc + 1 < KC) {
            asm volatile("cp.async.wait_group 1;" ::: "memory");
        } else {
            asm volatile("cp.async.wait_group 0;" ::: "memory");
        }
        __syncthreads();
        if (kc + 2 < KC)
            copy_chunk_sp(tid, sb + (uint32_t)((kc + 2) % 3) * SP_STG, kc + 2,
                          m0, n0, A, B);

        const uint32_t stg = sb + (uint32_t)(kc % 3) * SP_STG;
        const uint32_t sB = stg + SP_TILE;
#pragma unroll
        for (int ks = 0; ks < 4; ks++) {
            uint32_t ah[4][4], bb[2][4];
#pragma unroll
            for (int mt = 0; mt < 4; mt++)
                ldsm4(ah[mt], stg + a_off + mt * (16 * SP_STRIDE) + ks * 32);
#pragma unroll
            for (int pr = 0; pr < 2; pr++)
                ldsm4(bb[pr], sB + b_off + pr * (16 * SP_STRIDE) + ks * 32);
#pragma unroll
            for (int mt = 0; mt < 4; mt++)
#pragma unroll
                for (int nt = 0; nt < 4; nt++)
                    mma16816h(acc[mt][nt], ah[mt], &bb[nt >> 1][(nt & 1) * 2]);
        }
        __syncthreads();
    }

    const int tg = lane >> 2, tq = lane & 3;
#pragma unroll
    for (int mt = 0; mt < 4; mt++) {
#pragma unroll
        for (int nt = 0; nt < 4; nt++) {
            int row = m0 + warp_m * 64 + mt * 16 + tg;
            int col = n0 + warp_n * 32 + nt * 8 + tq * 2;
            if (PROJ) {
                float* dst0 = outp_ + (size_t)row * DM + col;
                float* dst1 = outp_ + (size_t)(row + 8) * DM + col;
                *(float2*)dst0 = make_float2(acc[mt][nt][0], acc[mt][nt][1]);
                *(float2*)dst1 = make_float2(acc[mt][nt][2], acc[mt][nt][3]);
            } else {
                const float scale = (z == 0) ? QSCALE : 1.0f;
                int bb_ = row >> 11, ss = row & 2047, hh = col >> 6, dk = col & 63;
                size_t base = (size_t)z * QKV_ELE
                            + (((size_t)(bb_ * NH + hh)) * SEQ + ss) * DKH + dk;
                *(__half2*)&g_qkvh[base] =
                    __floats2half2_rn(acc[mt][nt][0] * scale, acc[mt][nt][1] * scale);
                *(__half2*)&g_qkvh[base + 8 * DKH] =
                    __floats2half2_rn(acc[mt][nt][2] * scale, acc[mt][nt][3] * scale);
            }
        }
    }
}

// ---------------- causal flash attention on HMMA ----------------------------
// BM=128 (8 warps x 16 rows), BN=64, d=64.
// QK^T: fp16 single (Q x K). PV: fp16x2 (P exact pair x V single).
#define AT_STRIDE 144
#define Q_TILE_B   (128 * AT_STRIDE)        // 18432
#define KV_ARR_B   (64 * AT_STRIDE)         // 9216
#define KV_STAGE_B (2 * KV_ARR_B)           // 18432: K | V
#define ATT_SMEM   (Q_TILE_B + 2 * KV_STAGE_B)   // 55296 -> 2 CTAs/SM

__device__ __forceinline__ void load_kv(int tid, uint32_t stg, int j,
    const __half* Kg, const __half* Vg)
{
#pragma unroll
    for (int it = 0; it < 4; it++) {
        int i = tid + it * 256;
        int arr = i >> 9, r = (i >> 3) & 63, c = i & 7;
        const __half* src = (arr == 0 ? Kg : Vg)
                          + ((size_t)(j * 64 + r)) * DKH + c * 8;
        cp16(stg + arr * KV_ARR_B + r * AT_STRIDE + c * 16, src);
    }
    asm volatile("cp.async.commit_group;" ::: "memory");
}

__global__ __launch_bounds__(256, 2) void attn_mma()
{
    extern __shared__ __align__(128) char dsm[];
    const uint32_t sb = smem_u32(dsm);
    const uint32_t sQ = sb;
    const uint32_t sKV = sb + Q_TILE_B;

    const int qi = (int)gridDim.x - 1 - (int)blockIdx.x;   // heavy tiles first
    const int q0 = qi * 128;
    const int bh = blockIdx.y;
    const int b = bh >> 4, h = bh & 15;
    const int tid = threadIdx.x, w = tid >> 5, lane = tid & 31;

    const __half* Qg = g_qkvh + ((size_t)bh * SEQ + q0) * DKH;
    const __half* Kg = g_qkvh + QKV_ELE     + (size_t)bh * SEQ * DKH;
    const __half* Vg = g_qkvh + 2 * QKV_ELE + (size_t)bh * SEQ * DKH;

    // Q -> smem, group 0
#pragma unroll
    for (int it = 0; it < 4; it++) {
        int i = tid + it * 256;
        int r = i >> 3, c = i & 7;
        cp16(sQ + r * AT_STRIDE + c * 16, Qg + (size_t)r * DKH + c * 8);
    }
    asm volatile("cp.async.commit_group;" ::: "memory");

    load_kv(tid, sKV, 0, Kg, Vg);

    float O[8][4];
#pragma unroll
    for (int i = 0; i < 8; i++)
#pragma unroll
        for (int j = 0; j < 4; j++) O[i][j] = 0.f;
    float m0 = -1e30f, m1 = -1e30f, l0 = 0.f, l1 = 0.f;

    const uint32_t qa_base = (uint32_t)(w * 16 + (lane & 15)) * AT_STRIDE + (lane >> 4) * 16;
    const uint32_t kb_base = (uint32_t)((lane & 7) + ((lane >> 4) & 1) * 8) * AT_STRIDE
                           + ((lane >> 3) & 1) * 16;
    const uint32_t vb_base = (uint32_t)(lane & 15) * AT_STRIDE + (lane >> 4) * 16;

    const int njt = 2 * qi + 2;
    for (int j = 0; j < njt; j++) {
        const uint32_t st = sKV + (uint32_t)(j & 1) * KV_STAGE_B;
        if (j + 1 < njt) {
            load_kv(tid, sKV + (uint32_t)((j + 1) & 1) * KV_STAGE_B, j + 1, Kg, Vg);
            asm volatile("cp.async.wait_group 1;" ::: "memory");
        } else {
            asm volatile("cp.async.wait_group 0;" ::: "memory");
        }
        __syncthreads();

        // ---- S = Qs @ K^T (fp16 single) ----
        float s[8][4];
#pragma unroll
        for (int i = 0; i < 8; i++)
#pragma unroll
            for (int jj = 0; jj < 4; jj++) s[i][jj] = 0.f;

#pragma unroll
        for (int ks = 0; ks < 4; ks++) {
            uint32_t qh[4];
            ldsm4(qh, sQ + qa_base + ks * 32);
#pragma unroll
            for (int ng = 0; ng < 4; ng++) {
                uint32_t kk[4];
                uint32_t ko = kb_base + ng * (16 * AT_STRIDE) + ks * 32;
                ldsm4(kk, st + 0 * KV_ARR_B + ko);
                mma16816h(s[2 * ng],     qh, &kk[0]);
                mma16816h(s[2 * ng + 1], qh, &kk[2]);
            }
        }

        // ---- causal mask (diagonal-region tiles only) ----
        if (j >= 2 * qi) {
            int r0 = q0 + w * 16 + (lane >> 2);
            int cb = j * 64 + (lane & 3) * 2;
#pragma unroll
            for (int nt = 0; nt < 8; nt++)
#pragma unroll
                for (int cc = 0; cc < 2; cc++) {
                    int col = cb + nt * 8 + cc;
                    if (col > r0)     s[nt][cc]     = -1e30f;
                    if (col > r0 + 8) s[nt][2 + cc] = -1e30f;
                }
        }

        // ---- online softmax (base-2; scale folded into Q) ----
        float mx0 = -1e30f, mx1 = -1e30f;
#pragma unroll
        for (int nt = 0; nt < 8; nt++) {
            mx0 = fmaxf(mx0, fmaxf(s[nt][0], s[nt][1]));
            mx1 = fmaxf(mx1, fmaxf(s[nt][2], s[nt][3]));
        }
        mx0 = fmaxf(mx0, __shfl_xor_sync(0xffffffffu, mx0, 1));
        mx0 = fmaxf(mx0, __shfl_xor_sync(0xffffffffu, mx0, 2));
        mx1 = fmaxf(mx1, __shfl_xor_sync(0xffffffffu, mx1, 1));
        mx1 = fmaxf(mx1, __shfl_xor_sync(0xffffffffu, mx1, 2));
        float mn0 = fmaxf(m0, mx0), mn1 = fmaxf(m1, mx1);
        float a0 = ex2(m0 - mn0), a1 = ex2(m1 - mn1);
        float sm0 = 0.f, sm1 = 0.f;
#pragma unroll
        for (int nt = 0; nt < 8; nt++) {
            s[nt][0] = ex2(s[nt][0] - mn0); sm0 += s[nt][0];
            s[nt][1] = ex2(s[nt][1] - mn0); sm0 += s[nt][1];
            s[nt][2] = ex2(s[nt][2] - mn1); sm1 += s[nt][2];
            s[nt][3] = ex2(s[nt][3] - mn1); sm1 += s[nt][3];
        }
        sm0 += __shfl_xor_sync(0xffffffffu, sm0, 1);
        sm0 += __shfl_xor_sync(0xffffffffu, sm0, 2);
        sm1 += __shfl_xor_sync(0xffffffffu, sm1, 1);
        sm1 += __shfl_xor_sync(0xffffffffu, sm1, 2);
        l0 = l0 * a0 + sm0; l1 = l1 * a1 + sm1;
        m0 = mn0; m1 = mn1;
#pragma unroll
        for (int nt = 0; nt < 8; nt++) {
            O[nt][0] *= a0; O[nt][1] *= a0;
            O[nt][2] *= a1; O[nt][3] *= a1;
        }

        // ---- O += P @ V (fp16x2: P exact pair in regs, V single in smem) ----
#pragma unroll
        for (int ks = 0; ks < 4; ks++) {
            uint32_t ph[4], pl[4];
            {
                __half2 t;
                t = __floats2half2_rn(s[2 * ks][0], s[2 * ks][1]);
                ph[0] = h2u(t);
                pl[0] = h2u(__floats2half2_rn(s[2 * ks][0] - __low2float(t),
                                              s[2 * ks][1] - __high2float(t)));
                t = __floats2half2_rn(s[2 * ks][2], s[2 * ks][3]);
                ph[1] = h2u(t);
                pl[1] = h2u(__floats2half2_rn(s[2 * ks][2] - __low2float(t),
                                              s[2 * ks][3] - __high2float(t)));
                t = __floats2half2_rn(s[2 * ks + 1][0], s[2 * ks + 1][1]);
                ph[2] = h2u(t);
                pl[2] = h2u(__floats2half2_rn(s[2 * ks + 1][0] - __low2float(t),
                                              s[2 * ks + 1][1] - __high2float(t)));
                t = __floats2half2_rn(s[2 * ks + 1][2], s[2 * ks + 1][3]);
                ph[3] = h2u(t);
                pl[3] = h2u(__floats2half2_rn(s[2 * ks + 1][2] - __low2float(t),
                                              s[2 * ks + 1][3] - __high2float(t)));
            }
#pragma unroll
            for (int ng = 0; ng < 4; ng++) {
                uint32_t vh[4];
                uint32_t vo = vb_base + ks * (16 * AT_STRIDE) + ng * 32;
                ldsm4t(vh, st + 1 * KV_ARR_B + vo);
                mma16816h(O[2 * ng],     ph, &vh[0]);
                mma16816h(O[2 * ng],     pl, &vh[0]);
                mma16816h(O[2 * ng + 1], ph, &vh[2]);
                mma16816h(O[2 * ng + 1], pl, &vh[2]);
            }
        }
        __syncthreads();
    }

    // ---- epilogue: normalize + single fp16 for the output projection ----
    float inv0 = 1.0f / l0, inv1 = 1.0f / l1;
    int r0 = q0 + w * 16 + (lane >> 2);
    size_t rb0 = ((size_t)b * SEQ + r0) * DM + h * 64;
    size_t rb1 = rb0 + (size_t)8 * DM;
#pragma unroll
    for (int nt = 0; nt < 8; nt++) {
        int c0 = nt * 8 + (lane & 3) * 2;
        *(__half2*)&g_Afh[rb0 + c0] =
            __floats2half2_rn(O[nt][0] * inv0, O[nt][1] * inv0);
        *(__half2*)&g_Afh[rb1 + c0] =
            __floats2half2_rn(O[nt][2] * inv1, O[nt][3] * inv1);
    }
}

// ---------------------------------------------------------------------------
extern "C" void kernel_launch(void* const* d_in, const int* in_sizes, int n_in,
                              void* d_out, int out_size)
{
    const float* x  = (const float*)d_in[0];
    const float* Wq = (const float*)d_in[1];
    const float* Wk = (const float*)d_in[2];
    const float* Wv = (const float*)d_in[3];
    const float* Wo = (const float*)d_in[4];
    float* out = (float*)d_out;

    cudaFuncSetAttribute(gemm_sp<0>, cudaFuncAttributeMaxDynamicSharedMemorySize, SP_SMEM);
    cudaFuncSetAttribute(gemm_sp<1>, cudaFuncAttributeMaxDynamicSharedMemorySize, SP_SMEM);
    cudaFuncSetAttribute(attn_mma,   cudaFuncAttributeMaxDynamicSharedMemorySize, ATT_SMEM);

    split_x_kernel<<<8192, 256>>>(x);
    tsplit_qkv_kernel<<<dim3(2, 32, 48), dim3(32, 8)>>>(Wq, Wk, Wv);
    tsplit_kernel<<<dim3(32, 32, 1), dim3(32, 8)>>>(Wo, 3, 1024, 1024);

    gemm_sp<0><<<dim3(64, 8, 3), 256, SP_SMEM>>>(nullptr);
    attn_mma<<<dim3(SEQ / 128, BATCH * NH), 256, ATT_SMEM>>>();
    gemm_sp<1><<<dim3(64, 8, 1), 256, SP_SMEM>>>(out);
}